// round 1
// baseline (speedup 1.0000x reference)
#include <cuda_runtime.h>
#include <math.h>

#define MTOT   8192
#define DMODEL 1024
#define DFFN   4096
#define NHEAD  16
#define HDIM   64
#define SEQ    1024
#define BATCH  8

// ---------------- scratch (device globals; no allocations) ----------------
__device__ float g_ln[MTOT * DMODEL];          // 32 MB (reused for ln1/ln2)
__device__ float g_qkv[MTOT * 3 * DMODEL];     // 96 MB
__device__ float g_att[MTOT * DMODEL];         // 32 MB
__device__ float g_x1[MTOT * DMODEL];          // 32 MB
__device__ float g_gate[MTOT * DFFN];          // 128 MB

// ---------------- LayerNorm: one block per row, D=1024 --------------------
__global__ __launch_bounds__(256) void ln_kernel(
    const float* __restrict__ x, const float* __restrict__ g,
    const float* __restrict__ b, float* __restrict__ y)
{
    __shared__ float redS[8];
    __shared__ float redQ[8];
    const int row = blockIdx.x;
    const int tid = threadIdx.x;

    const float4 v = ((const float4*)(x + (size_t)row * DMODEL))[tid];
    float s = v.x + v.y + v.z + v.w;
    float q = v.x*v.x + v.y*v.y + v.z*v.z + v.w*v.w;
    #pragma unroll
    for (int off = 16; off >= 1; off >>= 1) {
        s += __shfl_xor_sync(0xffffffffu, s, off);
        q += __shfl_xor_sync(0xffffffffu, q, off);
    }
    if ((tid & 31) == 0) { redS[tid >> 5] = s; redQ[tid >> 5] = q; }
    __syncthreads();
    if (tid < 32) {
        s = (tid < 8) ? redS[tid] : 0.f;
        q = (tid < 8) ? redQ[tid] : 0.f;
        #pragma unroll
        for (int off = 4; off >= 1; off >>= 1) {
            s += __shfl_xor_sync(0xffffffffu, s, off);
            q += __shfl_xor_sync(0xffffffffu, q, off);
        }
        if (tid == 0) { redS[0] = s; redQ[0] = q; }
    }
    __syncthreads();
    const float mu  = redS[0] * (1.f / DMODEL);
    const float var = redQ[0] * (1.f / DMODEL) - mu * mu;
    const float rstd = rsqrtf(var + 1e-5f);

    const float4 gv = ((const float4*)g)[tid];
    const float4 bv = ((const float4*)b)[tid];
    float4 o;
    o.x = (v.x - mu) * rstd * gv.x + bv.x;
    o.y = (v.y - mu) * rstd * gv.y + bv.y;
    o.z = (v.z - mu) * rstd * gv.z + bv.z;
    o.w = (v.w - mu) * rstd * gv.w + bv.w;
    ((float4*)(y + (size_t)row * DMODEL))[tid] = o;
}

// ---------------- NT GEMM: C[M,N] = A[M,K] * W[N,K]^T + bias --------------
// EPI 0: + bias
// EPI 1: + bias + aux[m,n]           (residual)
// EPI 2: silu(aux[m,n]) * (+ bias)   (SwiGLU combine; aux may alias C)
template <int EPI>
__global__ __launch_bounds__(256) void gemm_nt(
    const float* __restrict__ A, const float* __restrict__ W,
    const float* __restrict__ bias, const float* __restrict__ aux,
    float* __restrict__ C, int M, int N, int K)
{
    __shared__ float As[16][132];
    __shared__ float Bs[16][132];
    const int bm = blockIdx.x * 128;
    const int bn = blockIdx.y * 128;
    const int tid = threadIdx.x;
    const int tx = tid & 15;
    const int ty = tid >> 4;

    float acc[8][8];
    #pragma unroll
    for (int i = 0; i < 8; i++)
        #pragma unroll
        for (int j = 0; j < 8; j++) acc[i][j] = 0.f;

    const int lr = tid >> 2;        // 0..63 loader row
    const int lc = (tid & 3) * 4;   // 0,4,8,12 loader col
    const float* Aptr = A + (size_t)(bm + lr) * K + lc;
    const float* Wptr = W + (size_t)(bn + lr) * K + lc;

    for (int k0 = 0; k0 < K; k0 += 16) {
        #pragma unroll
        for (int h = 0; h < 2; h++) {
            const int r = lr + h * 64;
            float4 a = *(const float4*)(Aptr + (size_t)(h * 64) * K + k0);
            As[lc + 0][r] = a.x; As[lc + 1][r] = a.y;
            As[lc + 2][r] = a.z; As[lc + 3][r] = a.w;
            float4 w = *(const float4*)(Wptr + (size_t)(h * 64) * K + k0);
            Bs[lc + 0][r] = w.x; Bs[lc + 1][r] = w.y;
            Bs[lc + 2][r] = w.z; Bs[lc + 3][r] = w.w;
        }
        __syncthreads();
        #pragma unroll
        for (int k = 0; k < 16; k++) {
            float a[8], b[8];
            *(float4*)(a)     = *(const float4*)&As[k][ty * 8];
            *(float4*)(a + 4) = *(const float4*)&As[k][ty * 8 + 4];
            *(float4*)(b)     = *(const float4*)&Bs[k][tx * 8];
            *(float4*)(b + 4) = *(const float4*)&Bs[k][tx * 8 + 4];
            #pragma unroll
            for (int i = 0; i < 8; i++)
                #pragma unroll
                for (int j = 0; j < 8; j++)
                    acc[i][j] = fmaf(a[i], b[j], acc[i][j]);
        }
        __syncthreads();
    }

    #pragma unroll
    for (int i = 0; i < 8; i++) {
        const int m = bm + ty * 8 + i;
        #pragma unroll
        for (int j4 = 0; j4 < 2; j4++) {
            const int n = bn + tx * 8 + j4 * 4;
            float r0 = acc[i][j4 * 4 + 0] + bias[n + 0];
            float r1 = acc[i][j4 * 4 + 1] + bias[n + 1];
            float r2 = acc[i][j4 * 4 + 2] + bias[n + 2];
            float r3 = acc[i][j4 * 4 + 3] + bias[n + 3];
            if (EPI == 1) {
                const float4 v = *(const float4*)&aux[(size_t)m * N + n];
                r0 += v.x; r1 += v.y; r2 += v.z; r3 += v.w;
            }
            if (EPI == 2) {
                const float4 gq = *(const float4*)&aux[(size_t)m * N + n];
                r0 *= gq.x / (1.f + __expf(-gq.x));
                r1 *= gq.y / (1.f + __expf(-gq.y));
                r2 *= gq.z / (1.f + __expf(-gq.z));
                r3 *= gq.w / (1.f + __expf(-gq.w));
            }
            float4 o = make_float4(r0, r1, r2, r3);
            *(float4*)&C[(size_t)m * N + n] = o;
        }
    }
}

// ---------------- Flash attention with ALiBi ------------------------------
// Block: 256 threads, 64 query rows for one (b,h). 16 KV tiles of 64.
// Thread (ty,tx): owns S/P rows ty*4+i, kv cols tx*4+j; O rows ty*4+i, hd cols tx*4+j.
__global__ __launch_bounds__(256) void attn_kernel(
    const float* __restrict__ qkv, float* __restrict__ out)
{
    extern __shared__ float sm[];
    float (*Qts)[64] = (float(*)[64])(sm);            // [hd][q]
    float (*Kts)[64] = (float(*)[64])(sm + 4096);     // [hd][kv]
    float (*Vs)[64]  = (float(*)[64])(sm + 8192);     // [kv][hd]
    float (*Ps)[64]  = (float(*)[64])(sm + 12288);    // [q][kv]

    const int bq = blockIdx.x;   // q tile
    const int h  = blockIdx.y;
    const int b  = blockIdx.z;
    const int tid = threadIdx.x;
    const int tx = tid & 15, ty = tid >> 4;

    const float scale = 0.125f;                         // 1/sqrt(64)
    const float slope = exp2f(-0.5f * (float)(h + 1));  // 2^(-8(h+1)/16)

    const float* base = qkv + (size_t)b * SEQ * (3 * DMODEL);
    const float* qb = base + h * HDIM;
    const float* kb = base + DMODEL + h * HDIM;
    const float* vb = base + 2 * DMODEL + h * HDIM;

    // Load Q tile transposed: [hd][q]
    #pragma unroll
    for (int it = 0; it < 4; it++) {
        const int i = tid + it * 256;
        const int r = i >> 4, c4 = (i & 15) * 4;
        float4 v = *(const float4*)&qb[(size_t)(bq * 64 + r) * (3 * DMODEL) + c4];
        Qts[c4 + 0][r] = v.x; Qts[c4 + 1][r] = v.y;
        Qts[c4 + 2][r] = v.z; Qts[c4 + 3][r] = v.w;
    }

    float m[4], l[4], O[4][4];
    #pragma unroll
    for (int i = 0; i < 4; i++) {
        m[i] = -1e30f; l[i] = 0.f;
        #pragma unroll
        for (int j = 0; j < 4; j++) O[i][j] = 0.f;
    }

    for (int t = 0; t < 16; t++) {
        __syncthreads();   // protect Kts/Vs/Ps from previous iteration readers
        #pragma unroll
        for (int it = 0; it < 4; it++) {
            const int i = tid + it * 256;
            const int r = i >> 4, c4 = (i & 15) * 4;
            float4 kv4 = *(const float4*)&kb[(size_t)(t * 64 + r) * (3 * DMODEL) + c4];
            Kts[c4 + 0][r] = kv4.x; Kts[c4 + 1][r] = kv4.y;
            Kts[c4 + 2][r] = kv4.z; Kts[c4 + 3][r] = kv4.w;
            float4 vv = *(const float4*)&vb[(size_t)(t * 64 + r) * (3 * DMODEL) + c4];
            *(float4*)&Vs[r][c4] = vv;
        }
        __syncthreads();

        // S = Q K^T (per-thread 4x4)
        float s[4][4];
        #pragma unroll
        for (int i = 0; i < 4; i++)
            #pragma unroll
            for (int j = 0; j < 4; j++) s[i][j] = 0.f;
        #pragma unroll
        for (int k = 0; k < 64; k++) {
            const float4 qa = *(const float4*)&Qts[k][ty * 4];
            const float4 kk = *(const float4*)&Kts[k][tx * 4];
            const float qv[4] = {qa.x, qa.y, qa.z, qa.w};
            const float kvv[4] = {kk.x, kk.y, kk.z, kk.w};
            #pragma unroll
            for (int i = 0; i < 4; i++)
                #pragma unroll
                for (int j = 0; j < 4; j++)
                    s[i][j] = fmaf(qv[i], kvv[j], s[i][j]);
        }

        // bias + online softmax
        #pragma unroll
        for (int i = 0; i < 4; i++) {
            const int qp = bq * 64 + ty * 4 + i;
            float sv[4];
            float mx = -1e30f;
            #pragma unroll
            for (int j = 0; j < 4; j++) {
                const int kp = t * 64 + tx * 4 + j;
                sv[j] = s[i][j] * scale - slope * fabsf((float)(qp - kp));
                mx = fmaxf(mx, sv[j]);
            }
            #pragma unroll
            for (int off = 8; off >= 1; off >>= 1)
                mx = fmaxf(mx, __shfl_xor_sync(0xffffffffu, mx, off));
            const float mnew = fmaxf(m[i], mx);
            float p[4], ps = 0.f;
            #pragma unroll
            for (int j = 0; j < 4; j++) { p[j] = __expf(sv[j] - mnew); ps += p[j]; }
            #pragma unroll
            for (int off = 8; off >= 1; off >>= 1)
                ps += __shfl_xor_sync(0xffffffffu, ps, off);
            const float alpha = __expf(m[i] - mnew);
            l[i] = l[i] * alpha + ps;
            m[i] = mnew;
            #pragma unroll
            for (int j = 0; j < 4; j++) O[i][j] *= alpha;
            *(float4*)&Ps[ty * 4 + i][tx * 4] = make_float4(p[0], p[1], p[2], p[3]);
        }
        __syncthreads();

        // O += P V
        #pragma unroll
        for (int kv = 0; kv < 64; kv++) {
            const float4 vv = *(const float4*)&Vs[kv][tx * 4];
            #pragma unroll
            for (int i = 0; i < 4; i++) {
                const float p = Ps[ty * 4 + i][kv];
                O[i][0] = fmaf(p, vv.x, O[i][0]);
                O[i][1] = fmaf(p, vv.y, O[i][1]);
                O[i][2] = fmaf(p, vv.z, O[i][2]);
                O[i][3] = fmaf(p, vv.w, O[i][3]);
            }
        }
    }

    // write out: [B,N, h*64+d]
    #pragma unroll
    for (int i = 0; i < 4; i++) {
        const float inv = 1.f / l[i];
        const int qp = bq * 64 + ty * 4 + i;
        float4 o = make_float4(O[i][0] * inv, O[i][1] * inv, O[i][2] * inv, O[i][3] * inv);
        *(float4*)&out[((size_t)(b * SEQ + qp)) * DMODEL + h * HDIM + tx * 4] = o;
    }
}

// ---------------- launch ---------------------------------------------------
extern "C" void kernel_launch(void* const* d_in, const int* in_sizes, int n_in,
                              void* d_out, int out_size)
{
    const float* src    = (const float*)d_in[0];
    const float* wqkv   = (const float*)d_in[1];
    const float* bqkv   = (const float*)d_in[2];
    const float* wo     = (const float*)d_in[3];
    const float* bo     = (const float*)d_in[4];
    const float* g1     = (const float*)d_in[5];
    const float* b1     = (const float*)d_in[6];
    const float* g2     = (const float*)d_in[7];
    const float* b2     = (const float*)d_in[8];
    const float* w_gate = (const float*)d_in[9];
    const float* b_gate = (const float*)d_in[10];
    const float* w_up   = (const float*)d_in[11];
    const float* b_up   = (const float*)d_in[12];
    const float* w_down = (const float*)d_in[13];
    const float* b_down = (const float*)d_in[14];
    float* out = (float*)d_out;

    float *ln, *qkv, *att, *x1, *gate;
    cudaGetSymbolAddress((void**)&ln,   g_ln);
    cudaGetSymbolAddress((void**)&qkv,  g_qkv);
    cudaGetSymbolAddress((void**)&att,  g_att);
    cudaGetSymbolAddress((void**)&x1,   g_x1);
    cudaGetSymbolAddress((void**)&gate, g_gate);

    cudaFuncSetAttribute(attn_kernel,
                         cudaFuncAttributeMaxDynamicSharedMemorySize, 65536);

    // x = src + Attn(LN1(src))
    ln_kernel<<<MTOT, 256>>>(src, g1, b1, ln);
    gemm_nt<0><<<dim3(64, 24), 256>>>(ln, wqkv, bqkv, nullptr, qkv,
                                      MTOT, 3 * DMODEL, DMODEL);
    attn_kernel<<<dim3(16, NHEAD, BATCH), 256, 65536>>>(qkv, att);
    gemm_nt<1><<<dim3(64, 8), 256>>>(att, wo, bo, src, x1,
                                     MTOT, DMODEL, DMODEL);

    // x = x + SwiGLU(LN2(x))
    ln_kernel<<<MTOT, 256>>>(x1, g2, b2, ln);
    gemm_nt<0><<<dim3(64, 32), 256>>>(ln, w_gate, b_gate, nullptr, gate,
                                      MTOT, DFFN, DMODEL);
    gemm_nt<2><<<dim3(64, 32), 256>>>(ln, w_up, b_up, gate, gate,
                                      MTOT, DFFN, DMODEL);
    gemm_nt<1><<<dim3(64, 8), 256>>>(gate, w_down, b_down, x1, out,
                                     MTOT, DMODEL, DFFN);
}

// round 2
// speedup vs baseline: 1.8776x; 1.8776x over previous
#include <cuda_runtime.h>
#include <math.h>
#include <stdint.h>

#define MTOT   8192
#define DMODEL 1024
#define DFFN   4096
#define NHEAD  16
#define HDIM   64
#define SEQ    1024
#define BATCH  8

// ---------------- scratch (device globals; no allocations) ----------------
__device__ float g_ln[MTOT * DMODEL];          // 32 MB (reused for ln1/ln2)
__device__ float g_qkv[MTOT * 3 * DMODEL];     // 96 MB
__device__ float g_att[MTOT * DMODEL];         // 32 MB
__device__ float g_x1[MTOT * DMODEL];          // 32 MB
__device__ float g_gate[MTOT * DFFN];          // 128 MB

// ---------------- LayerNorm: one block per row, D=1024 --------------------
__global__ __launch_bounds__(256) void ln_kernel(
    const float* __restrict__ x, const float* __restrict__ g,
    const float* __restrict__ b, float* __restrict__ y)
{
    __shared__ float redS[8];
    __shared__ float redQ[8];
    const int row = blockIdx.x;
    const int tid = threadIdx.x;

    const float4 v = ((const float4*)(x + (size_t)row * DMODEL))[tid];
    float s = v.x + v.y + v.z + v.w;
    float q = v.x*v.x + v.y*v.y + v.z*v.z + v.w*v.w;
    #pragma unroll
    for (int off = 16; off >= 1; off >>= 1) {
        s += __shfl_xor_sync(0xffffffffu, s, off);
        q += __shfl_xor_sync(0xffffffffu, q, off);
    }
    if ((tid & 31) == 0) { redS[tid >> 5] = s; redQ[tid >> 5] = q; }
    __syncthreads();
    if (tid < 32) {
        s = (tid < 8) ? redS[tid] : 0.f;
        q = (tid < 8) ? redQ[tid] : 0.f;
        #pragma unroll
        for (int off = 4; off >= 1; off >>= 1) {
            s += __shfl_xor_sync(0xffffffffu, s, off);
            q += __shfl_xor_sync(0xffffffffu, q, off);
        }
        if (tid == 0) { redS[0] = s; redQ[0] = q; }
    }
    __syncthreads();
    const float mu  = redS[0] * (1.f / DMODEL);
    const float var = redQ[0] * (1.f / DMODEL) - mu * mu;
    const float rstd = rsqrtf(var + 1e-5f);

    const float4 gv = ((const float4*)g)[tid];
    const float4 bv = ((const float4*)b)[tid];
    float4 o;
    o.x = (v.x - mu) * rstd * gv.x + bv.x;
    o.y = (v.y - mu) * rstd * gv.y + bv.y;
    o.z = (v.z - mu) * rstd * gv.z + bv.z;
    o.w = (v.w - mu) * rstd * gv.w + bv.w;
    ((float4*)(y + (size_t)row * DMODEL))[tid] = o;
}

// ---------------- TF32 tensor-core NT GEMM --------------------------------
// C[M,N] = A[M,K] * W[N,K]^T + bias, with epilogues:
// EPI 0: + bias
// EPI 1: + bias + aux[m,n]           (residual)
// EPI 2: silu(aux[m,n]) * (+ bias)   (SwiGLU combine; aux may alias C)
// Tile: 128x128x16, 8 warps (4 along M x 2 along N), warp tile 32x64.
// mma.sync.aligned.m16n8k8.f32.tf32

__device__ __forceinline__ float to_tf32(float x) {
    uint32_t u;
    asm("cvt.rna.tf32.f32 %0, %1;" : "=r"(u) : "f"(x));
    return __uint_as_float(u);
}

__device__ __forceinline__ void mma_tf32(float c[4], const uint32_t a[4],
                                         const uint32_t b[2]) {
    asm volatile(
        "mma.sync.aligned.m16n8k8.row.col.f32.tf32.tf32.f32 "
        "{%0,%1,%2,%3}, {%4,%5,%6,%7}, {%8,%9}, {%0,%1,%2,%3};\n"
        : "+f"(c[0]), "+f"(c[1]), "+f"(c[2]), "+f"(c[3])
        : "r"(a[0]), "r"(a[1]), "r"(a[2]), "r"(a[3]), "r"(b[0]), "r"(b[1]));
}

template <int EPI>
__global__ __launch_bounds__(256, 2) void gemm_tf32(
    const float* __restrict__ A, const float* __restrict__ W,
    const float* __restrict__ bias, const float* __restrict__ aux,
    float* __restrict__ C, int M, int N, int K)
{
    __shared__ float As[2][128][20];   // [buf][m][k], stride 20 -> conflict-free frags
    __shared__ float Bs[2][128][20];   // [buf][n][k]

    const int tid  = threadIdx.x;
    const int warp = tid >> 5, lane = tid & 31;
    const int g  = lane >> 2;          // groupID
    const int th = lane & 3;           // threadID_in_group
    const int wm = (warp & 3) * 32;    // warp M offset
    const int wn = (warp >> 2) * 64;   // warp N offset
    const int bm = blockIdx.x * 128;
    const int bn = blockIdx.y * 128;

    const int lr = tid >> 2;           // loader row 0..63 (and +64)
    const int lc = (tid & 3) * 4;      // loader k col: 0,4,8,12
    const float* Ap = A + (size_t)(bm + lr) * K + lc;
    const float* Wp = W + (size_t)(bn + lr) * K + lc;

    float acc[2][8][4];
    #pragma unroll
    for (int i = 0; i < 2; i++)
        #pragma unroll
        for (int j = 0; j < 8; j++)
            #pragma unroll
            for (int c = 0; c < 4; c++) acc[i][j][c] = 0.f;

    float4 ra[2], rb[2];

    // prologue: load tile 0, convert, store to buf 0
    ra[0] = *(const float4*)(Ap);
    ra[1] = *(const float4*)(Ap + (size_t)64 * K);
    rb[0] = *(const float4*)(Wp);
    rb[1] = *(const float4*)(Wp + (size_t)64 * K);
    #pragma unroll
    for (int h = 0; h < 2; h++) {
        float4 ca = make_float4(to_tf32(ra[h].x), to_tf32(ra[h].y),
                                to_tf32(ra[h].z), to_tf32(ra[h].w));
        *(float4*)&As[0][lr + h * 64][lc] = ca;
        float4 cb = make_float4(to_tf32(rb[h].x), to_tf32(rb[h].y),
                                to_tf32(rb[h].z), to_tf32(rb[h].w));
        *(float4*)&Bs[0][lr + h * 64][lc] = cb;
    }
    __syncthreads();

    const int nt = K >> 4;
    for (int t = 0; t < nt; t++) {
        const int cur = t & 1;
        if (t + 1 < nt) {
            const int k0 = (t + 1) * 16;
            ra[0] = *(const float4*)(Ap + k0);
            ra[1] = *(const float4*)(Ap + (size_t)64 * K + k0);
            rb[0] = *(const float4*)(Wp + k0);
            rb[1] = *(const float4*)(Wp + (size_t)64 * K + k0);
        }

        #pragma unroll
        for (int ks = 0; ks < 2; ks++) {
            const int k = ks * 8;
            uint32_t af[2][4], bf[8][2];
            #pragma unroll
            for (int i = 0; i < 2; i++) {
                const int m = wm + i * 16;
                af[i][0] = __float_as_uint(As[cur][m + g    ][k + th    ]);
                af[i][1] = __float_as_uint(As[cur][m + g + 8][k + th    ]);
                af[i][2] = __float_as_uint(As[cur][m + g    ][k + th + 4]);
                af[i][3] = __float_as_uint(As[cur][m + g + 8][k + th + 4]);
            }
            #pragma unroll
            for (int j = 0; j < 8; j++) {
                const int n = wn + j * 8;
                bf[j][0] = __float_as_uint(Bs[cur][n + g][k + th    ]);
                bf[j][1] = __float_as_uint(Bs[cur][n + g][k + th + 4]);
            }
            #pragma unroll
            for (int i = 0; i < 2; i++)
                #pragma unroll
                for (int j = 0; j < 8; j++)
                    mma_tf32(acc[i][j], af[i], bf[j]);
        }

        if (t + 1 < nt) {
            const int nxt = cur ^ 1;
            #pragma unroll
            for (int h = 0; h < 2; h++) {
                float4 ca = make_float4(to_tf32(ra[h].x), to_tf32(ra[h].y),
                                        to_tf32(ra[h].z), to_tf32(ra[h].w));
                *(float4*)&As[nxt][lr + h * 64][lc] = ca;
                float4 cb = make_float4(to_tf32(rb[h].x), to_tf32(rb[h].y),
                                        to_tf32(rb[h].z), to_tf32(rb[h].w));
                *(float4*)&Bs[nxt][lr + h * 64][lc] = cb;
            }
        }
        __syncthreads();
    }

    // epilogue: c0,c1 -> (row g, cols 2*th, 2*th+1); c2,c3 -> row g+8
    #pragma unroll
    for (int i = 0; i < 2; i++) {
        #pragma unroll
        for (int r = 0; r < 2; r++) {
            const int m = bm + wm + i * 16 + g + r * 8;
            #pragma unroll
            for (int j = 0; j < 8; j++) {
                const int n = bn + wn + j * 8 + 2 * th;
                float v0 = acc[i][j][r * 2 + 0] + bias[n];
                float v1 = acc[i][j][r * 2 + 1] + bias[n + 1];
                if (EPI == 1) {
                    const float2 x = *(const float2*)&aux[(size_t)m * N + n];
                    v0 += x.x; v1 += x.y;
                }
                if (EPI == 2) {
                    const float2 x = *(const float2*)&aux[(size_t)m * N + n];
                    v0 *= x.x / (1.f + __expf(-x.x));
                    v1 *= x.y / (1.f + __expf(-x.y));
                }
                *(float2*)&C[(size_t)m * N + n] = make_float2(v0, v1);
            }
        }
    }
}

// ---------------- Flash attention with ALiBi (fp32 SIMT) ------------------
__global__ __launch_bounds__(256) void attn_kernel(
    const float* __restrict__ qkv, float* __restrict__ out)
{
    extern __shared__ float sm[];
    float (*Qts)[64] = (float(*)[64])(sm);            // [hd][q]
    float (*Kts)[64] = (float(*)[64])(sm + 4096);     // [hd][kv]
    float (*Vs)[64]  = (float(*)[64])(sm + 8192);     // [kv][hd]
    float (*Ps)[64]  = (float(*)[64])(sm + 12288);    // [q][kv]

    const int bq = blockIdx.x;
    const int h  = blockIdx.y;
    const int b  = blockIdx.z;
    const int tid = threadIdx.x;
    const int tx = tid & 15, ty = tid >> 4;

    const float scale = 0.125f;
    const float slope = exp2f(-0.5f * (float)(h + 1));

    const float* base = qkv + (size_t)b * SEQ * (3 * DMODEL);
    const float* qb = base + h * HDIM;
    const float* kb = base + DMODEL + h * HDIM;
    const float* vb = base + 2 * DMODEL + h * HDIM;

    #pragma unroll
    for (int it = 0; it < 4; it++) {
        const int i = tid + it * 256;
        const int r = i >> 4, c4 = (i & 15) * 4;
        float4 v = *(const float4*)&qb[(size_t)(bq * 64 + r) * (3 * DMODEL) + c4];
        Qts[c4 + 0][r] = v.x; Qts[c4 + 1][r] = v.y;
        Qts[c4 + 2][r] = v.z; Qts[c4 + 3][r] = v.w;
    }

    float m[4], l[4], O[4][4];
    #pragma unroll
    for (int i = 0; i < 4; i++) {
        m[i] = -1e30f; l[i] = 0.f;
        #pragma unroll
        for (int j = 0; j < 4; j++) O[i][j] = 0.f;
    }

    for (int t = 0; t < 16; t++) {
        __syncthreads();
        #pragma unroll
        for (int it = 0; it < 4; it++) {
            const int i = tid + it * 256;
            const int r = i >> 4, c4 = (i & 15) * 4;
            float4 kv4 = *(const float4*)&kb[(size_t)(t * 64 + r) * (3 * DMODEL) + c4];
            Kts[c4 + 0][r] = kv4.x; Kts[c4 + 1][r] = kv4.y;
            Kts[c4 + 2][r] = kv4.z; Kts[c4 + 3][r] = kv4.w;
            float4 vv = *(const float4*)&vb[(size_t)(t * 64 + r) * (3 * DMODEL) + c4];
            *(float4*)&Vs[r][c4] = vv;
        }
        __syncthreads();

        float s[4][4];
        #pragma unroll
        for (int i = 0; i < 4; i++)
            #pragma unroll
            for (int j = 0; j < 4; j++) s[i][j] = 0.f;
        #pragma unroll
        for (int k = 0; k < 64; k++) {
            const float4 qa = *(const float4*)&Qts[k][ty * 4];
            const float4 kk = *(const float4*)&Kts[k][tx * 4];
            const float qv[4] = {qa.x, qa.y, qa.z, qa.w};
            const float kvv[4] = {kk.x, kk.y, kk.z, kk.w};
            #pragma unroll
            for (int i = 0; i < 4; i++)
                #pragma unroll
                for (int j = 0; j < 4; j++)
                    s[i][j] = fmaf(qv[i], kvv[j], s[i][j]);
        }

        #pragma unroll
        for (int i = 0; i < 4; i++) {
            const int qp = bq * 64 + ty * 4 + i;
            float sv[4];
            float mx = -1e30f;
            #pragma unroll
            for (int j = 0; j < 4; j++) {
                const int kp = t * 64 + tx * 4 + j;
                sv[j] = s[i][j] * scale - slope * fabsf((float)(qp - kp));
                mx = fmaxf(mx, sv[j]);
            }
            #pragma unroll
            for (int off = 8; off >= 1; off >>= 1)
                mx = fmaxf(mx, __shfl_xor_sync(0xffffffffu, mx, off));
            const float mnew = fmaxf(m[i], mx);
            float p[4], ps = 0.f;
            #pragma unroll
            for (int j = 0; j < 4; j++) { p[j] = __expf(sv[j] - mnew); ps += p[j]; }
            #pragma unroll
            for (int off = 8; off >= 1; off >>= 1)
                ps += __shfl_xor_sync(0xffffffffu, ps, off);
            const float alpha = __expf(m[i] - mnew);
            l[i] = l[i] * alpha + ps;
            m[i] = mnew;
            #pragma unroll
            for (int j = 0; j < 4; j++) O[i][j] *= alpha;
            *(float4*)&Ps[ty * 4 + i][tx * 4] = make_float4(p[0], p[1], p[2], p[3]);
        }
        __syncthreads();

        #pragma unroll
        for (int kv = 0; kv < 64; kv++) {
            const float4 vv = *(const float4*)&Vs[kv][tx * 4];
            #pragma unroll
            for (int i = 0; i < 4; i++) {
                const float p = Ps[ty * 4 + i][kv];
                O[i][0] = fmaf(p, vv.x, O[i][0]);
                O[i][1] = fmaf(p, vv.y, O[i][1]);
                O[i][2] = fmaf(p, vv.z, O[i][2]);
                O[i][3] = fmaf(p, vv.w, O[i][3]);
            }
        }
    }

    #pragma unroll
    for (int i = 0; i < 4; i++) {
        const float inv = 1.f / l[i];
        const int qp = bq * 64 + ty * 4 + i;
        float4 o = make_float4(O[i][0] * inv, O[i][1] * inv, O[i][2] * inv, O[i][3] * inv);
        *(float4*)&out[((size_t)(b * SEQ + qp)) * DMODEL + h * HDIM + tx * 4] = o;
    }
}

// ---------------- launch ---------------------------------------------------
extern "C" void kernel_launch(void* const* d_in, const int* in_sizes, int n_in,
                              void* d_out, int out_size)
{
    const float* src    = (const float*)d_in[0];
    const float* wqkv   = (const float*)d_in[1];
    const float* bqkv   = (const float*)d_in[2];
    const float* wo     = (const float*)d_in[3];
    const float* bo     = (const float*)d_in[4];
    const float* g1     = (const float*)d_in[5];
    const float* b1     = (const float*)d_in[6];
    const float* g2     = (const float*)d_in[7];
    const float* b2     = (const float*)d_in[8];
    const float* w_gate = (const float*)d_in[9];
    const float* b_gate = (const float*)d_in[10];
    const float* w_up   = (const float*)d_in[11];
    const float* b_up   = (const float*)d_in[12];
    const float* w_down = (const float*)d_in[13];
    const float* b_down = (const float*)d_in[14];
    float* out = (float*)d_out;

    float *ln, *qkv, *att, *x1, *gate;
    cudaGetSymbolAddress((void**)&ln,   g_ln);
    cudaGetSymbolAddress((void**)&qkv,  g_qkv);
    cudaGetSymbolAddress((void**)&att,  g_att);
    cudaGetSymbolAddress((void**)&x1,   g_x1);
    cudaGetSymbolAddress((void**)&gate, g_gate);

    cudaFuncSetAttribute(attn_kernel,
                         cudaFuncAttributeMaxDynamicSharedMemorySize, 65536);

    // x = src + Attn(LN1(src))
    ln_kernel<<<MTOT, 256>>>(src, g1, b1, ln);
    gemm_tf32<0><<<dim3(64, 24), 256>>>(ln, wqkv, bqkv, nullptr, qkv,
                                        MTOT, 3 * DMODEL, DMODEL);
    attn_kernel<<<dim3(16, NHEAD, BATCH), 256, 65536>>>(qkv, att);
    gemm_tf32<1><<<dim3(64, 8), 256>>>(att, wo, bo, src, x1,
                                       MTOT, DMODEL, DMODEL);

    // x = x + SwiGLU(LN2(x))
    ln_kernel<<<MTOT, 256>>>(x1, g2, b2, ln);
    gemm_tf32<0><<<dim3(64, 32), 256>>>(ln, w_gate, b_gate, nullptr, gate,
                                        MTOT, DFFN, DMODEL);
    gemm_tf32<2><<<dim3(64, 32), 256>>>(ln, w_up, b_up, gate, gate,
                                        MTOT, DFFN, DMODEL);
    gemm_tf32<1><<<dim3(64, 8), 256>>>(gate, w_down, b_down, x1, out,
                                       MTOT, DMODEL, DFFN);
}

// round 5
// speedup vs baseline: 3.3113x; 1.7636x over previous
#include <cuda_runtime.h>
#include <math.h>
#include <stdint.h>

#define MTOT   8192
#define DMODEL 1024
#define DFFN   4096
#define NHEAD  16
#define HDIM   64
#define SEQ    1024
#define BATCH  8

// ---------------- scratch (device globals; no allocations) ----------------
__device__ float g_ln[MTOT * DMODEL];
__device__ float g_qkv[MTOT * 3 * DMODEL];
__device__ float g_att[MTOT * DMODEL];
__device__ float g_x1[MTOT * DMODEL];
__device__ float g_gate[MTOT * DFFN];
__device__ float g_w[16 * 1024 * 1024];     // tf32-rounded weights (64 MB)

#define W_QKV  0
#define W_O    (3 * 1024 * 1024)
#define W_G    (4 * 1024 * 1024)
#define W_U    (8 * 1024 * 1024)
#define W_D    (12 * 1024 * 1024)

// ---------------- PTX helpers ---------------------------------------------
__device__ __forceinline__ uint32_t smem_u32(const void* p) {
    uint32_t a;
    asm("{ .reg .u64 t; cvta.to.shared.u64 t, %1; cvt.u32.u64 %0, t; }"
        : "=r"(a) : "l"(p));
    return a;
}
__device__ __forceinline__ float to_tf32(float x) {
    uint32_t u;
    asm("cvt.rna.tf32.f32 %0, %1;" : "=r"(u) : "f"(x));
    return __uint_as_float(u);
}
__device__ __forceinline__ void cp16(uint32_t dst, const void* src) {
    asm volatile("cp.async.cg.shared.global [%0], [%1], 16;"
                 :: "r"(dst), "l"(src) : "memory");
}
__device__ __forceinline__ void cp_commit() {
    asm volatile("cp.async.commit_group;" ::: "memory");
}
template <int N>
__device__ __forceinline__ void cp_wait() {
    asm volatile("cp.async.wait_group %0;" :: "n"(N) : "memory");
}
__device__ __forceinline__ void ldsm_x4(uint32_t r[4], uint32_t addr) {
    asm volatile("ldmatrix.sync.aligned.m8n8.x4.shared.b16 {%0,%1,%2,%3}, [%4];"
        : "=r"(r[0]), "=r"(r[1]), "=r"(r[2]), "=r"(r[3]) : "r"(addr));
}
__device__ __forceinline__ void ldsm_x2(uint32_t r[2], uint32_t addr) {
    asm volatile("ldmatrix.sync.aligned.m8n8.x2.shared.b16 {%0,%1}, [%2];"
        : "=r"(r[0]), "=r"(r[1]) : "r"(addr));
}
__device__ __forceinline__ void mma_tf32(float c[4], const uint32_t a[4],
                                         const uint32_t b[2]) {
    asm volatile(
        "mma.sync.aligned.m16n8k8.row.col.f32.tf32.tf32.f32 "
        "{%0,%1,%2,%3}, {%4,%5,%6,%7}, {%8,%9}, {%0,%1,%2,%3};\n"
        : "+f"(c[0]), "+f"(c[1]), "+f"(c[2]), "+f"(c[3])
        : "r"(a[0]), "r"(a[1]), "r"(a[2]), "r"(a[3]), "r"(b[0]), "r"(b[1]));
}

// ---------------- weight tf32 pre-round ------------------------------------
__global__ __launch_bounds__(256) void round_w(
    const float4* __restrict__ in, float4* __restrict__ out, int n4)
{
    const int i = blockIdx.x * 256 + threadIdx.x;
    if (i < n4) {
        float4 v = in[i];
        out[i] = make_float4(to_tf32(v.x), to_tf32(v.y),
                             to_tf32(v.z), to_tf32(v.w));
    }
}

// ---------------- TF32 mma.sync NT GEMM ------------------------------------
// C[M, Ntot] = A[M, K] * W[Ntot, K]^T + bias. CTA 128x256, 8 warps (2x4),
// warp tile 64x64. 3-stage cp.async, XOR-swizzled smem, ldmatrix frags.
// EPI 0: +bias | 1: +bias+aux | 2: (+bias)*silu(aux). RND: tf32-round output.
#define GSTG_BYTES 24576     // A 8KB + B 16KB
#define GSMEM (3 * GSTG_BYTES)

__device__ __forceinline__ void g_issue(
    uint32_t sbase, int slot, const float* A, const float* W,
    int bm, int bn, int K, int k0, int tid)
{
    const uint32_t sb = sbase + slot * GSTG_BYTES;
    #pragma unroll
    for (int i = 0; i < 6; i++) {
        const int gi = tid + i * 256;
        if (gi < 512) {
            const int r = gi >> 2, c = gi & 3;
            cp16(sb + r * 64 + ((c ^ ((r >> 1) & 3)) * 16),
                 A + (size_t)(bm + r) * K + k0 + c * 4);
        } else {
            const int j = gi - 512;
            const int r = j >> 2, c = j & 3;
            cp16(sb + 8192 + r * 64 + ((c ^ ((r >> 1) & 3)) * 16),
                 W + (size_t)(bn + r) * K + k0 + c * 4);
        }
    }
}

template <int EPI, int RND>
__global__ __launch_bounds__(256, 1) void gemm_tc(
    const float* __restrict__ A, const float* __restrict__ W,
    const float* __restrict__ bias, const float* __restrict__ aux,
    float* __restrict__ C, int Ntot, int K)
{
    extern __shared__ float gsm[];
    const uint32_t sbase = smem_u32(gsm);
    const int tid = threadIdx.x, wid = tid >> 5, lane = tid & 31;
    const int g = lane >> 2, th = lane & 3;
    const int bm = blockIdx.x * 128, bn = blockIdx.y * 256;
    const int wm = (wid & 1) * 64, wn = (wid >> 1) * 64;

    float acc[4][8][4];
    #pragma unroll
    for (int mt = 0; mt < 4; mt++)
        #pragma unroll
        for (int nt = 0; nt < 8; nt++)
            #pragma unroll
            for (int c = 0; c < 4; c++) acc[mt][nt][c] = 0.f;

    const int NT = K >> 4;
    #pragma unroll
    for (int t = 0; t < 3; t++) {
        if (t < NT) g_issue(sbase, t, A, W, bm, bn, K, t * 16, tid);
        cp_commit();
    }

    for (int t = 0; t < NT; t++) {
        cp_wait<2>();
        __syncthreads();
        const uint32_t sa = sbase + (t % 3) * GSTG_BYTES;
        const uint32_t sb = sa + 8192;

        #pragma unroll
        for (int ks = 0; ks < 2; ks++) {
            uint32_t af[4][4], bf[8][2];
            #pragma unroll
            for (int mt = 0; mt < 4; mt++) {
                const int row = wm + mt * 16 + (lane & 15);
                const int gr = 2 * ks + (lane >> 4);
                ldsm_x4(af[mt], sa + row * 64 + ((gr ^ ((row >> 1) & 3)) * 16));
            }
            #pragma unroll
            for (int nt = 0; nt < 8; nt++) {
                const int row = wn + nt * 8 + (lane & 7);
                const int gr = 2 * ks + ((lane >> 3) & 1);
                ldsm_x2(bf[nt], sb + row * 64 + ((gr ^ ((row >> 1) & 3)) * 16));
            }
            #pragma unroll
            for (int mt = 0; mt < 4; mt++)
                #pragma unroll
                for (int nt = 0; nt < 8; nt++)
                    mma_tf32(acc[mt][nt], af[mt], bf[nt]);
        }
        __syncthreads();
        if (t + 3 < NT) g_issue(sbase, (t + 3) % 3, A, W, bm, bn, K,
                                (t + 3) * 16, tid);
        cp_commit();
    }

    #pragma unroll
    for (int mt = 0; mt < 4; mt++) {
        const int m0 = bm + wm + mt * 16 + g;
        #pragma unroll
        for (int nt = 0; nt < 8; nt++) {
            const int n = bn + wn + nt * 8 + 2 * th;
            const float b0 = bias[n], b1 = bias[n + 1];
            float v00 = acc[mt][nt][0] + b0, v01 = acc[mt][nt][1] + b1;
            float v10 = acc[mt][nt][2] + b0, v11 = acc[mt][nt][3] + b1;
            if (EPI == 1) {
                const float2 x0 = *(const float2*)&aux[(size_t)m0 * Ntot + n];
                const float2 x1 = *(const float2*)&aux[(size_t)(m0 + 8) * Ntot + n];
                v00 += x0.x; v01 += x0.y; v10 += x1.x; v11 += x1.y;
            }
            if (EPI == 2) {
                const float2 x0 = *(const float2*)&aux[(size_t)m0 * Ntot + n];
                const float2 x1 = *(const float2*)&aux[(size_t)(m0 + 8) * Ntot + n];
                v00 *= x0.x / (1.f + __expf(-x0.x));
                v01 *= x0.y / (1.f + __expf(-x0.y));
                v10 *= x1.x / (1.f + __expf(-x1.x));
                v11 *= x1.y / (1.f + __expf(-x1.y));
            }
            if (RND) {
                v00 = to_tf32(v00); v01 = to_tf32(v01);
                v10 = to_tf32(v10); v11 = to_tf32(v11);
            }
            *(float2*)&C[(size_t)m0 * Ntot + n]       = make_float2(v00, v01);
            *(float2*)&C[(size_t)(m0 + 8) * Ntot + n] = make_float2(v10, v11);
        }
    }
}

// ---------------- Flash attention with ALiBi, mma.sync tf32 ----------------
// 128 threads (4 warps); q-tile 64 rows (16 per warp); kv tiles of 64.
// smem floats: sK[64][68] @AK, sV[64][72] @AV, sP[warp][16][68] @AP (Q staging)
#define AK 0
#define AV (64 * 68)
#define AP (64 * 68 + 64 * 72)
#define ATT_SMEM ((64 * 68 + 64 * 72 + 4 * 16 * 68) * 4)

__global__ __launch_bounds__(128) void attn_mma(
    const float* __restrict__ qkv, float* __restrict__ out)
{
    extern __shared__ float sm[];
    const uint32_t sb = smem_u32(sm);
    const int tid = threadIdx.x, wid = tid >> 5, lane = tid & 31;
    const int g = lane >> 2, th = lane & 3;
    const int bq = blockIdx.x, h = blockIdx.y, b = blockIdx.z;
    const float slope = exp2f(-0.5f * (float)(h + 1));

    const float* base = qkv + (size_t)b * SEQ * 3072;

    // stage Q tile (64 x 64) into sP region (stride 68)
    {
        const float* qb = base + (size_t)(bq * 64) * 3072 + h * 64;
        for (int i = tid; i < 1024; i += 128) {
            const int r = i >> 4, gr = i & 15;
            cp16(sb + (AP + r * 68 + gr * 4) * 4, qb + (size_t)r * 3072 + gr * 4);
        }
        cp_commit();
        cp_wait<0>();
        __syncthreads();
    }

    // per-warp Q a-frags (rows wid*16..+15) held in regs
    uint32_t aQ[8][4];
    #pragma unroll
    for (int ks = 0; ks < 8; ks++) {
        const int r0 = AP + (wid * 16 + g) * 68 + ks * 8 + th;
        aQ[ks][0] = __float_as_uint(sm[r0]);
        aQ[ks][1] = __float_as_uint(sm[r0 + 8 * 68]);
        aQ[ks][2] = __float_as_uint(sm[r0 + 4]);
        aQ[ks][3] = __float_as_uint(sm[r0 + 8 * 68 + 4]);
    }
    __syncthreads();

    const int wp = AP + wid * (16 * 68);
    float m0 = -1e30f, m1 = -1e30f, l0 = 0.f, l1 = 0.f;
    float O[8][4];
    #pragma unroll
    for (int nt = 0; nt < 8; nt++)
        #pragma unroll
        for (int c = 0; c < 4; c++) O[nt][c] = 0.f;

    const int q0 = bq * 64 + wid * 16 + g;
    const int q1 = q0 + 8;

    for (int t = 0; t < 16; t++) {
        __syncthreads();
        const float* kb = base + (size_t)(t * 64) * 3072 + DMODEL + h * 64;
        const float* vb = kb + DMODEL;
        for (int i = tid; i < 1024; i += 128) {
            const int r = i >> 4, gr = i & 15;
            cp16(sb + (AK + r * 68 + gr * 4) * 4, kb + (size_t)r * 3072 + gr * 4);
            cp16(sb + (AV + r * 72 + gr * 4) * 4, vb + (size_t)r * 3072 + gr * 4);
        }
        cp_commit();
        cp_wait<0>();
        __syncthreads();

        // S = Q K^T (16 x 64 per warp)
        float S[8][4];
        #pragma unroll
        for (int nt = 0; nt < 8; nt++) {
            #pragma unroll
            for (int c = 0; c < 4; c++) S[nt][c] = 0.f;
            #pragma unroll
            for (int ks = 0; ks < 8; ks++) {
                uint32_t bf[2];
                const int bi = AK + (nt * 8 + g) * 68 + ks * 8 + th;
                bf[0] = __float_as_uint(sm[bi]);
                bf[1] = __float_as_uint(sm[bi + 4]);
                mma_tf32(S[nt], aQ[ks], bf);
            }
        }

        // ALiBi + online softmax (rows q0 via c0/c1, q1 via c2/c3)
        float mx0 = -1e30f, mx1 = -1e30f;
        #pragma unroll
        for (int nt = 0; nt < 8; nt++) {
            const int kc = t * 64 + nt * 8 + 2 * th;
            S[nt][0] = S[nt][0] * 0.125f - slope * fabsf((float)(q0 - kc));
            S[nt][1] = S[nt][1] * 0.125f - slope * fabsf((float)(q0 - kc - 1));
            S[nt][2] = S[nt][2] * 0.125f - slope * fabsf((float)(q1 - kc));
            S[nt][3] = S[nt][3] * 0.125f - slope * fabsf((float)(q1 - kc - 1));
            mx0 = fmaxf(mx0, fmaxf(S[nt][0], S[nt][1]));
            mx1 = fmaxf(mx1, fmaxf(S[nt][2], S[nt][3]));
        }
        #pragma unroll
        for (int off = 1; off <= 2; off <<= 1) {
            mx0 = fmaxf(mx0, __shfl_xor_sync(0xffffffffu, mx0, off));
            mx1 = fmaxf(mx1, __shfl_xor_sync(0xffffffffu, mx1, off));
        }
        const float mn0 = fmaxf(m0, mx0), mn1 = fmaxf(m1, mx1);
        const float sc0 = __expf(m0 - mn0), sc1 = __expf(m1 - mn1);
        float s0 = 0.f, s1 = 0.f;
        #pragma unroll
        for (int nt = 0; nt < 8; nt++) {
            const float p00 = to_tf32(__expf(S[nt][0] - mn0));
            const float p01 = to_tf32(__expf(S[nt][1] - mn0));
            const float p10 = to_tf32(__expf(S[nt][2] - mn1));
            const float p11 = to_tf32(__expf(S[nt][3] - mn1));
            s0 += p00 + p01; s1 += p10 + p11;
            *(float2*)&sm[wp + g * 68 + nt * 8 + 2 * th] = make_float2(p00, p01);
            *(float2*)&sm[wp + (g + 8) * 68 + nt * 8 + 2 * th] = make_float2(p10, p11);
        }
        #pragma unroll
        for (int off = 1; off <= 2; off <<= 1) {
            s0 += __shfl_xor_sync(0xffffffffu, s0, off);
            s1 += __shfl_xor_sync(0xffffffffu, s1, off);
        }
        l0 = l0 * sc0 + s0; l1 = l1 * sc1 + s1;
        m0 = mn0; m1 = mn1;
        #pragma unroll
        for (int nt = 0; nt < 8; nt++) {
            O[nt][0] *= sc0; O[nt][1] *= sc0;
            O[nt][2] *= sc1; O[nt][3] *= sc1;
        }
        __syncwarp();

        // O += P V
        #pragma unroll
        for (int ks = 0; ks < 8; ks++) {
            uint32_t aP[4];
            const int pi = wp + g * 68 + ks * 8 + th;
            aP[0] = __float_as_uint(sm[pi]);
            aP[1] = __float_as_uint(sm[pi + 8 * 68]);
            aP[2] = __float_as_uint(sm[pi + 4]);
            aP[3] = __float_as_uint(sm[pi + 8 * 68 + 4]);
            #pragma unroll
            for (int nt = 0; nt < 8; nt++) {
                uint32_t bf[2];
                bf[0] = __float_as_uint(sm[AV + (ks * 8 + th) * 72 + nt * 8 + g]);
                bf[1] = __float_as_uint(sm[AV + (ks * 8 + th + 4) * 72 + nt * 8 + g]);
                mma_tf32(O[nt], aP, bf);
            }
        }
        __syncwarp();
    }

    const float i0 = 1.f / l0, i1 = 1.f / l1;
    #pragma unroll
    for (int nt = 0; nt < 8; nt++) {
        const int n = h * 64 + nt * 8 + 2 * th;
        *(float2*)&out[(size_t)(b * SEQ + q0) * DMODEL + n] =
            make_float2(to_tf32(O[nt][0] * i0), to_tf32(O[nt][1] * i0));
        *(float2*)&out[(size_t)(b * SEQ + q1) * DMODEL + n] =
            make_float2(to_tf32(O[nt][2] * i1), to_tf32(O[nt][3] * i1));
    }
}

// ---------------- LayerNorm (tf32-rounded output) ---------------------------
__global__ __launch_bounds__(256) void ln_kernel(
    const float* __restrict__ x, const float* __restrict__ g,
    const float* __restrict__ b, float* __restrict__ y)
{
    __shared__ float redS[8];
    __shared__ float redQ[8];
    const int row = blockIdx.x;
    const int tid = threadIdx.x;

    const float4 v = ((const float4*)(x + (size_t)row * DMODEL))[tid];
    float s = v.x + v.y + v.z + v.w;
    float q = v.x*v.x + v.y*v.y + v.z*v.z + v.w*v.w;
    #pragma unroll
    for (int off = 16; off >= 1; off >>= 1) {
        s += __shfl_xor_sync(0xffffffffu, s, off);
        q += __shfl_xor_sync(0xffffffffu, q, off);
    }
    if ((tid & 31) == 0) { redS[tid >> 5] = s; redQ[tid >> 5] = q; }
    __syncthreads();
    if (tid < 32) {
        s = (tid < 8) ? redS[tid] : 0.f;
        q = (tid < 8) ? redQ[tid] : 0.f;
        #pragma unroll
        for (int off = 4; off >= 1; off >>= 1) {
            s += __shfl_xor_sync(0xffffffffu, s, off);
            q += __shfl_xor_sync(0xffffffffu, q, off);
        }
        if (tid == 0) { redS[0] = s; redQ[0] = q; }
    }
    __syncthreads();
    const float mu  = redS[0] * (1.f / DMODEL);
    const float var = redQ[0] * (1.f / DMODEL) - mu * mu;
    const float rstd = rsqrtf(var + 1e-5f);

    const float4 gv = ((const float4*)g)[tid];
    const float4 bv = ((const float4*)b)[tid];
    float4 o;
    o.x = to_tf32((v.x - mu) * rstd * gv.x + bv.x);
    o.y = to_tf32((v.y - mu) * rstd * gv.y + bv.y);
    o.z = to_tf32((v.z - mu) * rstd * gv.z + bv.z);
    o.w = to_tf32((v.w - mu) * rstd * gv.w + bv.w);
    ((float4*)(y + (size_t)row * DMODEL))[tid] = o;
}

// ---------------- launch -----------------------------------------------------
extern "C" void kernel_launch(void* const* d_in, const int* in_sizes, int n_in,
                              void* d_out, int out_size)
{
    const float* src    = (const float*)d_in[0];
    const float* wqkv   = (const float*)d_in[1];
    const float* bqkv   = (const float*)d_in[2];
    const float* wo     = (const float*)d_in[3];
    const float* bo     = (const float*)d_in[4];
    const float* g1     = (const float*)d_in[5];
    const float* b1     = (const float*)d_in[6];
    const float* g2     = (const float*)d_in[7];
    const float* b2     = (const float*)d_in[8];
    const float* w_gate = (const float*)d_in[9];
    const float* b_gate = (const float*)d_in[10];
    const float* w_up   = (const float*)d_in[11];
    const float* b_up   = (const float*)d_in[12];
    const float* w_down = (const float*)d_in[13];
    const float* b_down = (const float*)d_in[14];
    float* out = (float*)d_out;

    float *ln, *qkv, *att, *x1, *gate, *wbuf;
    cudaGetSymbolAddress((void**)&ln,   g_ln);
    cudaGetSymbolAddress((void**)&qkv,  g_qkv);
    cudaGetSymbolAddress((void**)&att,  g_att);
    cudaGetSymbolAddress((void**)&x1,   g_x1);
    cudaGetSymbolAddress((void**)&gate, g_gate);
    cudaGetSymbolAddress((void**)&wbuf, g_w);

    cudaFuncSetAttribute(gemm_tc<0, 1>,
        cudaFuncAttributeMaxDynamicSharedMemorySize, GSMEM);
    cudaFuncSetAttribute(gemm_tc<0, 0>,
        cudaFuncAttributeMaxDynamicSharedMemorySize, GSMEM);
    cudaFuncSetAttribute(gemm_tc<1, 0>,
        cudaFuncAttributeMaxDynamicSharedMemorySize, GSMEM);
    cudaFuncSetAttribute(gemm_tc<2, 1>,
        cudaFuncAttributeMaxDynamicSharedMemorySize, GSMEM);
    cudaFuncSetAttribute(attn_mma,
        cudaFuncAttributeMaxDynamicSharedMemorySize, ATT_SMEM);

    // pre-round weights to tf32 (rna)
    round_w<<<3072, 256>>>((const float4*)wqkv,   (float4*)(wbuf + W_QKV), 786432);
    round_w<<<1024, 256>>>((const float4*)wo,     (float4*)(wbuf + W_O),   262144);
    round_w<<<4096, 256>>>((const float4*)w_gate, (float4*)(wbuf + W_G),  1048576);
    round_w<<<4096, 256>>>((const float4*)w_up,   (float4*)(wbuf + W_U),  1048576);
    round_w<<<4096, 256>>>((const float4*)w_down, (float4*)(wbuf + W_D),  1048576);

    // x = src + Attn(LN1(src))
    ln_kernel<<<MTOT, 256>>>(src, g1, b1, ln);
    gemm_tc<0, 1><<<dim3(64, 12), 256, GSMEM>>>(ln, wbuf + W_QKV, bqkv, nullptr,
                                                qkv, 3 * DMODEL, DMODEL);
    attn_mma<<<dim3(16, NHEAD, BATCH), 128, ATT_SMEM>>>(qkv, att);
    gemm_tc<1, 0><<<dim3(64, 4), 256, GSMEM>>>(att, wbuf + W_O, bo, src,
                                               x1, DMODEL, DMODEL);

    // x = x + SwiGLU(LN2(x))
    ln_kernel<<<MTOT, 256>>>(x1, g2, b2, ln);
    gemm_tc<0, 0><<<dim3(64, 16), 256, GSMEM>>>(ln, wbuf + W_G, b_gate, nullptr,
                                                gate, DFFN, DMODEL);
    gemm_tc<2, 1><<<dim3(64, 16), 256, GSMEM>>>(ln, wbuf + W_U, b_up, gate,
                                                gate, DFFN, DMODEL);
    gemm_tc<1, 0><<<dim3(64, 4), 256, GSMEM>>>(gate, wbuf + W_D, b_down, x1,
                                               out, DMODEL, DFFN);
}

// round 6
// speedup vs baseline: 3.5186x; 1.0626x over previous
#include <cuda_runtime.h>
#include <math.h>
#include <stdint.h>

#define MTOT   8192
#define DMODEL 1024
#define DFFN   4096
#define NHEAD  16
#define HDIM   64
#define SEQ    1024
#define BATCH  8

// ---------------- scratch (device globals; no allocations) ----------------
__device__ float g_ln[MTOT * DMODEL];
__device__ float g_qkv[MTOT * 3 * DMODEL];
__device__ float g_att[MTOT * DMODEL];
__device__ float g_x1[MTOT * DMODEL];
__device__ float g_h[MTOT * DFFN];          // fused silu(gate)*up
__device__ float g_w[16 * 1024 * 1024];     // tf32-rounded weights (64 MB)

#define W_QKV  0
#define W_O    (3 * 1024 * 1024)
#define W_G    (4 * 1024 * 1024)
#define W_U    (8 * 1024 * 1024)
#define W_D    (12 * 1024 * 1024)

// ---------------- PTX helpers ---------------------------------------------
__device__ __forceinline__ uint32_t smem_u32(const void* p) {
    uint32_t a;
    asm("{ .reg .u64 t; cvta.to.shared.u64 t, %1; cvt.u32.u64 %0, t; }"
        : "=r"(a) : "l"(p));
    return a;
}
__device__ __forceinline__ float to_tf32(float x) {
    uint32_t u;
    asm("cvt.rna.tf32.f32 %0, %1;" : "=r"(u) : "f"(x));
    return __uint_as_float(u);
}
__device__ __forceinline__ void cp16(uint32_t dst, const void* src) {
    asm volatile("cp.async.cg.shared.global [%0], [%1], 16;"
                 :: "r"(dst), "l"(src) : "memory");
}
__device__ __forceinline__ void cp_commit() {
    asm volatile("cp.async.commit_group;" ::: "memory");
}
template <int N>
__device__ __forceinline__ void cp_wait() {
    asm volatile("cp.async.wait_group %0;" :: "n"(N) : "memory");
}
__device__ __forceinline__ void ldsm_x4(uint32_t r[4], uint32_t addr) {
    asm volatile("ldmatrix.sync.aligned.m8n8.x4.shared.b16 {%0,%1,%2,%3}, [%4];"
        : "=r"(r[0]), "=r"(r[1]), "=r"(r[2]), "=r"(r[3]) : "r"(addr));
}
__device__ __forceinline__ void ldsm_x2(uint32_t r[2], uint32_t addr) {
    asm volatile("ldmatrix.sync.aligned.m8n8.x2.shared.b16 {%0,%1}, [%2];"
        : "=r"(r[0]), "=r"(r[1]) : "r"(addr));
}
__device__ __forceinline__ void mma_tf32(float c[4], const uint32_t a[4],
                                         const uint32_t b[2]) {
    asm volatile(
        "mma.sync.aligned.m16n8k8.row.col.f32.tf32.tf32.f32 "
        "{%0,%1,%2,%3}, {%4,%5,%6,%7}, {%8,%9}, {%0,%1,%2,%3};\n"
        : "+f"(c[0]), "+f"(c[1]), "+f"(c[2]), "+f"(c[3])
        : "r"(a[0]), "r"(a[1]), "r"(a[2]), "r"(a[3]), "r"(b[0]), "r"(b[1]));
}

// ---------------- weight tf32 pre-round ------------------------------------
__global__ __launch_bounds__(256) void round_w(
    const float4* __restrict__ in, float4* __restrict__ out, int n4)
{
    const int i = blockIdx.x * 256 + threadIdx.x;
    if (i < n4) {
        float4 v = in[i];
        out[i] = make_float4(to_tf32(v.x), to_tf32(v.y),
                             to_tf32(v.z), to_tf32(v.w));
    }
}

// ---------------- TF32 mma.sync NT GEMM ------------------------------------
// C[M, Ntot] = A[M, K] * W[Ntot, K]^T + bias. CTA 128x256, 8 warps (2x4),
// warp tile 64x64. 4-stage cp.async, XOR-swizzled smem, ldmatrix frags.
// EPI 0: +bias | 1: +bias+aux. RND: tf32-round output.
#define GSTG_BYTES 24576     // A 8KB + B 16KB
#define GSMEM (4 * GSTG_BYTES)

__device__ __forceinline__ void g_issue(
    uint32_t sbase, int slot, const float* A, const float* W,
    int bm, int bn, int K, int k0, int tid)
{
    const uint32_t sb = sbase + slot * GSTG_BYTES;
    #pragma unroll
    for (int i = 0; i < 6; i++) {
        const int gi = tid + i * 256;
        if (gi < 512) {
            const int r = gi >> 2, c = gi & 3;
            cp16(sb + r * 64 + ((c ^ ((r >> 1) & 3)) * 16),
                 A + (size_t)(bm + r) * K + k0 + c * 4);
        } else {
            const int j = gi - 512;
            const int r = j >> 2, c = j & 3;
            cp16(sb + 8192 + r * 64 + ((c ^ ((r >> 1) & 3)) * 16),
                 W + (size_t)(bn + r) * K + k0 + c * 4);
        }
    }
}

template <int EPI, int RND>
__global__ __launch_bounds__(256, 1) void gemm_tc(
    const float* __restrict__ A, const float* __restrict__ W,
    const float* __restrict__ bias, const float* __restrict__ aux,
    float* __restrict__ C, int Ntot, int K)
{
    extern __shared__ float gsm[];
    const uint32_t sbase = smem_u32(gsm);
    const int tid = threadIdx.x, wid = tid >> 5, lane = tid & 31;
    const int g = lane >> 2, th = lane & 3;
    const int bm = blockIdx.x * 128, bn = blockIdx.y * 256;
    const int wm = (wid & 1) * 64, wn = (wid >> 1) * 64;

    float acc[4][8][4];
    #pragma unroll
    for (int mt = 0; mt < 4; mt++)
        #pragma unroll
        for (int nt = 0; nt < 8; nt++)
            #pragma unroll
            for (int c = 0; c < 4; c++) acc[mt][nt][c] = 0.f;

    const int NT = K >> 4;
    #pragma unroll
    for (int t = 0; t < 4; t++) {
        if (t < NT) g_issue(sbase, t, A, W, bm, bn, K, t * 16, tid);
        cp_commit();
    }

    for (int t = 0; t < NT; t++) {
        cp_wait<3>();
        __syncthreads();
        const uint32_t sa = sbase + (t & 3) * GSTG_BYTES;
        const uint32_t sb = sa + 8192;

        #pragma unroll
        for (int ks = 0; ks < 2; ks++) {
            uint32_t af[4][4], bf[8][2];
            #pragma unroll
            for (int mt = 0; mt < 4; mt++) {
                const int row = wm + mt * 16 + (lane & 15);
                const int gr = 2 * ks + (lane >> 4);
                ldsm_x4(af[mt], sa + row * 64 + ((gr ^ ((row >> 1) & 3)) * 16));
            }
            #pragma unroll
            for (int nt = 0; nt < 8; nt++) {
                const int row = wn + nt * 8 + (lane & 7);
                const int gr = 2 * ks + ((lane >> 3) & 1);
                ldsm_x2(bf[nt], sb + row * 64 + ((gr ^ ((row >> 1) & 3)) * 16));
            }
            #pragma unroll
            for (int mt = 0; mt < 4; mt++)
                #pragma unroll
                for (int nt = 0; nt < 8; nt++)
                    mma_tf32(acc[mt][nt], af[mt], bf[nt]);
        }
        __syncthreads();
        if (t + 4 < NT) g_issue(sbase, t & 3, A, W, bm, bn, K,
                                (t + 4) * 16, tid);
        cp_commit();
    }

    #pragma unroll
    for (int mt = 0; mt < 4; mt++) {
        const int m0 = bm + wm + mt * 16 + g;
        #pragma unroll
        for (int nt = 0; nt < 8; nt++) {
            const int n = bn + wn + nt * 8 + 2 * th;
            const float b0 = bias[n], b1 = bias[n + 1];
            float v00 = acc[mt][nt][0] + b0, v01 = acc[mt][nt][1] + b1;
            float v10 = acc[mt][nt][2] + b0, v11 = acc[mt][nt][3] + b1;
            if (EPI == 1) {
                const float2 x0 = *(const float2*)&aux[(size_t)m0 * Ntot + n];
                const float2 x1 = *(const float2*)&aux[(size_t)(m0 + 8) * Ntot + n];
                v00 += x0.x; v01 += x0.y; v10 += x1.x; v11 += x1.y;
            }
            if (RND) {
                v00 = to_tf32(v00); v01 = to_tf32(v01);
                v10 = to_tf32(v10); v11 = to_tf32(v11);
            }
            *(float2*)&C[(size_t)m0 * Ntot + n]       = make_float2(v00, v01);
            *(float2*)&C[(size_t)(m0 + 8) * Ntot + n] = make_float2(v10, v11);
        }
    }
}

// ---------------- Fused SwiGLU GEMM ----------------------------------------
// H[M, DFFN] = silu(A Wg^T + bg) * (A Wu^T + bu). CTA 128x128, 8 warps (2x4),
// warp tile 64x32, dual accumulators, 4-stage cp.async.
#define USTG_BYTES 24576     // A 8KB + Wg 8KB + Wu 8KB
#define USMEM (4 * USTG_BYTES)

__device__ __forceinline__ void u_issue(
    uint32_t sbase, int slot, const float* A, const float* Wg, const float* Wu,
    int bm, int bn, int k0, int tid)
{
    const uint32_t sb = sbase + slot * USTG_BYTES;
    #pragma unroll
    for (int i = 0; i < 6; i++) {
        const int gi = tid + i * 256;
        const int r = (gi & 511) >> 2, c = gi & 3;
        const uint32_t dst = r * 64 + ((c ^ ((r >> 1) & 3)) * 16);
        if (gi < 512)
            cp16(sb + dst, A + (size_t)(bm + r) * DMODEL + k0 + c * 4);
        else if (gi < 1024)
            cp16(sb + 8192 + dst, Wg + (size_t)(bn + r) * DMODEL + k0 + c * 4);
        else
            cp16(sb + 16384 + dst, Wu + (size_t)(bn + r) * DMODEL + k0 + c * 4);
    }
}

__global__ __launch_bounds__(256, 1) void gemm_glu(
    const float* __restrict__ A, const float* __restrict__ Wg,
    const float* __restrict__ Wu, const float* __restrict__ bg,
    const float* __restrict__ bu, float* __restrict__ H)
{
    extern __shared__ float usm[];
    const uint32_t sbase = smem_u32(usm);
    const int tid = threadIdx.x, wid = tid >> 5, lane = tid & 31;
    const int g = lane >> 2, th = lane & 3;
    const int bm = blockIdx.x * 128, bn = blockIdx.y * 128;
    const int wm = (wid & 1) * 64, wn = (wid >> 1) * 32;

    float accG[4][4][4], accU[4][4][4];
    #pragma unroll
    for (int mt = 0; mt < 4; mt++)
        #pragma unroll
        for (int nt = 0; nt < 4; nt++)
            #pragma unroll
            for (int c = 0; c < 4; c++) { accG[mt][nt][c] = 0.f; accU[mt][nt][c] = 0.f; }

    const int NT = DMODEL >> 4;   // 64
    #pragma unroll
    for (int t = 0; t < 4; t++) {
        u_issue(sbase, t, A, Wg, Wu, bm, bn, t * 16, tid);
        cp_commit();
    }

    for (int t = 0; t < NT; t++) {
        cp_wait<3>();
        __syncthreads();
        const uint32_t sa = sbase + (t & 3) * USTG_BYTES;

        #pragma unroll
        for (int ks = 0; ks < 2; ks++) {
            uint32_t af[4][4], bG[4][2], bU[4][2];
            #pragma unroll
            for (int mt = 0; mt < 4; mt++) {
                const int row = wm + mt * 16 + (lane & 15);
                const int gr = 2 * ks + (lane >> 4);
                ldsm_x4(af[mt], sa + row * 64 + ((gr ^ ((row >> 1) & 3)) * 16));
            }
            #pragma unroll
            for (int nt = 0; nt < 4; nt++) {
                const int row = wn + nt * 8 + (lane & 7);
                const int gr = 2 * ks + ((lane >> 3) & 1);
                const uint32_t off = row * 64 + ((gr ^ ((row >> 1) & 3)) * 16);
                ldsm_x2(bG[nt], sa + 8192 + off);
                ldsm_x2(bU[nt], sa + 16384 + off);
            }
            #pragma unroll
            for (int mt = 0; mt < 4; mt++)
                #pragma unroll
                for (int nt = 0; nt < 4; nt++) {
                    mma_tf32(accG[mt][nt], af[mt], bG[nt]);
                    mma_tf32(accU[mt][nt], af[mt], bU[nt]);
                }
        }
        __syncthreads();
        if (t + 4 < NT) u_issue(sbase, t & 3, A, Wg, Wu, bm, bn,
                                (t + 4) * 16, tid);
        cp_commit();
    }

    #pragma unroll
    for (int mt = 0; mt < 4; mt++) {
        const int m0 = bm + wm + mt * 16 + g;
        #pragma unroll
        for (int nt = 0; nt < 4; nt++) {
            const int n = bn + wn + nt * 8 + 2 * th;
            const float bg0 = bg[n], bg1 = bg[n + 1];
            const float bu0 = bu[n], bu1 = bu[n + 1];
            #pragma unroll
            for (int r = 0; r < 2; r++) {
                const float ga = accG[mt][nt][2 * r]     + bg0;
                const float gb = accG[mt][nt][2 * r + 1] + bg1;
                const float ua = accU[mt][nt][2 * r]     + bu0;
                const float ub = accU[mt][nt][2 * r + 1] + bu1;
                const float ha = to_tf32(ua * ga / (1.f + __expf(-ga)));
                const float hb = to_tf32(ub * gb / (1.f + __expf(-gb)));
                *(float2*)&H[(size_t)(m0 + 8 * r) * DFFN + n] = make_float2(ha, hb);
            }
        }
    }
}

// ---------------- Flash attention: 128-q tiles, double-buffered K/V --------
// 256 threads (8 warps), each warp 16 q rows. smem floats:
// K stage s: [64][68] @ s*KVSTG ; V stage s: [64][72] @ s*KVSTG+64*68
// P/Q region: [128][68] @ 2*KVSTG (warp wid owns rows wid*16..+15)
#define KVSTG (64 * 68 + 64 * 72)
#define APQ   (2 * KVSTG)
#define ATT_SMEM ((2 * KVSTG + 128 * 68) * 4)

__device__ __forceinline__ void kv_issue(
    uint32_t sb, int slot, const float* kb, const float* vb, int tid)
{
    const int kbase = slot * KVSTG;
    const int vbase = slot * KVSTG + 64 * 68;
    #pragma unroll
    for (int i = 0; i < 4; i++) {
        const int gi = tid + i * 256;
        const int r = gi >> 4, gr = gi & 15;
        cp16(sb + (kbase + r * 68 + gr * 4) * 4, kb + (size_t)r * 3072 + gr * 4);
        cp16(sb + (vbase + r * 72 + gr * 4) * 4, vb + (size_t)r * 3072 + gr * 4);
    }
}

__global__ __launch_bounds__(256) void attn_mma(
    const float* __restrict__ qkv, float* __restrict__ out)
{
    extern __shared__ float sm[];
    const uint32_t sb = smem_u32(sm);
    const int tid = threadIdx.x, wid = tid >> 5, lane = tid & 31;
    const int g = lane >> 2, th = lane & 3;
    const int bq = blockIdx.x, h = blockIdx.y, b = blockIdx.z;
    const float slope = exp2f(-0.5f * (float)(h + 1));

    const float* base = qkv + (size_t)b * SEQ * 3072;

    // stage Q tile (128 x 64) into P/Q region (stride 68)
    {
        const float* qb = base + (size_t)(bq * 128) * 3072 + h * 64;
        #pragma unroll
        for (int i = 0; i < 8; i++) {
            const int gi = tid + i * 256;
            const int r = gi >> 4, gr = gi & 15;
            cp16(sb + (APQ + r * 68 + gr * 4) * 4, qb + (size_t)r * 3072 + gr * 4);
        }
        cp_commit();
        cp_wait<0>();
        __syncthreads();
    }

    // per-warp Q a-frags (rows wid*16..+15) in regs
    uint32_t aQ[8][4];
    #pragma unroll
    for (int ks = 0; ks < 8; ks++) {
        const int r0 = APQ + (wid * 16 + g) * 68 + ks * 8 + th;
        aQ[ks][0] = __float_as_uint(sm[r0]);
        aQ[ks][1] = __float_as_uint(sm[r0 + 8 * 68]);
        aQ[ks][2] = __float_as_uint(sm[r0 + 4]);
        aQ[ks][3] = __float_as_uint(sm[r0 + 8 * 68 + 4]);
    }
    __syncthreads();

    const int wp = APQ + wid * (16 * 68);
    float m0 = -1e30f, m1 = -1e30f, l0 = 0.f, l1 = 0.f;
    float O[8][4];
    #pragma unroll
    for (int nt = 0; nt < 8; nt++)
        #pragma unroll
        for (int c = 0; c < 4; c++) O[nt][c] = 0.f;

    const int q0 = bq * 128 + wid * 16 + g;
    const int q1 = q0 + 8;
    const float* kb0 = base + DMODEL + h * 64;
    const float* vb0 = base + 2 * DMODEL + h * 64;

    kv_issue(sb, 0, kb0, vb0, tid);
    cp_commit();

    for (int t = 0; t < 16; t++) {
        if (t + 1 < 16) {
            kv_issue(sb, (t + 1) & 1, kb0 + (size_t)((t + 1) * 64) * 3072,
                     vb0 + (size_t)((t + 1) * 64) * 3072, tid);
        }
        cp_commit();
        cp_wait<1>();
        __syncthreads();

        const int AK = (t & 1) * KVSTG;
        const int AV = AK + 64 * 68;

        // S = Q K^T (16 x 64 per warp)
        float S[8][4];
        #pragma unroll
        for (int nt = 0; nt < 8; nt++) {
            #pragma unroll
            for (int c = 0; c < 4; c++) S[nt][c] = 0.f;
            #pragma unroll
            for (int ks = 0; ks < 8; ks++) {
                uint32_t bf[2];
                const int bi = AK + (nt * 8 + g) * 68 + ks * 8 + th;
                bf[0] = __float_as_uint(sm[bi]);
                bf[1] = __float_as_uint(sm[bi + 4]);
                mma_tf32(S[nt], aQ[ks], bf);
            }
        }

        // ALiBi + online softmax
        float mx0 = -1e30f, mx1 = -1e30f;
        #pragma unroll
        for (int nt = 0; nt < 8; nt++) {
            const int kc = t * 64 + nt * 8 + 2 * th;
            S[nt][0] = S[nt][0] * 0.125f - slope * fabsf((float)(q0 - kc));
            S[nt][1] = S[nt][1] * 0.125f - slope * fabsf((float)(q0 - kc - 1));
            S[nt][2] = S[nt][2] * 0.125f - slope * fabsf((float)(q1 - kc));
            S[nt][3] = S[nt][3] * 0.125f - slope * fabsf((float)(q1 - kc - 1));
            mx0 = fmaxf(mx0, fmaxf(S[nt][0], S[nt][1]));
            mx1 = fmaxf(mx1, fmaxf(S[nt][2], S[nt][3]));
        }
        #pragma unroll
        for (int off = 1; off <= 2; off <<= 1) {
            mx0 = fmaxf(mx0, __shfl_xor_sync(0xffffffffu, mx0, off));
            mx1 = fmaxf(mx1, __shfl_xor_sync(0xffffffffu, mx1, off));
        }
        const float mn0 = fmaxf(m0, mx0), mn1 = fmaxf(m1, mx1);
        const float sc0 = __expf(m0 - mn0), sc1 = __expf(m1 - mn1);
        float s0 = 0.f, s1 = 0.f;
        #pragma unroll
        for (int nt = 0; nt < 8; nt++) {
            const float p00 = to_tf32(__expf(S[nt][0] - mn0));
            const float p01 = to_tf32(__expf(S[nt][1] - mn0));
            const float p10 = to_tf32(__expf(S[nt][2] - mn1));
            const float p11 = to_tf32(__expf(S[nt][3] - mn1));
            s0 += p00 + p01; s1 += p10 + p11;
            *(float2*)&sm[wp + g * 68 + nt * 8 + 2 * th] = make_float2(p00, p01);
            *(float2*)&sm[wp + (g + 8) * 68 + nt * 8 + 2 * th] = make_float2(p10, p11);
        }
        #pragma unroll
        for (int off = 1; off <= 2; off <<= 1) {
            s0 += __shfl_xor_sync(0xffffffffu, s0, off);
            s1 += __shfl_xor_sync(0xffffffffu, s1, off);
        }
        l0 = l0 * sc0 + s0; l1 = l1 * sc1 + s1;
        m0 = mn0; m1 = mn1;
        #pragma unroll
        for (int nt = 0; nt < 8; nt++) {
            O[nt][0] *= sc0; O[nt][1] *= sc0;
            O[nt][2] *= sc1; O[nt][3] *= sc1;
        }
        __syncwarp();

        // O += P V
        #pragma unroll
        for (int ks = 0; ks < 8; ks++) {
            uint32_t aP[4];
            const int pi = wp + g * 68 + ks * 8 + th;
            aP[0] = __float_as_uint(sm[pi]);
            aP[1] = __float_as_uint(sm[pi + 8 * 68]);
            aP[2] = __float_as_uint(sm[pi + 4]);
            aP[3] = __float_as_uint(sm[pi + 8 * 68 + 4]);
            #pragma unroll
            for (int nt = 0; nt < 8; nt++) {
                uint32_t bf[2];
                bf[0] = __float_as_uint(sm[AV + (ks * 8 + th) * 72 + nt * 8 + g]);
                bf[1] = __float_as_uint(sm[AV + (ks * 8 + th + 4) * 72 + nt * 8 + g]);
                mma_tf32(O[nt], aP, bf);
            }
        }
        __syncthreads();   // all warps done with this K/V buffer before refill
    }

    const float i0 = 1.f / l0, i1 = 1.f / l1;
    #pragma unroll
    for (int nt = 0; nt < 8; nt++) {
        const int n = h * 64 + nt * 8 + 2 * th;
        *(float2*)&out[(size_t)(b * SEQ + q0) * DMODEL + n] =
            make_float2(to_tf32(O[nt][0] * i0), to_tf32(O[nt][1] * i0));
        *(float2*)&out[(size_t)(b * SEQ + q1) * DMODEL + n] =
            make_float2(to_tf32(O[nt][2] * i1), to_tf32(O[nt][3] * i1));
    }
}

// ---------------- LayerNorm (tf32-rounded output) ---------------------------
__global__ __launch_bounds__(256) void ln_kernel(
    const float* __restrict__ x, const float* __restrict__ g,
    const float* __restrict__ b, float* __restrict__ y)
{
    __shared__ float redS[8];
    __shared__ float redQ[8];
    const int row = blockIdx.x;
    const int tid = threadIdx.x;

    const float4 v = ((const float4*)(x + (size_t)row * DMODEL))[tid];
    float s = v.x + v.y + v.z + v.w;
    float q = v.x*v.x + v.y*v.y + v.z*v.z + v.w*v.w;
    #pragma unroll
    for (int off = 16; off >= 1; off >>= 1) {
        s += __shfl_xor_sync(0xffffffffu, s, off);
        q += __shfl_xor_sync(0xffffffffu, q, off);
    }
    if ((tid & 31) == 0) { redS[tid >> 5] = s; redQ[tid >> 5] = q; }
    __syncthreads();
    if (tid < 32) {
        s = (tid < 8) ? redS[tid] : 0.f;
        q = (tid < 8) ? redQ[tid] : 0.f;
        #pragma unroll
        for (int off = 4; off >= 1; off >>= 1) {
            s += __shfl_xor_sync(0xffffffffu, s, off);
            q += __shfl_xor_sync(0xffffffffu, q, off);
        }
        if (tid == 0) { redS[0] = s; redQ[0] = q; }
    }
    __syncthreads();
    const float mu  = redS[0] * (1.f / DMODEL);
    const float var = redQ[0] * (1.f / DMODEL) - mu * mu;
    const float rstd = rsqrtf(var + 1e-5f);

    const float4 gv = ((const float4*)g)[tid];
    const float4 bv = ((const float4*)b)[tid];
    float4 o;
    o.x = to_tf32((v.x - mu) * rstd * gv.x + bv.x);
    o.y = to_tf32((v.y - mu) * rstd * gv.y + bv.y);
    o.z = to_tf32((v.z - mu) * rstd * gv.z + bv.z);
    o.w = to_tf32((v.w - mu) * rstd * gv.w + bv.w);
    ((float4*)(y + (size_t)row * DMODEL))[tid] = o;
}

// ---------------- launch -----------------------------------------------------
extern "C" void kernel_launch(void* const* d_in, const int* in_sizes, int n_in,
                              void* d_out, int out_size)
{
    const float* src    = (const float*)d_in[0];
    const float* wqkv   = (const float*)d_in[1];
    const float* bqkv   = (const float*)d_in[2];
    const float* wo     = (const float*)d_in[3];
    const float* bo     = (const float*)d_in[4];
    const float* g1     = (const float*)d_in[5];
    const float* b1     = (const float*)d_in[6];
    const float* g2     = (const float*)d_in[7];
    const float* b2     = (const float*)d_in[8];
    const float* w_gate = (const float*)d_in[9];
    const float* b_gate = (const float*)d_in[10];
    const float* w_up   = (const float*)d_in[11];
    const float* b_up   = (const float*)d_in[12];
    const float* w_down = (const float*)d_in[13];
    const float* b_down = (const float*)d_in[14];
    float* out = (float*)d_out;

    float *ln, *qkv, *att, *x1, *hbuf, *wbuf;
    cudaGetSymbolAddress((void**)&ln,   g_ln);
    cudaGetSymbolAddress((void**)&qkv,  g_qkv);
    cudaGetSymbolAddress((void**)&att,  g_att);
    cudaGetSymbolAddress((void**)&x1,   g_x1);
    cudaGetSymbolAddress((void**)&hbuf, g_h);
    cudaGetSymbolAddress((void**)&wbuf, g_w);

    cudaFuncSetAttribute(gemm_tc<0, 1>,
        cudaFuncAttributeMaxDynamicSharedMemorySize, GSMEM);
    cudaFuncSetAttribute(gemm_tc<1, 0>,
        cudaFuncAttributeMaxDynamicSharedMemorySize, GSMEM);
    cudaFuncSetAttribute(gemm_glu,
        cudaFuncAttributeMaxDynamicSharedMemorySize, USMEM);
    cudaFuncSetAttribute(attn_mma,
        cudaFuncAttributeMaxDynamicSharedMemorySize, ATT_SMEM);

    // pre-round weights to tf32 (rna)
    round_w<<<3072, 256>>>((const float4*)wqkv,   (float4*)(wbuf + W_QKV), 786432);
    round_w<<<1024, 256>>>((const float4*)wo,     (float4*)(wbuf + W_O),   262144);
    round_w<<<4096, 256>>>((const float4*)w_gate, (float4*)(wbuf + W_G),  1048576);
    round_w<<<4096, 256>>>((const float4*)w_up,   (float4*)(wbuf + W_U),  1048576);
    round_w<<<4096, 256>>>((const float4*)w_down, (float4*)(wbuf + W_D),  1048576);

    // x = src + Attn(LN1(src))
    ln_kernel<<<MTOT, 256>>>(src, g1, b1, ln);
    gemm_tc<0, 1><<<dim3(64, 12), 256, GSMEM>>>(ln, wbuf + W_QKV, bqkv, nullptr,
                                                qkv, 3 * DMODEL, DMODEL);
    attn_mma<<<dim3(8, NHEAD, BATCH), 256, ATT_SMEM>>>(qkv, att);
    gemm_tc<1, 0><<<dim3(64, 4), 256, GSMEM>>>(att, wbuf + W_O, bo, src,
                                               x1, DMODEL, DMODEL);

    // x = x + SwiGLU(LN2(x))
    ln_kernel<<<MTOT, 256>>>(x1, g2, b2, ln);
    gemm_glu<<<dim3(64, 32), 256, USMEM>>>(ln, wbuf + W_G, wbuf + W_U,
                                           b_gate, b_up, hbuf);
    gemm_tc<1, 0><<<dim3(64, 4), 256, GSMEM>>>(hbuf, wbuf + W_D, b_down, x1,
                                               out, DMODEL, DFFN);
}

// round 7
// speedup vs baseline: 3.6120x; 1.0266x over previous
#include <cuda_runtime.h>
#include <math.h>
#include <stdint.h>

#define MTOT   8192
#define DMODEL 1024
#define DFFN   4096
#define NHEAD  16
#define HDIM   64
#define SEQ    1024
#define BATCH  8

// ---------------- scratch (device globals; no allocations) ----------------
__device__ float g_ln[MTOT * DMODEL];
__device__ float g_qkv[MTOT * 3 * DMODEL];
__device__ float g_att[MTOT * DMODEL];
__device__ float g_x1[MTOT * DMODEL];
__device__ float g_h[MTOT * DFFN];          // fused silu(gate)*up
__device__ float g_w[16 * 1024 * 1024];     // tf32-rounded weights (64 MB)

#define W_QKV  0
#define W_O    (3 * 1024 * 1024)
#define W_G    (4 * 1024 * 1024)
#define W_U    (8 * 1024 * 1024)
#define W_D    (12 * 1024 * 1024)

// ---------------- PTX helpers ---------------------------------------------
__device__ __forceinline__ uint32_t smem_u32(const void* p) {
    uint32_t a;
    asm("{ .reg .u64 t; cvta.to.shared.u64 t, %1; cvt.u32.u64 %0, t; }"
        : "=r"(a) : "l"(p));
    return a;
}
__device__ __forceinline__ float to_tf32(float x) {
    uint32_t u;
    asm("cvt.rna.tf32.f32 %0, %1;" : "=r"(u) : "f"(x));
    return __uint_as_float(u);
}
__device__ __forceinline__ void cp16(uint32_t dst, const void* src) {
    asm volatile("cp.async.cg.shared.global [%0], [%1], 16;"
                 :: "r"(dst), "l"(src) : "memory");
}
__device__ __forceinline__ void cp_commit() {
    asm volatile("cp.async.commit_group;" ::: "memory");
}
template <int N>
__device__ __forceinline__ void cp_wait() {
    asm volatile("cp.async.wait_group %0;" :: "n"(N) : "memory");
}
__device__ __forceinline__ void ldsm_x4(uint32_t r[4], uint32_t addr) {
    asm volatile("ldmatrix.sync.aligned.m8n8.x4.shared.b16 {%0,%1,%2,%3}, [%4];"
        : "=r"(r[0]), "=r"(r[1]), "=r"(r[2]), "=r"(r[3]) : "r"(addr));
}
__device__ __forceinline__ void mma_tf32(float c[4], const uint32_t a[4],
                                         const uint32_t b[2]) {
    asm volatile(
        "mma.sync.aligned.m16n8k8.row.col.f32.tf32.tf32.f32 "
        "{%0,%1,%2,%3}, {%4,%5,%6,%7}, {%8,%9}, {%0,%1,%2,%3};\n"
        : "+f"(c[0]), "+f"(c[1]), "+f"(c[2]), "+f"(c[3])
        : "r"(a[0]), "r"(a[1]), "r"(a[2]), "r"(a[3]), "r"(b[0]), "r"(b[1]));
}

// ---------------- weight tf32 pre-round ------------------------------------
__global__ __launch_bounds__(256) void round_w(
    const float4* __restrict__ in, float4* __restrict__ out, int n4)
{
    const int i = blockIdx.x * 256 + threadIdx.x;
    if (i < n4) {
        float4 v = in[i];
        out[i] = make_float4(to_tf32(v.x), to_tf32(v.y),
                             to_tf32(v.z), to_tf32(v.w));
    }
}

// ---------------- TF32 mma.sync NT GEMM ------------------------------------
// C[M, Ntot] = A[M, K] * W[Ntot, K]^T + bias. CTA 128x256, 8 warps (2x4),
// warp tile 64x64. K-chunk 32 per stage, 3-stage cp.async, 128B-row swizzle,
// all-x4 ldmatrix. EPI 0: +bias | 1: +bias+aux. RND: tf32-round output.
#define GSTG_BYTES 49152     // A 16KB + B 32KB
#define GSMEM (3 * GSTG_BYTES)

__device__ __forceinline__ void g_issue(
    uint32_t sbase, int slot, const float* A, const float* W,
    int bm, int bn, int K, int k0, int tid)
{
    const uint32_t sb = sbase + slot * GSTG_BYTES;
    #pragma unroll
    for (int i = 0; i < 12; i++) {
        const int gi = tid + i * 256;
        if (gi < 1024) {
            const int r = gi >> 3, c = gi & 7;
            cp16(sb + r * 128 + ((c ^ (r & 7)) * 16),
                 A + (size_t)(bm + r) * K + k0 + c * 4);
        } else {
            const int j = gi - 1024;
            const int r = j >> 3, c = j & 7;
            cp16(sb + 16384 + r * 128 + ((c ^ (r & 7)) * 16),
                 W + (size_t)(bn + r) * K + k0 + c * 4);
        }
    }
}

template <int EPI, int RND>
__global__ __launch_bounds__(256, 1) void gemm_tc(
    const float* __restrict__ A, const float* __restrict__ W,
    const float* __restrict__ bias, const float* __restrict__ aux,
    float* __restrict__ C, int Ntot, int K)
{
    extern __shared__ float gsm[];
    const uint32_t sbase = smem_u32(gsm);
    const int tid = threadIdx.x, wid = tid >> 5, lane = tid & 31;
    const int g = lane >> 2, th = lane & 3;
    const int bm = blockIdx.x * 128, bn = blockIdx.y * 256;
    const int wm = (wid & 1) * 64, wn = (wid >> 1) * 64;

    float acc[4][8][4];
    #pragma unroll
    for (int mt = 0; mt < 4; mt++)
        #pragma unroll
        for (int nt = 0; nt < 8; nt++)
            #pragma unroll
            for (int c = 0; c < 4; c++) acc[mt][nt][c] = 0.f;

    const int NT = K >> 5;
    #pragma unroll
    for (int t = 0; t < 3; t++) {
        if (t < NT) g_issue(sbase, t, A, W, bm, bn, K, t * 32, tid);
        cp_commit();
    }

    for (int t = 0; t < NT; t++) {
        cp_wait<2>();
        __syncthreads();
        const uint32_t sa = sbase + (t % 3) * GSTG_BYTES;
        const uint32_t sbB = sa + 16384;

        #pragma unroll
        for (int ks = 0; ks < 4; ks++) {
            const int gr = 2 * ks + (lane >> 4);
            uint32_t af[4][4], bf[8][2];
            #pragma unroll
            for (int mt = 0; mt < 4; mt++) {
                const int row = wm + mt * 16 + (lane & 15);
                ldsm_x4(af[mt], sa + row * 128 + ((gr ^ (row & 7)) * 16));
            }
            #pragma unroll
            for (int np = 0; np < 4; np++) {
                const int row = wn + np * 16 + (lane & 15);
                uint32_t q[4];
                ldsm_x4(q, sbB + row * 128 + ((gr ^ (row & 7)) * 16));
                bf[2 * np][0] = q[0]; bf[2 * np + 1][0] = q[1];
                bf[2 * np][1] = q[2]; bf[2 * np + 1][1] = q[3];
            }
            #pragma unroll
            for (int mt = 0; mt < 4; mt++)
                #pragma unroll
                for (int nt = 0; nt < 8; nt++)
                    mma_tf32(acc[mt][nt], af[mt], bf[nt]);
        }
        __syncthreads();
        if (t + 3 < NT) g_issue(sbase, t % 3, A, W, bm, bn, K,
                                (t + 3) * 32, tid);
        cp_commit();
    }

    #pragma unroll
    for (int mt = 0; mt < 4; mt++) {
        const int m0 = bm + wm + mt * 16 + g;
        #pragma unroll
        for (int nt = 0; nt < 8; nt++) {
            const int n = bn + wn + nt * 8 + 2 * th;
            const float b0 = bias[n], b1 = bias[n + 1];
            float v00 = acc[mt][nt][0] + b0, v01 = acc[mt][nt][1] + b1;
            float v10 = acc[mt][nt][2] + b0, v11 = acc[mt][nt][3] + b1;
            if (EPI == 1) {
                const float2 x0 = *(const float2*)&aux[(size_t)m0 * Ntot + n];
                const float2 x1 = *(const float2*)&aux[(size_t)(m0 + 8) * Ntot + n];
                v00 += x0.x; v01 += x0.y; v10 += x1.x; v11 += x1.y;
            }
            if (RND) {
                v00 = to_tf32(v00); v01 = to_tf32(v01);
                v10 = to_tf32(v10); v11 = to_tf32(v11);
            }
            *(float2*)&C[(size_t)m0 * Ntot + n]       = make_float2(v00, v01);
            *(float2*)&C[(size_t)(m0 + 8) * Ntot + n] = make_float2(v10, v11);
        }
    }
}

// ---------------- Fused SwiGLU GEMM ----------------------------------------
// H[M, DFFN] = silu(A Wg^T + bg) * (A Wu^T + bu). CTA 128x128, 8 warps (2x4),
// warp tile 64x32, dual accumulators, K-chunk 32, 3-stage cp.async.
#define USTG_BYTES 49152     // A 16KB + Wg 16KB + Wu 16KB
#define USMEM (3 * USTG_BYTES)

__device__ __forceinline__ void u_issue(
    uint32_t sbase, int slot, const float* A, const float* Wg, const float* Wu,
    int bm, int bn, int k0, int tid)
{
    const uint32_t sb = sbase + slot * USTG_BYTES;
    #pragma unroll
    for (int i = 0; i < 12; i++) {
        const int gi = tid + i * 256;
        const int r = (gi & 1023) >> 3, c = gi & 7;
        const uint32_t dst = r * 128 + ((c ^ (r & 7)) * 16);
        if (gi < 1024)
            cp16(sb + dst, A + (size_t)(bm + r) * DMODEL + k0 + c * 4);
        else if (gi < 2048)
            cp16(sb + 16384 + dst, Wg + (size_t)(bn + r) * DMODEL + k0 + c * 4);
        else
            cp16(sb + 32768 + dst, Wu + (size_t)(bn + r) * DMODEL + k0 + c * 4);
    }
}

__global__ __launch_bounds__(256, 1) void gemm_glu(
    const float* __restrict__ A, const float* __restrict__ Wg,
    const float* __restrict__ Wu, const float* __restrict__ bg,
    const float* __restrict__ bu, float* __restrict__ H)
{
    extern __shared__ float usm[];
    const uint32_t sbase = smem_u32(usm);
    const int tid = threadIdx.x, wid = tid >> 5, lane = tid & 31;
    const int g = lane >> 2, th = lane & 3;
    const int bm = blockIdx.x * 128, bn = blockIdx.y * 128;
    const int wm = (wid & 1) * 64, wn = (wid >> 1) * 32;

    float accG[4][4][4], accU[4][4][4];
    #pragma unroll
    for (int mt = 0; mt < 4; mt++)
        #pragma unroll
        for (int nt = 0; nt < 4; nt++)
            #pragma unroll
            for (int c = 0; c < 4; c++) { accG[mt][nt][c] = 0.f; accU[mt][nt][c] = 0.f; }

    const int NT = DMODEL >> 5;   // 32
    #pragma unroll
    for (int t = 0; t < 3; t++) {
        u_issue(sbase, t, A, Wg, Wu, bm, bn, t * 32, tid);
        cp_commit();
    }

    for (int t = 0; t < NT; t++) {
        cp_wait<2>();
        __syncthreads();
        const uint32_t sa = sbase + (t % 3) * USTG_BYTES;

        #pragma unroll
        for (int ks = 0; ks < 4; ks++) {
            const int gr = 2 * ks + (lane >> 4);
            uint32_t af[4][4], bG[4][2], bU[4][2];
            #pragma unroll
            for (int mt = 0; mt < 4; mt++) {
                const int row = wm + mt * 16 + (lane & 15);
                ldsm_x4(af[mt], sa + row * 128 + ((gr ^ (row & 7)) * 16));
            }
            #pragma unroll
            for (int np = 0; np < 2; np++) {
                const int row = wn + np * 16 + (lane & 15);
                const uint32_t off = row * 128 + ((gr ^ (row & 7)) * 16);
                uint32_t q[4];
                ldsm_x4(q, sa + 16384 + off);
                bG[2 * np][0] = q[0]; bG[2 * np + 1][0] = q[1];
                bG[2 * np][1] = q[2]; bG[2 * np + 1][1] = q[3];
                ldsm_x4(q, sa + 32768 + off);
                bU[2 * np][0] = q[0]; bU[2 * np + 1][0] = q[1];
                bU[2 * np][1] = q[2]; bU[2 * np + 1][1] = q[3];
            }
            #pragma unroll
            for (int mt = 0; mt < 4; mt++)
                #pragma unroll
                for (int nt = 0; nt < 4; nt++) {
                    mma_tf32(accG[mt][nt], af[mt], bG[nt]);
                    mma_tf32(accU[mt][nt], af[mt], bU[nt]);
                }
        }
        __syncthreads();
        if (t + 3 < NT) u_issue(sbase, t % 3, A, Wg, Wu, bm, bn,
                                (t + 3) * 32, tid);
        cp_commit();
    }

    #pragma unroll
    for (int mt = 0; mt < 4; mt++) {
        const int m0 = bm + wm + mt * 16 + g;
        #pragma unroll
        for (int nt = 0; nt < 4; nt++) {
            const int n = bn + wn + nt * 8 + 2 * th;
            const float bg0 = bg[n], bg1 = bg[n + 1];
            const float bu0 = bu[n], bu1 = bu[n + 1];
            #pragma unroll
            for (int r = 0; r < 2; r++) {
                const float ga = accG[mt][nt][2 * r]     + bg0;
                const float gb = accG[mt][nt][2 * r + 1] + bg1;
                const float ua = accU[mt][nt][2 * r]     + bu0;
                const float ub = accU[mt][nt][2 * r + 1] + bu1;
                const float ha = to_tf32(ua * ga / (1.f + __expf(-ga)));
                const float hb = to_tf32(ub * gb / (1.f + __expf(-gb)));
                *(float2*)&H[(size_t)(m0 + 8 * r) * DFFN + n] = make_float2(ha, hb);
            }
        }
    }
}

// ---------------- Flash attention: 128-q tiles, double-buffered K/V --------
#define KVSTG (64 * 68 + 64 * 72)
#define APQ   (2 * KVSTG)
#define ATT_SMEM ((2 * KVSTG + 128 * 68) * 4)

__device__ __forceinline__ void kv_issue(
    uint32_t sb, int slot, const float* kb, const float* vb, int tid)
{
    const int kbase = slot * KVSTG;
    const int vbase = slot * KVSTG + 64 * 68;
    #pragma unroll
    for (int i = 0; i < 4; i++) {
        const int gi = tid + i * 256;
        const int r = gi >> 4, gr = gi & 15;
        cp16(sb + (kbase + r * 68 + gr * 4) * 4, kb + (size_t)r * 3072 + gr * 4);
        cp16(sb + (vbase + r * 72 + gr * 4) * 4, vb + (size_t)r * 3072 + gr * 4);
    }
}

__global__ __launch_bounds__(256) void attn_mma(
    const float* __restrict__ qkv, float* __restrict__ out)
{
    extern __shared__ float sm[];
    const uint32_t sb = smem_u32(sm);
    const int tid = threadIdx.x, wid = tid >> 5, lane = tid & 31;
    const int g = lane >> 2, th = lane & 3;
    const int bq = blockIdx.x, h = blockIdx.y, b = blockIdx.z;
    const float slope = exp2f(-0.5f * (float)(h + 1));

    const float* base = qkv + (size_t)b * SEQ * 3072;

    {
        const float* qb = base + (size_t)(bq * 128) * 3072 + h * 64;
        #pragma unroll
        for (int i = 0; i < 8; i++) {
            const int gi = tid + i * 256;
            const int r = gi >> 4, gr = gi & 15;
            cp16(sb + (APQ + r * 68 + gr * 4) * 4, qb + (size_t)r * 3072 + gr * 4);
        }
        cp_commit();
        cp_wait<0>();
        __syncthreads();
    }

    uint32_t aQ[8][4];
    #pragma unroll
    for (int ks = 0; ks < 8; ks++) {
        const int r0 = APQ + (wid * 16 + g) * 68 + ks * 8 + th;
        aQ[ks][0] = __float_as_uint(sm[r0]);
        aQ[ks][1] = __float_as_uint(sm[r0 + 8 * 68]);
        aQ[ks][2] = __float_as_uint(sm[r0 + 4]);
        aQ[ks][3] = __float_as_uint(sm[r0 + 8 * 68 + 4]);
    }
    __syncthreads();

    const int wp = APQ + wid * (16 * 68);
    float m0 = -1e30f, m1 = -1e30f, l0 = 0.f, l1 = 0.f;
    float O[8][4];
    #pragma unroll
    for (int nt = 0; nt < 8; nt++)
        #pragma unroll
        for (int c = 0; c < 4; c++) O[nt][c] = 0.f;

    const int q0 = bq * 128 + wid * 16 + g;
    const int q1 = q0 + 8;
    const float* kb0 = base + DMODEL + h * 64;
    const float* vb0 = base + 2 * DMODEL + h * 64;

    kv_issue(sb, 0, kb0, vb0, tid);
    cp_commit();

    for (int t = 0; t < 16; t++) {
        if (t + 1 < 16) {
            kv_issue(sb, (t + 1) & 1, kb0 + (size_t)((t + 1) * 64) * 3072,
                     vb0 + (size_t)((t + 1) * 64) * 3072, tid);
        }
        cp_commit();
        cp_wait<1>();
        __syncthreads();

        const int AK = (t & 1) * KVSTG;
        const int AV = AK + 64 * 68;

        float S[8][4];
        #pragma unroll
        for (int nt = 0; nt < 8; nt++) {
            #pragma unroll
            for (int c = 0; c < 4; c++) S[nt][c] = 0.f;
            #pragma unroll
            for (int ks = 0; ks < 8; ks++) {
                uint32_t bf[2];
                const int bi = AK + (nt * 8 + g) * 68 + ks * 8 + th;
                bf[0] = __float_as_uint(sm[bi]);
                bf[1] = __float_as_uint(sm[bi + 4]);
                mma_tf32(S[nt], aQ[ks], bf);
            }
        }

        float mx0 = -1e30f, mx1 = -1e30f;
        #pragma unroll
        for (int nt = 0; nt < 8; nt++) {
            const int kc = t * 64 + nt * 8 + 2 * th;
            S[nt][0] = S[nt][0] * 0.125f - slope * fabsf((float)(q0 - kc));
            S[nt][1] = S[nt][1] * 0.125f - slope * fabsf((float)(q0 - kc - 1));
            S[nt][2] = S[nt][2] * 0.125f - slope * fabsf((float)(q1 - kc));
            S[nt][3] = S[nt][3] * 0.125f - slope * fabsf((float)(q1 - kc - 1));
            mx0 = fmaxf(mx0, fmaxf(S[nt][0], S[nt][1]));
            mx1 = fmaxf(mx1, fmaxf(S[nt][2], S[nt][3]));
        }
        #pragma unroll
        for (int off = 1; off <= 2; off <<= 1) {
            mx0 = fmaxf(mx0, __shfl_xor_sync(0xffffffffu, mx0, off));
            mx1 = fmaxf(mx1, __shfl_xor_sync(0xffffffffu, mx1, off));
        }
        const float mn0 = fmaxf(m0, mx0), mn1 = fmaxf(m1, mx1);
        const float sc0 = __expf(m0 - mn0), sc1 = __expf(m1 - mn1);
        float s0 = 0.f, s1 = 0.f;
        #pragma unroll
        for (int nt = 0; nt < 8; nt++) {
            const float p00 = to_tf32(__expf(S[nt][0] - mn0));
            const float p01 = to_tf32(__expf(S[nt][1] - mn0));
            const float p10 = to_tf32(__expf(S[nt][2] - mn1));
            const float p11 = to_tf32(__expf(S[nt][3] - mn1));
            s0 += p00 + p01; s1 += p10 + p11;
            *(float2*)&sm[wp + g * 68 + nt * 8 + 2 * th] = make_float2(p00, p01);
            *(float2*)&sm[wp + (g + 8) * 68 + nt * 8 + 2 * th] = make_float2(p10, p11);
        }
        #pragma unroll
        for (int off = 1; off <= 2; off <<= 1) {
            s0 += __shfl_xor_sync(0xffffffffu, s0, off);
            s1 += __shfl_xor_sync(0xffffffffu, s1, off);
        }
        l0 = l0 * sc0 + s0; l1 = l1 * sc1 + s1;
        m0 = mn0; m1 = mn1;
        #pragma unroll
        for (int nt = 0; nt < 8; nt++) {
            O[nt][0] *= sc0; O[nt][1] *= sc0;
            O[nt][2] *= sc1; O[nt][3] *= sc1;
        }
        __syncwarp();

        #pragma unroll
        for (int ks = 0; ks < 8; ks++) {
            uint32_t aP[4];
            const int pi = wp + g * 68 + ks * 8 + th;
            aP[0] = __float_as_uint(sm[pi]);
            aP[1] = __float_as_uint(sm[pi + 8 * 68]);
            aP[2] = __float_as_uint(sm[pi + 4]);
            aP[3] = __float_as_uint(sm[pi + 8 * 68 + 4]);
            #pragma unroll
            for (int nt = 0; nt < 8; nt++) {
                uint32_t bf[2];
                bf[0] = __float_as_uint(sm[AV + (ks * 8 + th) * 72 + nt * 8 + g]);
                bf[1] = __float_as_uint(sm[AV + (ks * 8 + th + 4) * 72 + nt * 8 + g]);
                mma_tf32(O[nt], aP, bf);
            }
        }
        __syncthreads();
    }

    const float i0 = 1.f / l0, i1 = 1.f / l1;
    #pragma unroll
    for (int nt = 0; nt < 8; nt++) {
        const int n = h * 64 + nt * 8 + 2 * th;
        *(float2*)&out[(size_t)(b * SEQ + q0) * DMODEL + n] =
            make_float2(to_tf32(O[nt][0] * i0), to_tf32(O[nt][1] * i0));
        *(float2*)&out[(size_t)(b * SEQ + q1) * DMODEL + n] =
            make_float2(to_tf32(O[nt][2] * i1), to_tf32(O[nt][3] * i1));
    }
}

// ---------------- LayerNorm (tf32-rounded output) ---------------------------
__global__ __launch_bounds__(256) void ln_kernel(
    const float* __restrict__ x, const float* __restrict__ g,
    const float* __restrict__ b, float* __restrict__ y)
{
    __shared__ float redS[8];
    __shared__ float redQ[8];
    const int row = blockIdx.x;
    const int tid = threadIdx.x;

    const float4 v = ((const float4*)(x + (size_t)row * DMODEL))[tid];
    float s = v.x + v.y + v.z + v.w;
    float q = v.x*v.x + v.y*v.y + v.z*v.z + v.w*v.w;
    #pragma unroll
    for (int off = 16; off >= 1; off >>= 1) {
        s += __shfl_xor_sync(0xffffffffu, s, off);
        q += __shfl_xor_sync(0xffffffffu, q, off);
    }
    if ((tid & 31) == 0) { redS[tid >> 5] = s; redQ[tid >> 5] = q; }
    __syncthreads();
    if (tid < 32) {
        s = (tid < 8) ? redS[tid] : 0.f;
        q = (tid < 8) ? redQ[tid] : 0.f;
        #pragma unroll
        for (int off = 4; off >= 1; off >>= 1) {
            s += __shfl_xor_sync(0xffffffffu, s, off);
            q += __shfl_xor_sync(0xffffffffu, q, off);
        }
        if (tid == 0) { redS[0] = s; redQ[0] = q; }
    }
    __syncthreads();
    const float mu  = redS[0] * (1.f / DMODEL);
    const float var = redQ[0] * (1.f / DMODEL) - mu * mu;
    const float rstd = rsqrtf(var + 1e-5f);

    const float4 gv = ((const float4*)g)[tid];
    const float4 bv = ((const float4*)b)[tid];
    float4 o;
    o.x = to_tf32((v.x - mu) * rstd * gv.x + bv.x);
    o.y = to_tf32((v.y - mu) * rstd * gv.y + bv.y);
    o.z = to_tf32((v.z - mu) * rstd * gv.z + bv.z);
    o.w = to_tf32((v.w - mu) * rstd * gv.w + bv.w);
    ((float4*)(y + (size_t)row * DMODEL))[tid] = o;
}

// ---------------- launch -----------------------------------------------------
extern "C" void kernel_launch(void* const* d_in, const int* in_sizes, int n_in,
                              void* d_out, int out_size)
{
    const float* src    = (const float*)d_in[0];
    const float* wqkv   = (const float*)d_in[1];
    const float* bqkv   = (const float*)d_in[2];
    const float* wo     = (const float*)d_in[3];
    const float* bo     = (const float*)d_in[4];
    const float* g1     = (const float*)d_in[5];
    const float* b1     = (const float*)d_in[6];
    const float* g2     = (const float*)d_in[7];
    const float* b2     = (const float*)d_in[8];
    const float* w_gate = (const float*)d_in[9];
    const float* b_gate = (const float*)d_in[10];
    const float* w_up   = (const float*)d_in[11];
    const float* b_up   = (const float*)d_in[12];
    const float* w_down = (const float*)d_in[13];
    const float* b_down = (const float*)d_in[14];
    float* out = (float*)d_out;

    float *ln, *qkv, *att, *x1, *hbuf, *wbuf;
    cudaGetSymbolAddress((void**)&ln,   g_ln);
    cudaGetSymbolAddress((void**)&qkv,  g_qkv);
    cudaGetSymbolAddress((void**)&att,  g_att);
    cudaGetSymbolAddress((void**)&x1,   g_x1);
    cudaGetSymbolAddress((void**)&hbuf, g_h);
    cudaGetSymbolAddress((void**)&wbuf, g_w);

    cudaFuncSetAttribute(gemm_tc<0, 1>,
        cudaFuncAttributeMaxDynamicSharedMemorySize, GSMEM);
    cudaFuncSetAttribute(gemm_tc<1, 0>,
        cudaFuncAttributeMaxDynamicSharedMemorySize, GSMEM);
    cudaFuncSetAttribute(gemm_glu,
        cudaFuncAttributeMaxDynamicSharedMemorySize, USMEM);
    cudaFuncSetAttribute(attn_mma,
        cudaFuncAttributeMaxDynamicSharedMemorySize, ATT_SMEM);

    // pre-round weights to tf32 (rna)
    round_w<<<3072, 256>>>((const float4*)wqkv,   (float4*)(wbuf + W_QKV), 786432);
    round_w<<<1024, 256>>>((const float4*)wo,     (float4*)(wbuf + W_O),   262144);
    round_w<<<4096, 256>>>((const float4*)w_gate, (float4*)(wbuf + W_G),  1048576);
    round_w<<<4096, 256>>>((const float4*)w_up,   (float4*)(wbuf + W_U),  1048576);
    round_w<<<4096, 256>>>((const float4*)w_down, (float4*)(wbuf + W_D),  1048576);

    // x = src + Attn(LN1(src))
    ln_kernel<<<MTOT, 256>>>(src, g1, b1, ln);
    gemm_tc<0, 1><<<dim3(64, 12), 256, GSMEM>>>(ln, wbuf + W_QKV, bqkv, nullptr,
                                                qkv, 3 * DMODEL, DMODEL);
    attn_mma<<<dim3(8, NHEAD, BATCH), 256, ATT_SMEM>>>(qkv, att);
    gemm_tc<1, 0><<<dim3(64, 4), 256, GSMEM>>>(att, wbuf + W_O, bo, src,
                                               x1, DMODEL, DMODEL);

    // x = x + SwiGLU(LN2(x))
    ln_kernel<<<MTOT, 256>>>(x1, g2, b2, ln);
    gemm_glu<<<dim3(64, 32), 256, USMEM>>>(ln, wbuf + W_G, wbuf + W_U,
                                           b_gate, b_up, hbuf);
    gemm_tc<1, 0><<<dim3(64, 4), 256, GSMEM>>>(hbuf, wbuf + W_D, b_down, x1,
                                               out, DMODEL, DFFN);
}

// round 10
// speedup vs baseline: 5.8120x; 1.6091x over previous
#include <cuda_runtime.h>
#include <cuda_fp16.h>
#include <math.h>
#include <stdint.h>

#define MTOT   8192
#define DMODEL 1024
#define DFFN   4096
#define NHEAD  16
#define HDIM   64
#define SEQ    1024
#define BATCH  8

// ---------------- scratch (device globals; no allocations) ----------------
__device__ __half g_wh[16 * 1024 * 1024];      // fp16 weights (32 MB)
__device__ __half g_lnh[MTOT * DMODEL];        // fp16 LN output
__device__ float  g_qkv[MTOT * 3 * DMODEL];    // fp32 qkv (attention input)
__device__ __half g_atth[MTOT * DMODEL];       // fp16 attention output
__device__ __half g_hh[MTOT * DFFN];           // fp16 silu(gate)*up
__device__ float  g_x1[MTOT * DMODEL];         // fp32 residual stream

#define W_QKV  0
#define W_O    (3 * 1024 * 1024)
#define W_G    (4 * 1024 * 1024)
#define W_U    (8 * 1024 * 1024)
#define W_D    (12 * 1024 * 1024)

// ---------------- PTX helpers ---------------------------------------------
__device__ __forceinline__ uint32_t smem_u32(const void* p) {
    uint32_t a;
    asm("{ .reg .u64 t; cvta.to.shared.u64 t, %1; cvt.u32.u64 %0, t; }"
        : "=r"(a) : "l"(p));
    return a;
}
__device__ __forceinline__ float to_tf32(float x) {
    uint32_t u;
    asm("cvt.rna.tf32.f32 %0, %1;" : "=r"(u) : "f"(x));
    return __uint_as_float(u);
}
__device__ __forceinline__ void cp16(uint32_t dst, const void* src) {
    asm volatile("cp.async.cg.shared.global [%0], [%1], 16;"
                 :: "r"(dst), "l"(src) : "memory");
}
__device__ __forceinline__ void cp_commit() {
    asm volatile("cp.async.commit_group;" ::: "memory");
}
template <int N>
__device__ __forceinline__ void cp_wait() {
    asm volatile("cp.async.wait_group %0;" :: "n"(N) : "memory");
}
__device__ __forceinline__ void ldsm_x4(uint32_t r[4], uint32_t addr) {
    asm volatile("ldmatrix.sync.aligned.m8n8.x4.shared.b16 {%0,%1,%2,%3}, [%4];"
        : "=r"(r[0]), "=r"(r[1]), "=r"(r[2]), "=r"(r[3]) : "r"(addr));
}
__device__ __forceinline__ void mma_f16(float c[4], const uint32_t a[4],
                                        const uint32_t b[2]) {
    asm volatile(
        "mma.sync.aligned.m16n8k16.row.col.f32.f16.f16.f32 "
        "{%0,%1,%2,%3}, {%4,%5,%6,%7}, {%8,%9}, {%0,%1,%2,%3};\n"
        : "+f"(c[0]), "+f"(c[1]), "+f"(c[2]), "+f"(c[3])
        : "r"(a[0]), "r"(a[1]), "r"(a[2]), "r"(a[3]), "r"(b[0]), "r"(b[1]));
}
__device__ __forceinline__ void mma_tf32(float c[4], const uint32_t a[4],
                                         const uint32_t b[2]) {
    asm volatile(
        "mma.sync.aligned.m16n8k8.row.col.f32.tf32.tf32.f32 "
        "{%0,%1,%2,%3}, {%4,%5,%6,%7}, {%8,%9}, {%0,%1,%2,%3};\n"
        : "+f"(c[0]), "+f"(c[1]), "+f"(c[2]), "+f"(c[3])
        : "r"(a[0]), "r"(a[1]), "r"(a[2]), "r"(a[3]), "r"(b[0]), "r"(b[1]));
}
__device__ __forceinline__ uint32_t pack_h2(float a, float b) {
    __half2 h = __floats2half2_rn(a, b);
    return *reinterpret_cast<uint32_t*>(&h);
}

// ---------------- weight fp32 -> fp16 --------------------------------------
__global__ __launch_bounds__(256) void cvt_w(
    const float4* __restrict__ in, __half2* __restrict__ out, int n4)
{
    const int i = blockIdx.x * 256 + threadIdx.x;
    if (i < n4) {
        float4 v = in[i];
        out[2 * i]     = __floats2half2_rn(v.x, v.y);
        out[2 * i + 1] = __floats2half2_rn(v.z, v.w);
    }
}

// ---------------- FP16 mma.sync NT GEMM ------------------------------------
// C[M, Ntot] = A[M, K] * W[Ntot, K]^T + bias. CTA 128x256, 8 warps (2x4),
// warp tile 64x64. K-chunk 64 per stage (row = 64 fp16 = 128B, swizzle
// chunk ^ (row&7)), 3-stage cp.async, all-x4 ldmatrix.
// EPI 0: +bias | 1: +bias+aux(fp32). OUT16: write fp16 else fp32.
#define GSTG_BYTES 49152     // A 16KB + B 32KB
#define GSMEM (3 * GSTG_BYTES)

__device__ __forceinline__ void g_issue(
    uint32_t sbase, int slot, const __half* A, const __half* W,
    int bm, int bn, int K, int k0, int tid)
{
    const uint32_t sb = sbase + slot * GSTG_BYTES;
    #pragma unroll
    for (int i = 0; i < 12; i++) {
        const int gi = tid + i * 256;
        if (gi < 1024) {
            const int r = gi >> 3, c = gi & 7;
            cp16(sb + r * 128 + ((c ^ (r & 7)) * 16),
                 A + (size_t)(bm + r) * K + k0 + c * 8);
        } else {
            const int j = gi - 1024;
            const int r = j >> 3, c = j & 7;
            cp16(sb + 16384 + r * 128 + ((c ^ (r & 7)) * 16),
                 W + (size_t)(bn + r) * K + k0 + c * 8);
        }
    }
}

template <int EPI, int OUT16>
__global__ __launch_bounds__(256, 1) void gemm_h(
    const __half* __restrict__ A, const __half* __restrict__ W,
    const float* __restrict__ bias, const float* __restrict__ aux,
    void* __restrict__ Cv, int Ntot, int K)
{
    extern __shared__ float gsm[];
    const uint32_t sbase = smem_u32(gsm);
    const int tid = threadIdx.x, wid = tid >> 5, lane = tid & 31;
    const int g = lane >> 2, th = lane & 3;
    const int bm = blockIdx.x * 128, bn = blockIdx.y * 256;
    const int wm = (wid & 1) * 64, wn = (wid >> 1) * 64;

    float acc[4][8][4];
    #pragma unroll
    for (int mt = 0; mt < 4; mt++)
        #pragma unroll
        for (int nt = 0; nt < 8; nt++)
            #pragma unroll
            for (int c = 0; c < 4; c++) acc[mt][nt][c] = 0.f;

    const int NT = K >> 6;
    #pragma unroll
    for (int t = 0; t < 3; t++) {
        if (t < NT) g_issue(sbase, t, A, W, bm, bn, K, t * 64, tid);
        cp_commit();
    }

    for (int t = 0; t < NT; t++) {
        cp_wait<2>();
        __syncthreads();
        const uint32_t sa = sbase + (t % 3) * GSTG_BYTES;
        const uint32_t sbB = sa + 16384;

        #pragma unroll
        for (int ks = 0; ks < 4; ks++) {
            const int gr = 2 * ks + (lane >> 4);
            uint32_t af[4][4], bf[8][2];
            #pragma unroll
            for (int mt = 0; mt < 4; mt++) {
                const int row = wm + mt * 16 + (lane & 15);
                ldsm_x4(af[mt], sa + row * 128 + ((gr ^ (row & 7)) * 16));
            }
            #pragma unroll
            for (int np = 0; np < 4; np++) {
                const int row = wn + np * 16 + (lane & 15);
                uint32_t q[4];
                ldsm_x4(q, sbB + row * 128 + ((gr ^ (row & 7)) * 16));
                bf[2 * np][0] = q[0]; bf[2 * np + 1][0] = q[1];
                bf[2 * np][1] = q[2]; bf[2 * np + 1][1] = q[3];
            }
            #pragma unroll
            for (int mt = 0; mt < 4; mt++)
                #pragma unroll
                for (int nt = 0; nt < 8; nt++)
                    mma_f16(acc[mt][nt], af[mt], bf[nt]);
        }
        __syncthreads();
        if (t + 3 < NT) g_issue(sbase, t % 3, A, W, bm, bn, K,
                                (t + 3) * 64, tid);
        cp_commit();
    }

    #pragma unroll
    for (int mt = 0; mt < 4; mt++) {
        const int m0 = bm + wm + mt * 16 + g;
        #pragma unroll
        for (int nt = 0; nt < 8; nt++) {
            const int n = bn + wn + nt * 8 + 2 * th;
            const float b0 = bias[n], b1 = bias[n + 1];
            float v00 = acc[mt][nt][0] + b0, v01 = acc[mt][nt][1] + b1;
            float v10 = acc[mt][nt][2] + b0, v11 = acc[mt][nt][3] + b1;
            if (EPI == 1) {
                const float2 x0 = *(const float2*)&aux[(size_t)m0 * Ntot + n];
                const float2 x1 = *(const float2*)&aux[(size_t)(m0 + 8) * Ntot + n];
                v00 += x0.x; v01 += x0.y; v10 += x1.x; v11 += x1.y;
            }
            if (OUT16) {
                __half* C = (__half*)Cv;
                *(uint32_t*)&C[(size_t)m0 * Ntot + n]       = pack_h2(v00, v01);
                *(uint32_t*)&C[(size_t)(m0 + 8) * Ntot + n] = pack_h2(v10, v11);
            } else {
                float* C = (float*)Cv;
                *(float2*)&C[(size_t)m0 * Ntot + n]       = make_float2(v00, v01);
                *(float2*)&C[(size_t)(m0 + 8) * Ntot + n] = make_float2(v10, v11);
            }
        }
    }
}

// ---------------- Fused SwiGLU GEMM (fp16) ----------------------------------
#define USTG_BYTES 49152     // A 16KB + Wg 16KB + Wu 16KB
#define USMEM (3 * USTG_BYTES)

__device__ __forceinline__ void u_issue(
    uint32_t sbase, int slot, const __half* A, const __half* Wg,
    const __half* Wu, int bm, int bn, int k0, int tid)
{
    const uint32_t sb = sbase + slot * USTG_BYTES;
    #pragma unroll
    for (int i = 0; i < 12; i++) {
        const int gi = tid + i * 256;
        const int r = (gi & 1023) >> 3, c = gi & 7;
        const uint32_t dst = r * 128 + ((c ^ (r & 7)) * 16);
        if (gi < 1024)
            cp16(sb + dst, A + (size_t)(bm + r) * DMODEL + k0 + c * 8);
        else if (gi < 2048)
            cp16(sb + 16384 + dst, Wg + (size_t)(bn + r) * DMODEL + k0 + c * 8);
        else
            cp16(sb + 32768 + dst, Wu + (size_t)(bn + r) * DMODEL + k0 + c * 8);
    }
}

__global__ __launch_bounds__(256, 1) void gemm_glu(
    const __half* __restrict__ A, const __half* __restrict__ Wg,
    const __half* __restrict__ Wu, const float* __restrict__ bg,
    const float* __restrict__ bu, __half* __restrict__ H)
{
    extern __shared__ float usm[];
    const uint32_t sbase = smem_u32(usm);
    const int tid = threadIdx.x, wid = tid >> 5, lane = tid & 31;
    const int g = lane >> 2, th = lane & 3;
    const int bm = blockIdx.x * 128, bn = blockIdx.y * 128;
    const int wm = (wid & 1) * 64, wn = (wid >> 1) * 32;

    float accG[4][4][4], accU[4][4][4];
    #pragma unroll
    for (int mt = 0; mt < 4; mt++)
        #pragma unroll
        for (int nt = 0; nt < 4; nt++)
            #pragma unroll
            for (int c = 0; c < 4; c++) { accG[mt][nt][c] = 0.f; accU[mt][nt][c] = 0.f; }

    const int NT = DMODEL >> 6;   // 16
    #pragma unroll
    for (int t = 0; t < 3; t++) {
        u_issue(sbase, t, A, Wg, Wu, bm, bn, t * 64, tid);
        cp_commit();
    }

    for (int t = 0; t < NT; t++) {
        cp_wait<2>();
        __syncthreads();
        const uint32_t sa = sbase + (t % 3) * USTG_BYTES;

        #pragma unroll
        for (int ks = 0; ks < 4; ks++) {
            const int gr = 2 * ks + (lane >> 4);
            uint32_t af[4][4], bG[4][2], bU[4][2];
            #pragma unroll
            for (int mt = 0; mt < 4; mt++) {
                const int row = wm + mt * 16 + (lane & 15);
                ldsm_x4(af[mt], sa + row * 128 + ((gr ^ (row & 7)) * 16));
            }
            #pragma unroll
            for (int np = 0; np < 2; np++) {
                const int row = wn + np * 16 + (lane & 15);
                const uint32_t off = row * 128 + ((gr ^ (row & 7)) * 16);
                uint32_t q[4];
                ldsm_x4(q, sa + 16384 + off);
                bG[2 * np][0] = q[0]; bG[2 * np + 1][0] = q[1];
                bG[2 * np][1] = q[2]; bG[2 * np + 1][1] = q[3];
                ldsm_x4(q, sa + 32768 + off);
                bU[2 * np][0] = q[0]; bU[2 * np + 1][0] = q[1];
                bU[2 * np][1] = q[2]; bU[2 * np + 1][1] = q[3];
            }
            #pragma unroll
            for (int mt = 0; mt < 4; mt++)
                #pragma unroll
                for (int nt = 0; nt < 4; nt++) {
                    mma_f16(accG[mt][nt], af[mt], bG[nt]);
                    mma_f16(accU[mt][nt], af[mt], bU[nt]);
                }
        }
        __syncthreads();
        if (t + 3 < NT) u_issue(sbase, t % 3, A, Wg, Wu, bm, bn,
                                (t + 3) * 64, tid);
        cp_commit();
    }

    #pragma unroll
    for (int mt = 0; mt < 4; mt++) {
        const int m0 = bm + wm + mt * 16 + g;
        #pragma unroll
        for (int nt = 0; nt < 4; nt++) {
            const int n = bn + wn + nt * 8 + 2 * th;
            const float bg0 = bg[n], bg1 = bg[n + 1];
            const float bu0 = bu[n], bu1 = bu[n + 1];
            #pragma unroll
            for (int r = 0; r < 2; r++) {
                const float ga = accG[mt][nt][2 * r]     + bg0;
                const float gb = accG[mt][nt][2 * r + 1] + bg1;
                const float ua = accU[mt][nt][2 * r]     + bu0;
                const float ub = accU[mt][nt][2 * r + 1] + bu1;
                const float ha = ua * ga / (1.f + __expf(-ga));
                const float hb = ub * gb / (1.f + __expf(-gb));
                *(uint32_t*)&H[(size_t)(m0 + 8 * r) * DFFN + n] = pack_h2(ha, hb);
            }
        }
    }
}

// ---------------- Flash attention (round-7 proven tf32 kernel) --------------
// 256 threads (8 warps), q-tile 128, kv tiles 64, double-buffered fp32 smem.
// Input: fp32 qkv.  Output: fp16 (feeds o-proj GEMM).
#define KVSTG (64 * 68 + 64 * 72)
#define APQ   (2 * KVSTG)
#define ATT_SMEM ((2 * KVSTG + 128 * 68) * 4)

__device__ __forceinline__ void kv_issue(
    uint32_t sb, int slot, const float* kb, const float* vb, int tid)
{
    const int kbase = slot * KVSTG;
    const int vbase = slot * KVSTG + 64 * 68;
    #pragma unroll
    for (int i = 0; i < 4; i++) {
        const int gi = tid + i * 256;
        const int r = gi >> 4, gr = gi & 15;
        cp16(sb + (kbase + r * 68 + gr * 4) * 4, kb + (size_t)r * 3072 + gr * 4);
        cp16(sb + (vbase + r * 72 + gr * 4) * 4, vb + (size_t)r * 3072 + gr * 4);
    }
}

__global__ __launch_bounds__(256) void attn_mma(
    const float* __restrict__ qkv, __half* __restrict__ out)
{
    extern __shared__ float sm[];
    const uint32_t sb = smem_u32(sm);
    const int tid = threadIdx.x, wid = tid >> 5, lane = tid & 31;
    const int g = lane >> 2, th = lane & 3;
    const int bq = blockIdx.x, h = blockIdx.y, b = blockIdx.z;
    const float slope = exp2f(-0.5f * (float)(h + 1));

    const float* base = qkv + (size_t)b * SEQ * 3072;

    {
        const float* qb = base + (size_t)(bq * 128) * 3072 + h * 64;
        #pragma unroll
        for (int i = 0; i < 8; i++) {
            const int gi = tid + i * 256;
            const int r = gi >> 4, gr = gi & 15;
            cp16(sb + (APQ + r * 68 + gr * 4) * 4, qb + (size_t)r * 3072 + gr * 4);
        }
        cp_commit();
        cp_wait<0>();
        __syncthreads();
    }

    uint32_t aQ[8][4];
    #pragma unroll
    for (int ks = 0; ks < 8; ks++) {
        const int r0 = APQ + (wid * 16 + g) * 68 + ks * 8 + th;
        aQ[ks][0] = __float_as_uint(sm[r0]);
        aQ[ks][1] = __float_as_uint(sm[r0 + 8 * 68]);
        aQ[ks][2] = __float_as_uint(sm[r0 + 4]);
        aQ[ks][3] = __float_as_uint(sm[r0 + 8 * 68 + 4]);
    }
    __syncthreads();

    const int wp = APQ + wid * (16 * 68);
    float m0 = -1e30f, m1 = -1e30f, l0 = 0.f, l1 = 0.f;
    float O[8][4];
    #pragma unroll
    for (int nt = 0; nt < 8; nt++)
        #pragma unroll
        for (int c = 0; c < 4; c++) O[nt][c] = 0.f;

    const int q0 = bq * 128 + wid * 16 + g;
    const int q1 = q0 + 8;
    const float* kb0 = base + DMODEL + h * 64;
    const float* vb0 = base + 2 * DMODEL + h * 64;

    kv_issue(sb, 0, kb0, vb0, tid);
    cp_commit();

    for (int t = 0; t < 16; t++) {
        if (t + 1 < 16) {
            kv_issue(sb, (t + 1) & 1, kb0 + (size_t)((t + 1) * 64) * 3072,
                     vb0 + (size_t)((t + 1) * 64) * 3072, tid);
        }
        cp_commit();
        cp_wait<1>();
        __syncthreads();

        const int AK = (t & 1) * KVSTG;
        const int AV = AK + 64 * 68;

        float S[8][4];
        #pragma unroll
        for (int nt = 0; nt < 8; nt++) {
            #pragma unroll
            for (int c = 0; c < 4; c++) S[nt][c] = 0.f;
            #pragma unroll
            for (int ks = 0; ks < 8; ks++) {
                uint32_t bf[2];
                const int bi = AK + (nt * 8 + g) * 68 + ks * 8 + th;
                bf[0] = __float_as_uint(sm[bi]);
                bf[1] = __float_as_uint(sm[bi + 4]);
                mma_tf32(S[nt], aQ[ks], bf);
            }
        }

        float mx0 = -1e30f, mx1 = -1e30f;
        #pragma unroll
        for (int nt = 0; nt < 8; nt++) {
            const int kc = t * 64 + nt * 8 + 2 * th;
            S[nt][0] = S[nt][0] * 0.125f - slope * fabsf((float)(q0 - kc));
            S[nt][1] = S[nt][1] * 0.125f - slope * fabsf((float)(q0 - kc - 1));
            S[nt][2] = S[nt][2] * 0.125f - slope * fabsf((float)(q1 - kc));
            S[nt][3] = S[nt][3] * 0.125f - slope * fabsf((float)(q1 - kc - 1));
            mx0 = fmaxf(mx0, fmaxf(S[nt][0], S[nt][1]));
            mx1 = fmaxf(mx1, fmaxf(S[nt][2], S[nt][3]));
        }
        #pragma unroll
        for (int off = 1; off <= 2; off <<= 1) {
            mx0 = fmaxf(mx0, __shfl_xor_sync(0xffffffffu, mx0, off));
            mx1 = fmaxf(mx1, __shfl_xor_sync(0xffffffffu, mx1, off));
        }
        const float mn0 = fmaxf(m0, mx0), mn1 = fmaxf(m1, mx1);
        const float sc0 = __expf(m0 - mn0), sc1 = __expf(m1 - mn1);
        float s0 = 0.f, s1 = 0.f;
        #pragma unroll
        for (int nt = 0; nt < 8; nt++) {
            const float p00 = to_tf32(__expf(S[nt][0] - mn0));
            const float p01 = to_tf32(__expf(S[nt][1] - mn0));
            const float p10 = to_tf32(__expf(S[nt][2] - mn1));
            const float p11 = to_tf32(__expf(S[nt][3] - mn1));
            s0 += p00 + p01; s1 += p10 + p11;
            *(float2*)&sm[wp + g * 68 + nt * 8 + 2 * th] = make_float2(p00, p01);
            *(float2*)&sm[wp + (g + 8) * 68 + nt * 8 + 2 * th] = make_float2(p10, p11);
        }
        #pragma unroll
        for (int off = 1; off <= 2; off <<= 1) {
            s0 += __shfl_xor_sync(0xffffffffu, s0, off);
            s1 += __shfl_xor_sync(0xffffffffu, s1, off);
        }
        l0 = l0 * sc0 + s0; l1 = l1 * sc1 + s1;
        m0 = mn0; m1 = mn1;
        #pragma unroll
        for (int nt = 0; nt < 8; nt++) {
            O[nt][0] *= sc0; O[nt][1] *= sc0;
            O[nt][2] *= sc1; O[nt][3] *= sc1;
        }
        __syncwarp();

        #pragma unroll
        for (int ks = 0; ks < 8; ks++) {
            uint32_t aP[4];
            const int pi = wp + g * 68 + ks * 8 + th;
            aP[0] = __float_as_uint(sm[pi]);
            aP[1] = __float_as_uint(sm[pi + 8 * 68]);
            aP[2] = __float_as_uint(sm[pi + 4]);
            aP[3] = __float_as_uint(sm[pi + 8 * 68 + 4]);
            #pragma unroll
            for (int nt = 0; nt < 8; nt++) {
                uint32_t bf[2];
                bf[0] = __float_as_uint(sm[AV + (ks * 8 + th) * 72 + nt * 8 + g]);
                bf[1] = __float_as_uint(sm[AV + (ks * 8 + th + 4) * 72 + nt * 8 + g]);
                mma_tf32(O[nt], aP, bf);
            }
        }
        __syncthreads();
    }

    const float i0 = 1.f / l0, i1 = 1.f / l1;
    #pragma unroll
    for (int nt = 0; nt < 8; nt++) {
        const int n = h * 64 + nt * 8 + 2 * th;
        *(uint32_t*)&out[(size_t)(b * SEQ + q0) * DMODEL + n] =
            pack_h2(O[nt][0] * i0, O[nt][1] * i0);
        *(uint32_t*)&out[(size_t)(b * SEQ + q1) * DMODEL + n] =
            pack_h2(O[nt][2] * i1, O[nt][3] * i1);
    }
}

// ---------------- LayerNorm (fp16 output) -----------------------------------
__global__ __launch_bounds__(256) void ln_kernel(
    const float* __restrict__ x, const float* __restrict__ g,
    const float* __restrict__ b, __half* __restrict__ y)
{
    __shared__ float redS[8];
    __shared__ float redQ[8];
    const int row = blockIdx.x;
    const int tid = threadIdx.x;

    const float4 v = ((const float4*)(x + (size_t)row * DMODEL))[tid];
    float s = v.x + v.y + v.z + v.w;
    float q = v.x*v.x + v.y*v.y + v.z*v.z + v.w*v.w;
    #pragma unroll
    for (int off = 16; off >= 1; off >>= 1) {
        s += __shfl_xor_sync(0xffffffffu, s, off);
        q += __shfl_xor_sync(0xffffffffu, q, off);
    }
    if ((tid & 31) == 0) { redS[tid >> 5] = s; redQ[tid >> 5] = q; }
    __syncthreads();
    if (tid < 32) {
        s = (tid < 8) ? redS[tid] : 0.f;
        q = (tid < 8) ? redQ[tid] : 0.f;
        #pragma unroll
        for (int off = 4; off >= 1; off >>= 1) {
            s += __shfl_xor_sync(0xffffffffu, s, off);
            q += __shfl_xor_sync(0xffffffffu, q, off);
        }
        if (tid == 0) { redS[0] = s; redQ[0] = q; }
    }
    __syncthreads();
    const float mu  = redS[0] * (1.f / DMODEL);
    const float var = redQ[0] * (1.f / DMODEL) - mu * mu;
    const float rstd = rsqrtf(var + 1e-5f);

    const float4 gv = ((const float4*)g)[tid];
    const float4 bv = ((const float4*)b)[tid];
    uint32_t o0 = pack_h2((v.x - mu) * rstd * gv.x + bv.x,
                          (v.y - mu) * rstd * gv.y + bv.y);
    uint32_t o1 = pack_h2((v.z - mu) * rstd * gv.z + bv.z,
                          (v.w - mu) * rstd * gv.w + bv.w);
    uint2* yo = (uint2*)(y + (size_t)row * DMODEL);
    yo[tid] = make_uint2(o0, o1);
}

// ---------------- launch -----------------------------------------------------
extern "C" void kernel_launch(void* const* d_in, const int* in_sizes, int n_in,
                              void* d_out, int out_size)
{
    const float* src    = (const float*)d_in[0];
    const float* wqkv   = (const float*)d_in[1];
    const float* bqkv   = (const float*)d_in[2];
    const float* wo     = (const float*)d_in[3];
    const float* bo     = (const float*)d_in[4];
    const float* g1     = (const float*)d_in[5];
    const float* b1     = (const float*)d_in[6];
    const float* g2     = (const float*)d_in[7];
    const float* b2     = (const float*)d_in[8];
    const float* w_gate = (const float*)d_in[9];
    const float* b_gate = (const float*)d_in[10];
    const float* w_up   = (const float*)d_in[11];
    const float* b_up   = (const float*)d_in[12];
    const float* w_down = (const float*)d_in[13];
    const float* b_down = (const float*)d_in[14];
    float* out = (float*)d_out;

    __half *lnh, *atth, *hh, *wh;
    float  *qkv, *x1;
    cudaGetSymbolAddress((void**)&lnh,  g_lnh);
    cudaGetSymbolAddress((void**)&qkv,  g_qkv);
    cudaGetSymbolAddress((void**)&atth, g_atth);
    cudaGetSymbolAddress((void**)&hh,   g_hh);
    cudaGetSymbolAddress((void**)&wh,   g_wh);
    cudaGetSymbolAddress((void**)&x1,   g_x1);

    cudaFuncSetAttribute(gemm_h<0, 0>,
        cudaFuncAttributeMaxDynamicSharedMemorySize, GSMEM);
    cudaFuncSetAttribute(gemm_h<1, 0>,
        cudaFuncAttributeMaxDynamicSharedMemorySize, GSMEM);
    cudaFuncSetAttribute(gemm_glu,
        cudaFuncAttributeMaxDynamicSharedMemorySize, USMEM);
    cudaFuncSetAttribute(attn_mma,
        cudaFuncAttributeMaxDynamicSharedMemorySize, ATT_SMEM);

    // weights fp32 -> fp16
    cvt_w<<<3072, 256>>>((const float4*)wqkv,   (__half2*)(wh + W_QKV), 786432);
    cvt_w<<<1024, 256>>>((const float4*)wo,     (__half2*)(wh + W_O),   262144);
    cvt_w<<<4096, 256>>>((const float4*)w_gate, (__half2*)(wh + W_G),  1048576);
    cvt_w<<<4096, 256>>>((const float4*)w_up,   (__half2*)(wh + W_U),  1048576);
    cvt_w<<<4096, 256>>>((const float4*)w_down, (__half2*)(wh + W_D),  1048576);

    // x = src + Attn(LN1(src))
    ln_kernel<<<MTOT, 256>>>(src, g1, b1, lnh);
    gemm_h<0, 0><<<dim3(64, 12), 256, GSMEM>>>(lnh, wh + W_QKV, bqkv, nullptr,
                                               qkv, 3 * DMODEL, DMODEL);
    attn_mma<<<dim3(8, NHEAD, BATCH), 256, ATT_SMEM>>>(qkv, atth);
    gemm_h<1, 0><<<dim3(64, 4), 256, GSMEM>>>(atth, wh + W_O, bo, src,
                                              x1, DMODEL, DMODEL);

    // x = x + SwiGLU(LN2(x))
    ln_kernel<<<MTOT, 256>>>(x1, g2, b2, lnh);
    gemm_glu<<<dim3(64, 32), 256, USMEM>>>(lnh, wh + W_G, wh + W_U,
                                           b_gate, b_up, hh);
    gemm_h<1, 0><<<dim3(64, 4), 256, GSMEM>>>(hh, wh + W_D, b_down, x1,
                                              out, DMODEL, DFFN);
}

// round 11
// speedup vs baseline: 5.8273x; 1.0026x over previous
#include <cuda_runtime.h>
#include <cuda_fp16.h>
#include <math.h>
#include <stdint.h>

#define MTOT   8192
#define DMODEL 1024
#define DFFN   4096
#define NHEAD  16
#define HDIM   64
#define SEQ    1024
#define BATCH  8

// ---------------- scratch (device globals; no allocations) ----------------
__device__ __half g_wh[16 * 1024 * 1024];      // fp16 weights (32 MB)
__device__ __half g_lnh[MTOT * DMODEL];        // fp16 LN output
__device__ float  g_qkv[MTOT * 3 * DMODEL];    // fp32 qkv (attention input)
__device__ __half g_atth[MTOT * DMODEL];       // fp16 attention output
__device__ __half g_hh[MTOT * DFFN];           // fp16 silu(gate)*up
__device__ float  g_x1[MTOT * DMODEL];         // fp32 residual stream

#define W_QKV  0
#define W_O    (3 * 1024 * 1024)
#define W_G    (4 * 1024 * 1024)
#define W_U    (8 * 1024 * 1024)
#define W_D    (12 * 1024 * 1024)

// ---------------- PTX helpers ---------------------------------------------
__device__ __forceinline__ uint32_t smem_u32(const void* p) {
    uint32_t a;
    asm("{ .reg .u64 t; cvta.to.shared.u64 t, %1; cvt.u32.u64 %0, t; }"
        : "=r"(a) : "l"(p));
    return a;
}
__device__ __forceinline__ float to_tf32(float x) {
    uint32_t u;
    asm("cvt.rna.tf32.f32 %0, %1;" : "=r"(u) : "f"(x));
    return __uint_as_float(u);
}
__device__ __forceinline__ void cp16(uint32_t dst, const void* src) {
    asm volatile("cp.async.cg.shared.global [%0], [%1], 16;"
                 :: "r"(dst), "l"(src) : "memory");
}
__device__ __forceinline__ void cp_commit() {
    asm volatile("cp.async.commit_group;" ::: "memory");
}
template <int N>
__device__ __forceinline__ void cp_wait() {
    asm volatile("cp.async.wait_group %0;" :: "n"(N) : "memory");
}
__device__ __forceinline__ void ldsm_x4(uint32_t r[4], uint32_t addr) {
    asm volatile("ldmatrix.sync.aligned.m8n8.x4.shared.b16 {%0,%1,%2,%3}, [%4];"
        : "=r"(r[0]), "=r"(r[1]), "=r"(r[2]), "=r"(r[3]) : "r"(addr));
}
__device__ __forceinline__ void mma_f16(float c[4], const uint32_t a[4],
                                        const uint32_t b[2]) {
    asm volatile(
        "mma.sync.aligned.m16n8k16.row.col.f32.f16.f16.f32 "
        "{%0,%1,%2,%3}, {%4,%5,%6,%7}, {%8,%9}, {%0,%1,%2,%3};\n"
        : "+f"(c[0]), "+f"(c[1]), "+f"(c[2]), "+f"(c[3])
        : "r"(a[0]), "r"(a[1]), "r"(a[2]), "r"(a[3]), "r"(b[0]), "r"(b[1]));
}
__device__ __forceinline__ void mma_tf32(float c[4], const uint32_t a[4],
                                         const uint32_t b[2]) {
    asm volatile(
        "mma.sync.aligned.m16n8k8.row.col.f32.tf32.tf32.f32 "
        "{%0,%1,%2,%3}, {%4,%5,%6,%7}, {%8,%9}, {%0,%1,%2,%3};\n"
        : "+f"(c[0]), "+f"(c[1]), "+f"(c[2]), "+f"(c[3])
        : "r"(a[0]), "r"(a[1]), "r"(a[2]), "r"(a[3]), "r"(b[0]), "r"(b[1]));
}
__device__ __forceinline__ uint32_t pack_h2(float a, float b) {
    __half2 h = __floats2half2_rn(a, b);
    return *reinterpret_cast<uint32_t*>(&h);
}

// ---------------- weight fp32 -> fp16 --------------------------------------
__global__ __launch_bounds__(256) void cvt_w(
    const float4* __restrict__ in, __half2* __restrict__ out, int n4)
{
    const int i = blockIdx.x * 256 + threadIdx.x;
    if (i < n4) {
        float4 v = in[i];
        out[2 * i]     = __floats2half2_rn(v.x, v.y);
        out[2 * i + 1] = __floats2half2_rn(v.z, v.w);
    }
}

// ---------------- FP16 mma.sync NT GEMM ------------------------------------
// C[M, Ntot] = A[M, K] * W[Ntot, K]^T + bias. CTA 128x256, 512 threads
// (16 warps, 2x8), warp tile 64x32. K-chunk 64 per stage (row = 128B,
// swizzle chunk ^ (row&7)), 3-stage cp.async, all-x4 ldmatrix.
// EPI 0: +bias | 1: +bias+aux(fp32). OUT16: write fp16 else fp32.
#define GSTG_BYTES 49152     // A 16KB + B 32KB
#define GSMEM (3 * GSTG_BYTES)

__device__ __forceinline__ void g_issue(
    uint32_t sbase, int slot, const __half* A, const __half* W,
    int bm, int bn, int K, int k0, int tid)
{
    const uint32_t sb = sbase + slot * GSTG_BYTES;
    #pragma unroll
    for (int i = 0; i < 6; i++) {
        const int gi = tid + i * 512;
        if (gi < 1024) {
            const int r = gi >> 3, c = gi & 7;
            cp16(sb + r * 128 + ((c ^ (r & 7)) * 16),
                 A + (size_t)(bm + r) * K + k0 + c * 8);
        } else {
            const int j = gi - 1024;
            const int r = j >> 3, c = j & 7;
            cp16(sb + 16384 + r * 128 + ((c ^ (r & 7)) * 16),
                 W + (size_t)(bn + r) * K + k0 + c * 8);
        }
    }
}

template <int EPI, int OUT16>
__global__ __launch_bounds__(512, 1) void gemm_h(
    const __half* __restrict__ A, const __half* __restrict__ W,
    const float* __restrict__ bias, const float* __restrict__ aux,
    void* __restrict__ Cv, int Ntot, int K)
{
    extern __shared__ float gsm[];
    const uint32_t sbase = smem_u32(gsm);
    const int tid = threadIdx.x, wid = tid >> 5, lane = tid & 31;
    const int g = lane >> 2, th = lane & 3;
    const int bm = blockIdx.x * 128, bn = blockIdx.y * 256;
    const int wm = (wid & 1) * 64, wn = (wid >> 1) * 32;

    float acc[4][4][4];
    #pragma unroll
    for (int mt = 0; mt < 4; mt++)
        #pragma unroll
        for (int nt = 0; nt < 4; nt++)
            #pragma unroll
            for (int c = 0; c < 4; c++) acc[mt][nt][c] = 0.f;

    const int NT = K >> 6;
    #pragma unroll
    for (int t = 0; t < 3; t++) {
        if (t < NT) g_issue(sbase, t, A, W, bm, bn, K, t * 64, tid);
        cp_commit();
    }

    for (int t = 0; t < NT; t++) {
        cp_wait<2>();
        __syncthreads();
        const uint32_t sa = sbase + (t % 3) * GSTG_BYTES;
        const uint32_t sbB = sa + 16384;

        #pragma unroll
        for (int ks = 0; ks < 4; ks++) {
            const int gr = 2 * ks + (lane >> 4);
            uint32_t af[4][4], bf[4][2];
            #pragma unroll
            for (int mt = 0; mt < 4; mt++) {
                const int row = wm + mt * 16 + (lane & 15);
                ldsm_x4(af[mt], sa + row * 128 + ((gr ^ (row & 7)) * 16));
            }
            #pragma unroll
            for (int np = 0; np < 2; np++) {
                const int row = wn + np * 16 + (lane & 15);
                uint32_t q[4];
                ldsm_x4(q, sbB + row * 128 + ((gr ^ (row & 7)) * 16));
                bf[2 * np][0] = q[0]; bf[2 * np + 1][0] = q[1];
                bf[2 * np][1] = q[2]; bf[2 * np + 1][1] = q[3];
            }
            #pragma unroll
            for (int mt = 0; mt < 4; mt++)
                #pragma unroll
                for (int nt = 0; nt < 4; nt++)
                    mma_f16(acc[mt][nt], af[mt], bf[nt]);
        }
        __syncthreads();
        if (t + 3 < NT) g_issue(sbase, t % 3, A, W, bm, bn, K,
                                (t + 3) * 64, tid);
        cp_commit();
    }

    #pragma unroll
    for (int mt = 0; mt < 4; mt++) {
        const int m0 = bm + wm + mt * 16 + g;
        #pragma unroll
        for (int nt = 0; nt < 4; nt++) {
            const int n = bn + wn + nt * 8 + 2 * th;
            const float b0 = bias[n], b1 = bias[n + 1];
            float v00 = acc[mt][nt][0] + b0, v01 = acc[mt][nt][1] + b1;
            float v10 = acc[mt][nt][2] + b0, v11 = acc[mt][nt][3] + b1;
            if (EPI == 1) {
                const float2 x0 = *(const float2*)&aux[(size_t)m0 * Ntot + n];
                const float2 x1 = *(const float2*)&aux[(size_t)(m0 + 8) * Ntot + n];
                v00 += x0.x; v01 += x0.y; v10 += x1.x; v11 += x1.y;
            }
            if (OUT16) {
                __half* C = (__half*)Cv;
                *(uint32_t*)&C[(size_t)m0 * Ntot + n]       = pack_h2(v00, v01);
                *(uint32_t*)&C[(size_t)(m0 + 8) * Ntot + n] = pack_h2(v10, v11);
            } else {
                float* C = (float*)Cv;
                *(float2*)&C[(size_t)m0 * Ntot + n]       = make_float2(v00, v01);
                *(float2*)&C[(size_t)(m0 + 8) * Ntot + n] = make_float2(v10, v11);
            }
        }
    }
}

// ---------------- Fused SwiGLU GEMM (fp16) ----------------------------------
// H = silu(A Wg^T + bg) * (A Wu^T + bu). CTA 128x128, 512 threads (16 warps,
// 2x8), warp tile 64x16, dual accumulators, K-chunk 64, 3-stage.
#define USTG_BYTES 49152     // A 16KB + Wg 16KB + Wu 16KB
#define USMEM (3 * USTG_BYTES)

__device__ __forceinline__ void u_issue(
    uint32_t sbase, int slot, const __half* A, const __half* Wg,
    const __half* Wu, int bm, int bn, int k0, int tid)
{
    const uint32_t sb = sbase + slot * USTG_BYTES;
    #pragma unroll
    for (int i = 0; i < 6; i++) {
        const int gi = tid + i * 512;
        const int r = (gi & 1023) >> 3, c = gi & 7;
        const uint32_t dst = r * 128 + ((c ^ (r & 7)) * 16);
        if (gi < 1024)
            cp16(sb + dst, A + (size_t)(bm + r) * DMODEL + k0 + c * 8);
        else if (gi < 2048)
            cp16(sb + 16384 + dst, Wg + (size_t)(bn + r) * DMODEL + k0 + c * 8);
        else
            cp16(sb + 32768 + dst, Wu + (size_t)(bn + r) * DMODEL + k0 + c * 8);
    }
}

__global__ __launch_bounds__(512, 1) void gemm_glu(
    const __half* __restrict__ A, const __half* __restrict__ Wg,
    const __half* __restrict__ Wu, const float* __restrict__ bg,
    const float* __restrict__ bu, __half* __restrict__ H)
{
    extern __shared__ float usm[];
    const uint32_t sbase = smem_u32(usm);
    const int tid = threadIdx.x, wid = tid >> 5, lane = tid & 31;
    const int g = lane >> 2, th = lane & 3;
    const int bm = blockIdx.x * 128, bn = blockIdx.y * 128;
    const int wm = (wid & 1) * 64, wn = (wid >> 1) * 16;

    float accG[4][2][4], accU[4][2][4];
    #pragma unroll
    for (int mt = 0; mt < 4; mt++)
        #pragma unroll
        for (int nt = 0; nt < 2; nt++)
            #pragma unroll
            for (int c = 0; c < 4; c++) { accG[mt][nt][c] = 0.f; accU[mt][nt][c] = 0.f; }

    const int NT = DMODEL >> 6;   // 16
    #pragma unroll
    for (int t = 0; t < 3; t++) {
        u_issue(sbase, t, A, Wg, Wu, bm, bn, t * 64, tid);
        cp_commit();
    }

    for (int t = 0; t < NT; t++) {
        cp_wait<2>();
        __syncthreads();
        const uint32_t sa = sbase + (t % 3) * USTG_BYTES;

        #pragma unroll
        for (int ks = 0; ks < 4; ks++) {
            const int gr = 2 * ks + (lane >> 4);
            uint32_t af[4][4], bG[2][2], bU[2][2];
            #pragma unroll
            for (int mt = 0; mt < 4; mt++) {
                const int row = wm + mt * 16 + (lane & 15);
                ldsm_x4(af[mt], sa + row * 128 + ((gr ^ (row & 7)) * 16));
            }
            {
                const int row = wn + (lane & 15);
                const uint32_t off = row * 128 + ((gr ^ (row & 7)) * 16);
                uint32_t q[4];
                ldsm_x4(q, sa + 16384 + off);
                bG[0][0] = q[0]; bG[1][0] = q[1];
                bG[0][1] = q[2]; bG[1][1] = q[3];
                ldsm_x4(q, sa + 32768 + off);
                bU[0][0] = q[0]; bU[1][0] = q[1];
                bU[0][1] = q[2]; bU[1][1] = q[3];
            }
            #pragma unroll
            for (int mt = 0; mt < 4; mt++)
                #pragma unroll
                for (int nt = 0; nt < 2; nt++) {
                    mma_f16(accG[mt][nt], af[mt], bG[nt]);
                    mma_f16(accU[mt][nt], af[mt], bU[nt]);
                }
        }
        __syncthreads();
        if (t + 3 < NT) u_issue(sbase, t % 3, A, Wg, Wu, bm, bn,
                                (t + 3) * 64, tid);
        cp_commit();
    }

    #pragma unroll
    for (int mt = 0; mt < 4; mt++) {
        const int m0 = bm + wm + mt * 16 + g;
        #pragma unroll
        for (int nt = 0; nt < 2; nt++) {
            const int n = bn + wn + nt * 8 + 2 * th;
            const float bg0 = bg[n], bg1 = bg[n + 1];
            const float bu0 = bu[n], bu1 = bu[n + 1];
            #pragma unroll
            for (int r = 0; r < 2; r++) {
                const float ga = accG[mt][nt][2 * r]     + bg0;
                const float gb = accG[mt][nt][2 * r + 1] + bg1;
                const float ua = accU[mt][nt][2 * r]     + bu0;
                const float ub = accU[mt][nt][2 * r + 1] + bu1;
                const float ha = ua * ga / (1.f + __expf(-ga));
                const float hb = ub * gb / (1.f + __expf(-gb));
                *(uint32_t*)&H[(size_t)(m0 + 8 * r) * DFFN + n] = pack_h2(ha, hb);
            }
        }
    }
}

// ---------------- Flash attention (proven tf32 kernel) ----------------------
// 256 threads (8 warps), q-tile 128, kv tiles 64, double-buffered fp32 smem.
// Input: fp32 qkv.  Output: fp16 (feeds o-proj GEMM).
#define KVSTG (64 * 68 + 64 * 72)
#define APQ   (2 * KVSTG)
#define ATT_SMEM ((2 * KVSTG + 128 * 68) * 4)

__device__ __forceinline__ void kv_issue(
    uint32_t sb, int slot, const float* kb, const float* vb, int tid)
{
    const int kbase = slot * KVSTG;
    const int vbase = slot * KVSTG + 64 * 68;
    #pragma unroll
    for (int i = 0; i < 4; i++) {
        const int gi = tid + i * 256;
        const int r = gi >> 4, gr = gi & 15;
        cp16(sb + (kbase + r * 68 + gr * 4) * 4, kb + (size_t)r * 3072 + gr * 4);
        cp16(sb + (vbase + r * 72 + gr * 4) * 4, vb + (size_t)r * 3072 + gr * 4);
    }
}

__global__ __launch_bounds__(256) void attn_mma(
    const float* __restrict__ qkv, __half* __restrict__ out)
{
    extern __shared__ float sm[];
    const uint32_t sb = smem_u32(sm);
    const int tid = threadIdx.x, wid = tid >> 5, lane = tid & 31;
    const int g = lane >> 2, th = lane & 3;
    const int bq = blockIdx.x, h = blockIdx.y, b = blockIdx.z;
    const float slope = exp2f(-0.5f * (float)(h + 1));

    const float* base = qkv + (size_t)b * SEQ * 3072;

    {
        const float* qb = base + (size_t)(bq * 128) * 3072 + h * 64;
        #pragma unroll
        for (int i = 0; i < 8; i++) {
            const int gi = tid + i * 256;
            const int r = gi >> 4, gr = gi & 15;
            cp16(sb + (APQ + r * 68 + gr * 4) * 4, qb + (size_t)r * 3072 + gr * 4);
        }
        cp_commit();
        cp_wait<0>();
        __syncthreads();
    }

    uint32_t aQ[8][4];
    #pragma unroll
    for (int ks = 0; ks < 8; ks++) {
        const int r0 = APQ + (wid * 16 + g) * 68 + ks * 8 + th;
        aQ[ks][0] = __float_as_uint(sm[r0]);
        aQ[ks][1] = __float_as_uint(sm[r0 + 8 * 68]);
        aQ[ks][2] = __float_as_uint(sm[r0 + 4]);
        aQ[ks][3] = __float_as_uint(sm[r0 + 8 * 68 + 4]);
    }
    __syncthreads();

    const int wp = APQ + wid * (16 * 68);
    float m0 = -1e30f, m1 = -1e30f, l0 = 0.f, l1 = 0.f;
    float O[8][4];
    #pragma unroll
    for (int nt = 0; nt < 8; nt++)
        #pragma unroll
        for (int c = 0; c < 4; c++) O[nt][c] = 0.f;

    const int q0 = bq * 128 + wid * 16 + g;
    const int q1 = q0 + 8;
    const float* kb0 = base + DMODEL + h * 64;
    const float* vb0 = base + 2 * DMODEL + h * 64;

    kv_issue(sb, 0, kb0, vb0, tid);
    cp_commit();

    for (int t = 0; t < 16; t++) {
        if (t + 1 < 16) {
            kv_issue(sb, (t + 1) & 1, kb0 + (size_t)((t + 1) * 64) * 3072,
                     vb0 + (size_t)((t + 1) * 64) * 3072, tid);
        }
        cp_commit();
        cp_wait<1>();
        __syncthreads();

        const int AK = (t & 1) * KVSTG;
        const int AV = AK + 64 * 68;

        float S[8][4];
        #pragma unroll
        for (int nt = 0; nt < 8; nt++) {
            #pragma unroll
            for (int c = 0; c < 4; c++) S[nt][c] = 0.f;
            #pragma unroll
            for (int ks = 0; ks < 8; ks++) {
                uint32_t bf[2];
                const int bi = AK + (nt * 8 + g) * 68 + ks * 8 + th;
                bf[0] = __float_as_uint(sm[bi]);
                bf[1] = __float_as_uint(sm[bi + 4]);
                mma_tf32(S[nt], aQ[ks], bf);
            }
        }

        float mx0 = -1e30f, mx1 = -1e30f;
        #pragma unroll
        for (int nt = 0; nt < 8; nt++) {
            const int kc = t * 64 + nt * 8 + 2 * th;
            S[nt][0] = S[nt][0] * 0.125f - slope * fabsf((float)(q0 - kc));
            S[nt][1] = S[nt][1] * 0.125f - slope * fabsf((float)(q0 - kc - 1));
            S[nt][2] = S[nt][2] * 0.125f - slope * fabsf((float)(q1 - kc));
            S[nt][3] = S[nt][3] * 0.125f - slope * fabsf((float)(q1 - kc - 1));
            mx0 = fmaxf(mx0, fmaxf(S[nt][0], S[nt][1]));
            mx1 = fmaxf(mx1, fmaxf(S[nt][2], S[nt][3]));
        }
        #pragma unroll
        for (int off = 1; off <= 2; off <<= 1) {
            mx0 = fmaxf(mx0, __shfl_xor_sync(0xffffffffu, mx0, off));
            mx1 = fmaxf(mx1, __shfl_xor_sync(0xffffffffu, mx1, off));
        }
        const float mn0 = fmaxf(m0, mx0), mn1 = fmaxf(m1, mx1);
        const float sc0 = __expf(m0 - mn0), sc1 = __expf(m1 - mn1);
        float s0 = 0.f, s1 = 0.f;
        #pragma unroll
        for (int nt = 0; nt < 8; nt++) {
            const float p00 = to_tf32(__expf(S[nt][0] - mn0));
            const float p01 = to_tf32(__expf(S[nt][1] - mn0));
            const float p10 = to_tf32(__expf(S[nt][2] - mn1));
            const float p11 = to_tf32(__expf(S[nt][3] - mn1));
            s0 += p00 + p01; s1 += p10 + p11;
            *(float2*)&sm[wp + g * 68 + nt * 8 + 2 * th] = make_float2(p00, p01);
            *(float2*)&sm[wp + (g + 8) * 68 + nt * 8 + 2 * th] = make_float2(p10, p11);
        }
        #pragma unroll
        for (int off = 1; off <= 2; off <<= 1) {
            s0 += __shfl_xor_sync(0xffffffffu, s0, off);
            s1 += __shfl_xor_sync(0xffffffffu, s1, off);
        }
        l0 = l0 * sc0 + s0; l1 = l1 * sc1 + s1;
        m0 = mn0; m1 = mn1;
        #pragma unroll
        for (int nt = 0; nt < 8; nt++) {
            O[nt][0] *= sc0; O[nt][1] *= sc0;
            O[nt][2] *= sc1; O[nt][3] *= sc1;
        }
        __syncwarp();

        #pragma unroll
        for (int ks = 0; ks < 8; ks++) {
            uint32_t aP[4];
            const int pi = wp + g * 68 + ks * 8 + th;
            aP[0] = __float_as_uint(sm[pi]);
            aP[1] = __float_as_uint(sm[pi + 8 * 68]);
            aP[2] = __float_as_uint(sm[pi + 4]);
            aP[3] = __float_as_uint(sm[pi + 8 * 68 + 4]);
            #pragma unroll
            for (int nt = 0; nt < 8; nt++) {
                uint32_t bf[2];
                bf[0] = __float_as_uint(sm[AV + (ks * 8 + th) * 72 + nt * 8 + g]);
                bf[1] = __float_as_uint(sm[AV + (ks * 8 + th + 4) * 72 + nt * 8 + g]);
                mma_tf32(O[nt], aP, bf);
            }
        }
        __syncthreads();
    }

    const float i0 = 1.f / l0, i1 = 1.f / l1;
    #pragma unroll
    for (int nt = 0; nt < 8; nt++) {
        const int n = h * 64 + nt * 8 + 2 * th;
        *(uint32_t*)&out[(size_t)(b * SEQ + q0) * DMODEL + n] =
            pack_h2(O[nt][0] * i0, O[nt][1] * i0);
        *(uint32_t*)&out[(size_t)(b * SEQ + q1) * DMODEL + n] =
            pack_h2(O[nt][2] * i1, O[nt][3] * i1);
    }
}

// ---------------- LayerNorm (fp16 output) -----------------------------------
__global__ __launch_bounds__(256) void ln_kernel(
    const float* __restrict__ x, const float* __restrict__ g,
    const float* __restrict__ b, __half* __restrict__ y)
{
    __shared__ float redS[8];
    __shared__ float redQ[8];
    const int row = blockIdx.x;
    const int tid = threadIdx.x;

    const float4 v = ((const float4*)(x + (size_t)row * DMODEL))[tid];
    float s = v.x + v.y + v.z + v.w;
    float q = v.x*v.x + v.y*v.y + v.z*v.z + v.w*v.w;
    #pragma unroll
    for (int off = 16; off >= 1; off >>= 1) {
        s += __shfl_xor_sync(0xffffffffu, s, off);
        q += __shfl_xor_sync(0xffffffffu, q, off);
    }
    if ((tid & 31) == 0) { redS[tid >> 5] = s; redQ[tid >> 5] = q; }
    __syncthreads();
    if (tid < 32) {
        s = (tid < 8) ? redS[tid] : 0.f;
        q = (tid < 8) ? redQ[tid] : 0.f;
        #pragma unroll
        for (int off = 4; off >= 1; off >>= 1) {
            s += __shfl_xor_sync(0xffffffffu, s, off);
            q += __shfl_xor_sync(0xffffffffu, q, off);
        }
        if (tid == 0) { redS[0] = s; redQ[0] = q; }
    }
    __syncthreads();
    const float mu  = redS[0] * (1.f / DMODEL);
    const float var = redQ[0] * (1.f / DMODEL) - mu * mu;
    const float rstd = rsqrtf(var + 1e-5f);

    const float4 gv = ((const float4*)g)[tid];
    const float4 bv = ((const float4*)b)[tid];
    uint32_t o0 = pack_h2((v.x - mu) * rstd * gv.x + bv.x,
                          (v.y - mu) * rstd * gv.y + bv.y);
    uint32_t o1 = pack_h2((v.z - mu) * rstd * gv.z + bv.z,
                          (v.w - mu) * rstd * gv.w + bv.w);
    uint2* yo = (uint2*)(y + (size_t)row * DMODEL);
    yo[tid] = make_uint2(o0, o1);
}

// ---------------- launch -----------------------------------------------------
extern "C" void kernel_launch(void* const* d_in, const int* in_sizes, int n_in,
                              void* d_out, int out_size)
{
    const float* src    = (const float*)d_in[0];
    const float* wqkv   = (const float*)d_in[1];
    const float* bqkv   = (const float*)d_in[2];
    const float* wo     = (const float*)d_in[3];
    const float* bo     = (const float*)d_in[4];
    const float* g1     = (const float*)d_in[5];
    const float* b1     = (const float*)d_in[6];
    const float* g2     = (const float*)d_in[7];
    const float* b2     = (const float*)d_in[8];
    const float* w_gate = (const float*)d_in[9];
    const float* b_gate = (const float*)d_in[10];
    const float* w_up   = (const float*)d_in[11];
    const float* b_up   = (const float*)d_in[12];
    const float* w_down = (const float*)d_in[13];
    const float* b_down = (const float*)d_in[14];
    float* out = (float*)d_out;

    __half *lnh, *atth, *hh, *wh;
    float  *qkv, *x1;
    cudaGetSymbolAddress((void**)&lnh,  g_lnh);
    cudaGetSymbolAddress((void**)&qkv,  g_qkv);
    cudaGetSymbolAddress((void**)&atth, g_atth);
    cudaGetSymbolAddress((void**)&hh,   g_hh);
    cudaGetSymbolAddress((void**)&wh,   g_wh);
    cudaGetSymbolAddress((void**)&x1,   g_x1);

    cudaFuncSetAttribute(gemm_h<0, 0>,
        cudaFuncAttributeMaxDynamicSharedMemorySize, GSMEM);
    cudaFuncSetAttribute(gemm_h<1, 0>,
        cudaFuncAttributeMaxDynamicSharedMemorySize, GSMEM);
    cudaFuncSetAttribute(gemm_glu,
        cudaFuncAttributeMaxDynamicSharedMemorySize, USMEM);
    cudaFuncSetAttribute(attn_mma,
        cudaFuncAttributeMaxDynamicSharedMemorySize, ATT_SMEM);

    // weights fp32 -> fp16
    cvt_w<<<3072, 256>>>((const float4*)wqkv,   (__half2*)(wh + W_QKV), 786432);
    cvt_w<<<1024, 256>>>((const float4*)wo,     (__half2*)(wh + W_O),   262144);
    cvt_w<<<4096, 256>>>((const float4*)w_gate, (__half2*)(wh + W_G),  1048576);
    cvt_w<<<4096, 256>>>((const float4*)w_up,   (__half2*)(wh + W_U),  1048576);
    cvt_w<<<4096, 256>>>((const float4*)w_down, (__half2*)(wh + W_D),  1048576);

    // x = src + Attn(LN1(src))
    ln_kernel<<<MTOT, 256>>>(src, g1, b1, lnh);
    gemm_h<0, 0><<<dim3(64, 12), 512, GSMEM>>>(lnh, wh + W_QKV, bqkv, nullptr,
                                               qkv, 3 * DMODEL, DMODEL);
    attn_mma<<<dim3(8, NHEAD, BATCH), 256, ATT_SMEM>>>(qkv, atth);
    gemm_h<1, 0><<<dim3(64, 4), 512, GSMEM>>>(atth, wh + W_O, bo, src,
                                              x1, DMODEL, DMODEL);

    // x = x + SwiGLU(LN2(x))
    ln_kernel<<<MTOT, 256>>>(x1, g2, b2, lnh);
    gemm_glu<<<dim3(64, 32), 512, USMEM>>>(lnh, wh + W_G, wh + W_U,
                                           b_gate, b_up, hh);
    gemm_h<1, 0><<<dim3(64, 4), 512, GSMEM>>>(hh, wh + W_D, b_down, x1,
                                              out, DMODEL, DFFN);
}

// round 12
// speedup vs baseline: 6.6767x; 1.1458x over previous
#include <cuda_runtime.h>
#include <cuda_fp16.h>
#include <math.h>
#include <stdint.h>

#define MTOT   8192
#define DMODEL 1024
#define DFFN   4096
#define NHEAD  16
#define HDIM   64
#define SEQ    1024
#define BATCH  8

// ---------------- scratch (device globals; no allocations) ----------------
__device__ __half g_wh[16 * 1024 * 1024];      // fp16 weights (32 MB)
__device__ __half g_lnh[MTOT * DMODEL];        // fp16 LN output
__device__ __half g_qkvh[MTOT * 3 * DMODEL];   // fp16 qkv
__device__ __half g_atth[MTOT * DMODEL];       // fp16 attention output
__device__ __half g_hh[MTOT * DFFN];           // fp16 silu(gate)*up
__device__ float  g_x1[MTOT * DMODEL];         // fp32 residual stream

#define W_QKV  0
#define W_O    (3 * 1024 * 1024)
#define W_G    (4 * 1024 * 1024)
#define W_U    (8 * 1024 * 1024)
#define W_D    (12 * 1024 * 1024)

// ---------------- PTX helpers ---------------------------------------------
__device__ __forceinline__ uint32_t smem_u32(const void* p) {
    uint32_t a;
    asm("{ .reg .u64 t; cvta.to.shared.u64 t, %1; cvt.u32.u64 %0, t; }"
        : "=r"(a) : "l"(p));
    return a;
}
__device__ __forceinline__ void cp16(uint32_t dst, const void* src) {
    asm volatile("cp.async.cg.shared.global [%0], [%1], 16;"
                 :: "r"(dst), "l"(src) : "memory");
}
__device__ __forceinline__ void cp_commit() {
    asm volatile("cp.async.commit_group;" ::: "memory");
}
template <int N>
__device__ __forceinline__ void cp_wait() {
    asm volatile("cp.async.wait_group %0;" :: "n"(N) : "memory");
}
__device__ __forceinline__ void sts32(uint32_t addr, uint32_t val) {
    asm volatile("st.shared.b32 [%0], %1;" :: "r"(addr), "r"(val) : "memory");
}
__device__ __forceinline__ void ldsm_x4(uint32_t r[4], uint32_t addr) {
    asm volatile("ldmatrix.sync.aligned.m8n8.x4.shared.b16 {%0,%1,%2,%3}, [%4];"
        : "=r"(r[0]), "=r"(r[1]), "=r"(r[2]), "=r"(r[3]) : "r"(addr));
}
__device__ __forceinline__ void ldsm_x4t(uint32_t r[4], uint32_t addr) {
    asm volatile("ldmatrix.sync.aligned.m8n8.x4.trans.shared.b16 {%0,%1,%2,%3}, [%4];"
        : "=r"(r[0]), "=r"(r[1]), "=r"(r[2]), "=r"(r[3]) : "r"(addr));
}
__device__ __forceinline__ void mma_f16(float c[4], const uint32_t a[4],
                                        const uint32_t b[2]) {
    asm volatile(
        "mma.sync.aligned.m16n8k16.row.col.f32.f16.f16.f32 "
        "{%0,%1,%2,%3}, {%4,%5,%6,%7}, {%8,%9}, {%0,%1,%2,%3};\n"
        : "+f"(c[0]), "+f"(c[1]), "+f"(c[2]), "+f"(c[3])
        : "r"(a[0]), "r"(a[1]), "r"(a[2]), "r"(a[3]), "r"(b[0]), "r"(b[1]));
}
__device__ __forceinline__ uint32_t pack_h2(float a, float b) {
    __half2 h = __floats2half2_rn(a, b);
    return *reinterpret_cast<uint32_t*>(&h);
}

// ---------------- weight fp32 -> fp16 --------------------------------------
__global__ __launch_bounds__(256) void cvt_w(
    const float4* __restrict__ in, __half2* __restrict__ out, int n4)
{
    const int i = blockIdx.x * 256 + threadIdx.x;
    if (i < n4) {
        float4 v = in[i];
        out[2 * i]     = __floats2half2_rn(v.x, v.y);
        out[2 * i + 1] = __floats2half2_rn(v.z, v.w);
    }
}

// ---------------- FP16 mma.sync NT GEMM ------------------------------------
// C[M, Ntot] = A[M, K] * W[Ntot, K]^T + bias. CTA 128x256, 512 threads
// (16 warps, 2x8), warp tile 64x32. K-chunk 64 per stage (row = 128B,
// swizzle chunk ^ (row&7)), 3-stage cp.async, all-x4 ldmatrix.
// EPI 0: +bias | 1: +bias+aux(fp32). OUT16: write fp16 else fp32.
#define GSTG_BYTES 49152     // A 16KB + B 32KB
#define GSMEM (3 * GSTG_BYTES)

__device__ __forceinline__ void g_issue(
    uint32_t sbase, int slot, const __half* A, const __half* W,
    int bm, int bn, int K, int k0, int tid)
{
    const uint32_t sb = sbase + slot * GSTG_BYTES;
    #pragma unroll
    for (int i = 0; i < 6; i++) {
        const int gi = tid + i * 512;
        if (gi < 1024) {
            const int r = gi >> 3, c = gi & 7;
            cp16(sb + r * 128 + ((c ^ (r & 7)) * 16),
                 A + (size_t)(bm + r) * K + k0 + c * 8);
        } else {
            const int j = gi - 1024;
            const int r = j >> 3, c = j & 7;
            cp16(sb + 16384 + r * 128 + ((c ^ (r & 7)) * 16),
                 W + (size_t)(bn + r) * K + k0 + c * 8);
        }
    }
}

template <int EPI, int OUT16>
__global__ __launch_bounds__(512, 1) void gemm_h(
    const __half* __restrict__ A, const __half* __restrict__ W,
    const float* __restrict__ bias, const float* __restrict__ aux,
    void* __restrict__ Cv, int Ntot, int K)
{
    extern __shared__ float gsm[];
    const uint32_t sbase = smem_u32(gsm);
    const int tid = threadIdx.x, wid = tid >> 5, lane = tid & 31;
    const int g = lane >> 2, th = lane & 3;
    const int bm = blockIdx.x * 128, bn = blockIdx.y * 256;
    const int wm = (wid & 1) * 64, wn = (wid >> 1) * 32;

    float acc[4][4][4];
    #pragma unroll
    for (int mt = 0; mt < 4; mt++)
        #pragma unroll
        for (int nt = 0; nt < 4; nt++)
            #pragma unroll
            for (int c = 0; c < 4; c++) acc[mt][nt][c] = 0.f;

    const int NT = K >> 6;
    #pragma unroll
    for (int t = 0; t < 3; t++) {
        if (t < NT) g_issue(sbase, t, A, W, bm, bn, K, t * 64, tid);
        cp_commit();
    }

    for (int t = 0; t < NT; t++) {
        cp_wait<2>();
        __syncthreads();
        const uint32_t sa = sbase + (t % 3) * GSTG_BYTES;
        const uint32_t sbB = sa + 16384;

        #pragma unroll
        for (int ks = 0; ks < 4; ks++) {
            const int gr = 2 * ks + (lane >> 4);
            uint32_t af[4][4], bf[4][2];
            #pragma unroll
            for (int mt = 0; mt < 4; mt++) {
                const int row = wm + mt * 16 + (lane & 15);
                ldsm_x4(af[mt], sa + row * 128 + ((gr ^ (row & 7)) * 16));
            }
            #pragma unroll
            for (int np = 0; np < 2; np++) {
                const int row = wn + np * 16 + (lane & 15);
                uint32_t q[4];
                ldsm_x4(q, sbB + row * 128 + ((gr ^ (row & 7)) * 16));
                bf[2 * np][0] = q[0]; bf[2 * np + 1][0] = q[1];
                bf[2 * np][1] = q[2]; bf[2 * np + 1][1] = q[3];
            }
            #pragma unroll
            for (int mt = 0; mt < 4; mt++)
                #pragma unroll
                for (int nt = 0; nt < 4; nt++)
                    mma_f16(acc[mt][nt], af[mt], bf[nt]);
        }
        __syncthreads();
        if (t + 3 < NT) g_issue(sbase, t % 3, A, W, bm, bn, K,
                                (t + 3) * 64, tid);
        cp_commit();
    }

    #pragma unroll
    for (int mt = 0; mt < 4; mt++) {
        const int m0 = bm + wm + mt * 16 + g;
        #pragma unroll
        for (int nt = 0; nt < 4; nt++) {
            const int n = bn + wn + nt * 8 + 2 * th;
            const float b0 = bias[n], b1 = bias[n + 1];
            float v00 = acc[mt][nt][0] + b0, v01 = acc[mt][nt][1] + b1;
            float v10 = acc[mt][nt][2] + b0, v11 = acc[mt][nt][3] + b1;
            if (EPI == 1) {
                const float2 x0 = *(const float2*)&aux[(size_t)m0 * Ntot + n];
                const float2 x1 = *(const float2*)&aux[(size_t)(m0 + 8) * Ntot + n];
                v00 += x0.x; v01 += x0.y; v10 += x1.x; v11 += x1.y;
            }
            if (OUT16) {
                __half* C = (__half*)Cv;
                *(uint32_t*)&C[(size_t)m0 * Ntot + n]       = pack_h2(v00, v01);
                *(uint32_t*)&C[(size_t)(m0 + 8) * Ntot + n] = pack_h2(v10, v11);
            } else {
                float* C = (float*)Cv;
                *(float2*)&C[(size_t)m0 * Ntot + n]       = make_float2(v00, v01);
                *(float2*)&C[(size_t)(m0 + 8) * Ntot + n] = make_float2(v10, v11);
            }
        }
    }
}

// ---------------- Fused SwiGLU GEMM (fp16) ----------------------------------
#define USTG_BYTES 49152     // A 16KB + Wg 16KB + Wu 16KB
#define USMEM (3 * USTG_BYTES)

__device__ __forceinline__ void u_issue(
    uint32_t sbase, int slot, const __half* A, const __half* Wg,
    const __half* Wu, int bm, int bn, int k0, int tid)
{
    const uint32_t sb = sbase + slot * USTG_BYTES;
    #pragma unroll
    for (int i = 0; i < 6; i++) {
        const int gi = tid + i * 512;
        const int r = (gi & 1023) >> 3, c = gi & 7;
        const uint32_t dst = r * 128 + ((c ^ (r & 7)) * 16);
        if (gi < 1024)
            cp16(sb + dst, A + (size_t)(bm + r) * DMODEL + k0 + c * 8);
        else if (gi < 2048)
            cp16(sb + 16384 + dst, Wg + (size_t)(bn + r) * DMODEL + k0 + c * 8);
        else
            cp16(sb + 32768 + dst, Wu + (size_t)(bn + r) * DMODEL + k0 + c * 8);
    }
}

__global__ __launch_bounds__(512, 1) void gemm_glu(
    const __half* __restrict__ A, const __half* __restrict__ Wg,
    const __half* __restrict__ Wu, const float* __restrict__ bg,
    const float* __restrict__ bu, __half* __restrict__ H)
{
    extern __shared__ float usm[];
    const uint32_t sbase = smem_u32(usm);
    const int tid = threadIdx.x, wid = tid >> 5, lane = tid & 31;
    const int g = lane >> 2, th = lane & 3;
    const int bm = blockIdx.x * 128, bn = blockIdx.y * 128;
    const int wm = (wid & 1) * 64, wn = (wid >> 1) * 16;

    float accG[4][2][4], accU[4][2][4];
    #pragma unroll
    for (int mt = 0; mt < 4; mt++)
        #pragma unroll
        for (int nt = 0; nt < 2; nt++)
            #pragma unroll
            for (int c = 0; c < 4; c++) { accG[mt][nt][c] = 0.f; accU[mt][nt][c] = 0.f; }

    const int NT = DMODEL >> 6;   // 16
    #pragma unroll
    for (int t = 0; t < 3; t++) {
        u_issue(sbase, t, A, Wg, Wu, bm, bn, t * 64, tid);
        cp_commit();
    }

    for (int t = 0; t < NT; t++) {
        cp_wait<2>();
        __syncthreads();
        const uint32_t sa = sbase + (t % 3) * USTG_BYTES;

        #pragma unroll
        for (int ks = 0; ks < 4; ks++) {
            const int gr = 2 * ks + (lane >> 4);
            uint32_t af[4][4], bG[2][2], bU[2][2];
            #pragma unroll
            for (int mt = 0; mt < 4; mt++) {
                const int row = wm + mt * 16 + (lane & 15);
                ldsm_x4(af[mt], sa + row * 128 + ((gr ^ (row & 7)) * 16));
            }
            {
                const int row = wn + (lane & 15);
                const uint32_t off = row * 128 + ((gr ^ (row & 7)) * 16);
                uint32_t q[4];
                ldsm_x4(q, sa + 16384 + off);
                bG[0][0] = q[0]; bG[1][0] = q[1];
                bG[0][1] = q[2]; bG[1][1] = q[3];
                ldsm_x4(q, sa + 32768 + off);
                bU[0][0] = q[0]; bU[1][0] = q[1];
                bU[0][1] = q[2]; bU[1][1] = q[3];
            }
            #pragma unroll
            for (int mt = 0; mt < 4; mt++)
                #pragma unroll
                for (int nt = 0; nt < 2; nt++) {
                    mma_f16(accG[mt][nt], af[mt], bG[nt]);
                    mma_f16(accU[mt][nt], af[mt], bU[nt]);
                }
        }
        __syncthreads();
        if (t + 3 < NT) u_issue(sbase, t % 3, A, Wg, Wu, bm, bn,
                                (t + 3) * 64, tid);
        cp_commit();
    }

    #pragma unroll
    for (int mt = 0; mt < 4; mt++) {
        const int m0 = bm + wm + mt * 16 + g;
        #pragma unroll
        for (int nt = 0; nt < 2; nt++) {
            const int n = bn + wn + nt * 8 + 2 * th;
            const float bg0 = bg[n], bg1 = bg[n + 1];
            const float bu0 = bu[n], bu1 = bu[n + 1];
            #pragma unroll
            for (int r = 0; r < 2; r++) {
                const float ga = accG[mt][nt][2 * r]     + bg0;
                const float gb = accG[mt][nt][2 * r + 1] + bg1;
                const float ua = accU[mt][nt][2 * r]     + bu0;
                const float ub = accU[mt][nt][2 * r + 1] + bu1;
                const float ha = ua * ga / (1.f + __expf(-ga));
                const float hb = ub * gb / (1.f + __expf(-gb));
                *(uint32_t*)&H[(size_t)(m0 + 8 * r) * DFFN + n] = pack_h2(ha, hb);
            }
        }
    }
}

// ---------------- Flash attention (fp16 mma, ALiBi) -------------------------
// 256 threads (8 warps), q-tile 128 (16 rows/warp), kv tiles 64, double-buffer.
// smem bytes: K stage s 64x128B @ s*16384; V stage s @ s*16384 + 8192.
// PQ region @ 32768: Q staging 128x128B, then per-warp P 16x128B.
#define AKV   16384
#define APQ   32768
#define ATT_SMEM (32768 + 16384)

__device__ __forceinline__ void kv_issue(
    uint32_t sb, int slot, const __half* kb, const __half* vb, int tid)
{
    const uint32_t kb0 = sb + slot * AKV;
    const uint32_t vb0 = kb0 + 8192;
    #pragma unroll
    for (int i = 0; i < 4; i++) {
        const int gi = tid + i * 256;
        if (gi < 512) {
            const int r = gi >> 3, c = gi & 7;
            cp16(kb0 + r * 128 + ((c ^ (r & 7)) * 16),
                 kb + (size_t)r * 3072 + c * 8);
        } else {
            const int r2 = (gi - 512) >> 3, c2 = gi & 7;
            cp16(vb0 + r2 * 128 + ((c2 ^ (r2 & 7)) * 16),
                 vb + (size_t)r2 * 3072 + c2 * 8);
        }
    }
}

__global__ __launch_bounds__(256) void attn_mma(
    const __half* __restrict__ qkv, __half* __restrict__ out)
{
    extern __shared__ float smf[];
    const uint32_t sb = smem_u32(smf);
    const int tid = threadIdx.x, wid = tid >> 5, lane = tid & 31;
    const int g = lane >> 2, th = lane & 3;
    const int bq = blockIdx.x, h = blockIdx.y, b = blockIdx.z;
    const float slope = exp2f(-0.5f * (float)(h + 1));

    const __half* base = qkv + (size_t)b * SEQ * 3072;

    // stage Q tile (128 x 64 fp16)
    {
        const __half* qb = base + (size_t)(bq * 128) * 3072 + h * 64;
        #pragma unroll
        for (int i = 0; i < 4; i++) {
            const int gi = tid + i * 256;
            const int r = gi >> 3, c = gi & 7;
            cp16(sb + APQ + r * 128 + ((c ^ (r & 7)) * 16),
                 qb + (size_t)r * 3072 + c * 8);
        }
        cp_commit();
        cp_wait<0>();
        __syncthreads();
    }

    // per-warp Q a-frags (rows wid*16..+15), ks = k16 step
    uint32_t aQ[4][4];
    #pragma unroll
    for (int ks = 0; ks < 4; ks++) {
        const int row = wid * 16 + (lane & 15);
        const int gr = 2 * ks + (lane >> 4);
        ldsm_x4(aQ[ks], sb + APQ + row * 128 + ((gr ^ (row & 7)) * 16));
    }
    __syncthreads();

    const uint32_t wp = sb + APQ + wid * 2048;   // per-warp P (16 x 128B)
    float m0 = -1e30f, m1 = -1e30f, l0 = 0.f, l1 = 0.f;
    float O[8][4];
    #pragma unroll
    for (int nt = 0; nt < 8; nt++)
        #pragma unroll
        for (int c = 0; c < 4; c++) O[nt][c] = 0.f;

    const int q0 = bq * 128 + wid * 16 + g;
    const int q1 = q0 + 8;
    const __half* kb0 = base + DMODEL + h * 64;
    const __half* vb0 = base + 2 * DMODEL + h * 64;

    kv_issue(sb, 0, kb0, vb0, tid);
    cp_commit();

    for (int t = 0; t < 16; t++) {
        if (t + 1 < 16) {
            kv_issue(sb, (t + 1) & 1, kb0 + (size_t)((t + 1) * 64) * 3072,
                     vb0 + (size_t)((t + 1) * 64) * 3072, tid);
        }
        cp_commit();
        cp_wait<1>();
        __syncthreads();

        const uint32_t sk = sb + (t & 1) * AKV;
        const uint32_t sv = sk + 8192;

        // S = Q K^T (16 x 64 per warp)
        float S[8][4];
        #pragma unroll
        for (int nt = 0; nt < 8; nt++)
            #pragma unroll
            for (int c = 0; c < 4; c++) S[nt][c] = 0.f;
        #pragma unroll
        for (int ks = 0; ks < 4; ks++) {
            const int gr = 2 * ks + (lane >> 4);
            uint32_t bf[8][2];
            #pragma unroll
            for (int np = 0; np < 4; np++) {
                const int row = np * 16 + (lane & 15);
                uint32_t q[4];
                ldsm_x4(q, sk + row * 128 + ((gr ^ (row & 7)) * 16));
                bf[2 * np][0] = q[0]; bf[2 * np + 1][0] = q[1];
                bf[2 * np][1] = q[2]; bf[2 * np + 1][1] = q[3];
            }
            #pragma unroll
            for (int nt = 0; nt < 8; nt++)
                mma_f16(S[nt], aQ[ks], bf[nt]);
        }

        // ALiBi + online softmax
        float mx0 = -1e30f, mx1 = -1e30f;
        #pragma unroll
        for (int nt = 0; nt < 8; nt++) {
            const int kc = t * 64 + nt * 8 + 2 * th;
            S[nt][0] = S[nt][0] * 0.125f - slope * fabsf((float)(q0 - kc));
            S[nt][1] = S[nt][1] * 0.125f - slope * fabsf((float)(q0 - kc - 1));
            S[nt][2] = S[nt][2] * 0.125f - slope * fabsf((float)(q1 - kc));
            S[nt][3] = S[nt][3] * 0.125f - slope * fabsf((float)(q1 - kc - 1));
            mx0 = fmaxf(mx0, fmaxf(S[nt][0], S[nt][1]));
            mx1 = fmaxf(mx1, fmaxf(S[nt][2], S[nt][3]));
        }
        #pragma unroll
        for (int off = 1; off <= 2; off <<= 1) {
            mx0 = fmaxf(mx0, __shfl_xor_sync(0xffffffffu, mx0, off));
            mx1 = fmaxf(mx1, __shfl_xor_sync(0xffffffffu, mx1, off));
        }
        const float mn0 = fmaxf(m0, mx0), mn1 = fmaxf(m1, mx1);
        const float sc0 = __expf(m0 - mn0), sc1 = __expf(m1 - mn1);
        float s0 = 0.f, s1 = 0.f;
        #pragma unroll
        for (int nt = 0; nt < 8; nt++) {
            const float p00 = __expf(S[nt][0] - mn0);
            const float p01 = __expf(S[nt][1] - mn0);
            const float p10 = __expf(S[nt][2] - mn1);
            const float p11 = __expf(S[nt][3] - mn1);
            s0 += p00 + p01; s1 += p10 + p11;
            sts32(wp + g * 128 + ((nt ^ (g & 7)) * 16) + th * 4,
                  pack_h2(p00, p01));
            sts32(wp + (g + 8) * 128 + ((nt ^ ((g + 8) & 7)) * 16) + th * 4,
                  pack_h2(p10, p11));
        }
        #pragma unroll
        for (int off = 1; off <= 2; off <<= 1) {
            s0 += __shfl_xor_sync(0xffffffffu, s0, off);
            s1 += __shfl_xor_sync(0xffffffffu, s1, off);
        }
        l0 = l0 * sc0 + s0; l1 = l1 * sc1 + s1;
        m0 = mn0; m1 = mn1;
        #pragma unroll
        for (int nt = 0; nt < 8; nt++) {
            O[nt][0] *= sc0; O[nt][1] *= sc0;
            O[nt][2] *= sc1; O[nt][3] *= sc1;
        }
        __syncwarp();

        // O += P V  (A = P from warp smem; B = V via ldmatrix.trans)
        #pragma unroll
        for (int ks = 0; ks < 4; ks++) {
            uint32_t aP[4];
            {
                const int row = lane & 15;
                const int gr = 2 * ks + (lane >> 4);
                ldsm_x4(aP, wp + row * 128 + ((gr ^ (row & 7)) * 16));
            }
            #pragma unroll
            for (int np = 0; np < 4; np++) {
                const int row = ks * 16 + (lane & 15);       // kv row
                const int gr = np * 2 + (lane >> 4);         // hd chunk
                uint32_t q[4], bf0[2], bf1[2];
                ldsm_x4t(q, sv + row * 128 + ((gr ^ (row & 7)) * 16));
                bf0[0] = q[0]; bf0[1] = q[1];                // hd np*16+0..7
                bf1[0] = q[2]; bf1[1] = q[3];                // hd np*16+8..15
                mma_f16(O[2 * np],     aP, bf0);
                mma_f16(O[2 * np + 1], aP, bf1);
            }
        }
        __syncthreads();
    }

    const float i0 = 1.f / l0, i1 = 1.f / l1;
    #pragma unroll
    for (int nt = 0; nt < 8; nt++) {
        const int n = h * 64 + nt * 8 + 2 * th;
        *(uint32_t*)&out[(size_t)(b * SEQ + q0) * DMODEL + n] =
            pack_h2(O[nt][0] * i0, O[nt][1] * i0);
        *(uint32_t*)&out[(size_t)(b * SEQ + q1) * DMODEL + n] =
            pack_h2(O[nt][2] * i1, O[nt][3] * i1);
    }
}

// ---------------- LayerNorm (fp16 output) -----------------------------------
__global__ __launch_bounds__(256) void ln_kernel(
    const float* __restrict__ x, const float* __restrict__ g,
    const float* __restrict__ b, __half* __restrict__ y)
{
    __shared__ float redS[8];
    __shared__ float redQ[8];
    const int row = blockIdx.x;
    const int tid = threadIdx.x;

    const float4 v = ((const float4*)(x + (size_t)row * DMODEL))[tid];
    float s = v.x + v.y + v.z + v.w;
    float q = v.x*v.x + v.y*v.y + v.z*v.z + v.w*v.w;
    #pragma unroll
    for (int off = 16; off >= 1; off >>= 1) {
        s += __shfl_xor_sync(0xffffffffu, s, off);
        q += __shfl_xor_sync(0xffffffffu, q, off);
    }
    if ((tid & 31) == 0) { redS[tid >> 5] = s; redQ[tid >> 5] = q; }
    __syncthreads();
    if (tid < 32) {
        s = (tid < 8) ? redS[tid] : 0.f;
        q = (tid < 8) ? redQ[tid] : 0.f;
        #pragma unroll
        for (int off = 4; off >= 1; off >>= 1) {
            s += __shfl_xor_sync(0xffffffffu, s, off);
            q += __shfl_xor_sync(0xffffffffu, q, off);
        }
        if (tid == 0) { redS[0] = s; redQ[0] = q; }
    }
    __syncthreads();
    const float mu  = redS[0] * (1.f / DMODEL);
    const float var = redQ[0] * (1.f / DMODEL) - mu * mu;
    const float rstd = rsqrtf(var + 1e-5f);

    const float4 gv = ((const float4*)g)[tid];
    const float4 bv = ((const float4*)b)[tid];
    uint32_t o0 = pack_h2((v.x - mu) * rstd * gv.x + bv.x,
                          (v.y - mu) * rstd * gv.y + bv.y);
    uint32_t o1 = pack_h2((v.z - mu) * rstd * gv.z + bv.z,
                          (v.w - mu) * rstd * gv.w + bv.w);
    uint2* yo = (uint2*)(y + (size_t)row * DMODEL);
    yo[tid] = make_uint2(o0, o1);
}

// ---------------- launch -----------------------------------------------------
extern "C" void kernel_launch(void* const* d_in, const int* in_sizes, int n_in,
                              void* d_out, int out_size)
{
    const float* src    = (const float*)d_in[0];
    const float* wqkv   = (const float*)d_in[1];
    const float* bqkv   = (const float*)d_in[2];
    const float* wo     = (const float*)d_in[3];
    const float* bo     = (const float*)d_in[4];
    const float* g1     = (const float*)d_in[5];
    const float* b1     = (const float*)d_in[6];
    const float* g2     = (const float*)d_in[7];
    const float* b2     = (const float*)d_in[8];
    const float* w_gate = (const float*)d_in[9];
    const float* b_gate = (const float*)d_in[10];
    const float* w_up   = (const float*)d_in[11];
    const float* b_up   = (const float*)d_in[12];
    const float* w_down = (const float*)d_in[13];
    const float* b_down = (const float*)d_in[14];
    float* out = (float*)d_out;

    __half *lnh, *qkvh, *atth, *hh, *wh;
    float  *x1;
    cudaGetSymbolAddress((void**)&lnh,  g_lnh);
    cudaGetSymbolAddress((void**)&qkvh, g_qkvh);
    cudaGetSymbolAddress((void**)&atth, g_atth);
    cudaGetSymbolAddress((void**)&hh,   g_hh);
    cudaGetSymbolAddress((void**)&wh,   g_wh);
    cudaGetSymbolAddress((void**)&x1,   g_x1);

    cudaFuncSetAttribute(gemm_h<0, 1>,
        cudaFuncAttributeMaxDynamicSharedMemorySize, GSMEM);
    cudaFuncSetAttribute(gemm_h<1, 0>,
        cudaFuncAttributeMaxDynamicSharedMemorySize, GSMEM);
    cudaFuncSetAttribute(gemm_glu,
        cudaFuncAttributeMaxDynamicSharedMemorySize, USMEM);
    cudaFuncSetAttribute(attn_mma,
        cudaFuncAttributeMaxDynamicSharedMemorySize, ATT_SMEM);

    // weights fp32 -> fp16
    cvt_w<<<3072, 256>>>((const float4*)wqkv,   (__half2*)(wh + W_QKV), 786432);
    cvt_w<<<1024, 256>>>((const float4*)wo,     (__half2*)(wh + W_O),   262144);
    cvt_w<<<4096, 256>>>((const float4*)w_gate, (__half2*)(wh + W_G),  1048576);
    cvt_w<<<4096, 256>>>((const float4*)w_up,   (__half2*)(wh + W_U),  1048576);
    cvt_w<<<4096, 256>>>((const float4*)w_down, (__half2*)(wh + W_D),  1048576);

    // x = src + Attn(LN1(src))
    ln_kernel<<<MTOT, 256>>>(src, g1, b1, lnh);
    gemm_h<0, 1><<<dim3(64, 12), 512, GSMEM>>>(lnh, wh + W_QKV, bqkv, nullptr,
                                               qkvh, 3 * DMODEL, DMODEL);
    attn_mma<<<dim3(8, NHEAD, BATCH), 256, ATT_SMEM>>>(qkvh, atth);
    gemm_h<1, 0><<<dim3(64, 4), 512, GSMEM>>>(atth, wh + W_O, bo, src,
                                              x1, DMODEL, DMODEL);

    // x = x + SwiGLU(LN2(x))
    ln_kernel<<<MTOT, 256>>>(x1, g2, b2, lnh);
    gemm_glu<<<dim3(64, 32), 512, USMEM>>>(lnh, wh + W_G, wh + W_U,
                                           b_gate, b_up, hh);
    gemm_h<1, 0><<<dim3(64, 4), 512, GSMEM>>>(hh, wh + W_D, b_down, x1,
                                              out, DMODEL, DFFN);
}

// round 13
// speedup vs baseline: 6.9123x; 1.0353x over previous
#include <cuda_runtime.h>
#include <cuda_fp16.h>
#include <math.h>
#include <stdint.h>

#define MTOT   8192
#define DMODEL 1024
#define DFFN   4096
#define NHEAD  16
#define HDIM   64
#define SEQ    1024
#define BATCH  8

// ---------------- scratch (device globals; no allocations) ----------------
__device__ __half g_wh[16 * 1024 * 1024];      // fp16 weights (32 MB)
__device__ __half g_lnh[MTOT * DMODEL];        // fp16 LN output
__device__ __half g_qkvh[MTOT * 3 * DMODEL];   // fp16 qkv
__device__ __half g_atth[MTOT * DMODEL];       // fp16 attention output
__device__ __half g_hh[MTOT * DFFN];           // fp16 silu(gate)*up
__device__ float  g_x1[MTOT * DMODEL];         // fp32 residual stream

#define W_QKV  0
#define W_O    (3 * 1024 * 1024)
#define W_G    (4 * 1024 * 1024)
#define W_U    (8 * 1024 * 1024)
#define W_D    (12 * 1024 * 1024)

// ---------------- PTX helpers ---------------------------------------------
__device__ __forceinline__ uint32_t smem_u32(const void* p) {
    uint32_t a;
    asm("{ .reg .u64 t; cvta.to.shared.u64 t, %1; cvt.u32.u64 %0, t; }"
        : "=r"(a) : "l"(p));
    return a;
}
__device__ __forceinline__ void cp16(uint32_t dst, const void* src) {
    asm volatile("cp.async.cg.shared.global [%0], [%1], 16;"
                 :: "r"(dst), "l"(src) : "memory");
}
__device__ __forceinline__ void cp_commit() {
    asm volatile("cp.async.commit_group;" ::: "memory");
}
template <int N>
__device__ __forceinline__ void cp_wait() {
    asm volatile("cp.async.wait_group %0;" :: "n"(N) : "memory");
}
__device__ __forceinline__ void sts32(uint32_t addr, uint32_t val) {
    asm volatile("st.shared.b32 [%0], %1;" :: "r"(addr), "r"(val) : "memory");
}
__device__ __forceinline__ void ldsm_x4(uint32_t r[4], uint32_t addr) {
    asm volatile("ldmatrix.sync.aligned.m8n8.x4.shared.b16 {%0,%1,%2,%3}, [%4];"
        : "=r"(r[0]), "=r"(r[1]), "=r"(r[2]), "=r"(r[3]) : "r"(addr));
}
__device__ __forceinline__ void ldsm_x4t(uint32_t r[4], uint32_t addr) {
    asm volatile("ldmatrix.sync.aligned.m8n8.x4.trans.shared.b16 {%0,%1,%2,%3}, [%4];"
        : "=r"(r[0]), "=r"(r[1]), "=r"(r[2]), "=r"(r[3]) : "r"(addr));
}
__device__ __forceinline__ void mma_f16(float c[4], const uint32_t a[4],
                                        const uint32_t b[2]) {
    asm volatile(
        "mma.sync.aligned.m16n8k16.row.col.f32.f16.f16.f32 "
        "{%0,%1,%2,%3}, {%4,%5,%6,%7}, {%8,%9}, {%0,%1,%2,%3};\n"
        : "+f"(c[0]), "+f"(c[1]), "+f"(c[2]), "+f"(c[3])
        : "r"(a[0]), "r"(a[1]), "r"(a[2]), "r"(a[3]), "r"(b[0]), "r"(b[1]));
}
__device__ __forceinline__ uint32_t pack_h2(float a, float b) {
    __half2 h = __floats2half2_rn(a, b);
    return *reinterpret_cast<uint32_t*>(&h);
}

// ---------------- weight fp32 -> fp16 --------------------------------------
__global__ __launch_bounds__(256) void cvt_w(
    const float4* __restrict__ in, __half2* __restrict__ out, int n4)
{
    const int i = blockIdx.x * 256 + threadIdx.x;
    if (i < n4) {
        float4 v = in[i];
        out[2 * i]     = __floats2half2_rn(v.x, v.y);
        out[2 * i + 1] = __floats2half2_rn(v.z, v.w);
    }
}

// ---------------- FP16 mma.sync NT GEMM ------------------------------------
// C[M, Ntot] = A[M, K] * W[Ntot, K]^T + bias. CTA 128x256, 512 threads
// (16 warps, 2x8), warp tile 64x32. K-chunk 64, 4-stage ring, ONE barrier
// per chunk (issue targets the slot consumed last iteration).
// EPI 0: +bias | 1: +bias+aux(fp32). OUT16: write fp16 else fp32.
#define GSTG_BYTES 49152     // A 16KB + B 32KB
#define GSMEM (4 * GSTG_BYTES)

__device__ __forceinline__ void g_issue(
    uint32_t sbase, int slot, const __half* A, const __half* W,
    int bm, int bn, int K, int k0, int tid)
{
    const uint32_t sb = sbase + slot * GSTG_BYTES;
    #pragma unroll
    for (int i = 0; i < 6; i++) {
        const int gi = tid + i * 512;
        if (gi < 1024) {
            const int r = gi >> 3, c = gi & 7;
            cp16(sb + r * 128 + ((c ^ (r & 7)) * 16),
                 A + (size_t)(bm + r) * K + k0 + c * 8);
        } else {
            const int j = gi - 1024;
            const int r = j >> 3, c = j & 7;
            cp16(sb + 16384 + r * 128 + ((c ^ (r & 7)) * 16),
                 W + (size_t)(bn + r) * K + k0 + c * 8);
        }
    }
}

template <int EPI, int OUT16>
__global__ __launch_bounds__(512, 1) void gemm_h(
    const __half* __restrict__ A, const __half* __restrict__ W,
    const float* __restrict__ bias, const float* __restrict__ aux,
    void* __restrict__ Cv, int Ntot, int K)
{
    extern __shared__ float gsm[];
    const uint32_t sbase = smem_u32(gsm);
    const int tid = threadIdx.x, wid = tid >> 5, lane = tid & 31;
    const int g = lane >> 2, th = lane & 3;
    const int bm = blockIdx.x * 128, bn = blockIdx.y * 256;
    const int wm = (wid & 1) * 64, wn = (wid >> 1) * 32;

    float acc[4][4][4];
    #pragma unroll
    for (int mt = 0; mt < 4; mt++)
        #pragma unroll
        for (int nt = 0; nt < 4; nt++)
            #pragma unroll
            for (int c = 0; c < 4; c++) acc[mt][nt][c] = 0.f;

    const int NT = K >> 6;
    #pragma unroll
    for (int t = 0; t < 3; t++) {
        if (t < NT) g_issue(sbase, t, A, W, bm, bn, K, t * 64, tid);
        cp_commit();
    }

    for (int t = 0; t < NT; t++) {
        cp_wait<2>();
        __syncthreads();
        if (t + 3 < NT) g_issue(sbase, (t + 3) & 3, A, W, bm, bn, K,
                                (t + 3) * 64, tid);
        cp_commit();

        const uint32_t sa = sbase + (t & 3) * GSTG_BYTES;
        const uint32_t sbB = sa + 16384;

        #pragma unroll
        for (int ks = 0; ks < 4; ks++) {
            const int gr = 2 * ks + (lane >> 4);
            uint32_t af[4][4], bf[4][2];
            #pragma unroll
            for (int mt = 0; mt < 4; mt++) {
                const int row = wm + mt * 16 + (lane & 15);
                ldsm_x4(af[mt], sa + row * 128 + ((gr ^ (row & 7)) * 16));
            }
            #pragma unroll
            for (int np = 0; np < 2; np++) {
                const int row = wn + np * 16 + (lane & 15);
                uint32_t q[4];
                ldsm_x4(q, sbB + row * 128 + ((gr ^ (row & 7)) * 16));
                bf[2 * np][0] = q[0]; bf[2 * np + 1][0] = q[1];
                bf[2 * np][1] = q[2]; bf[2 * np + 1][1] = q[3];
            }
            #pragma unroll
            for (int mt = 0; mt < 4; mt++)
                #pragma unroll
                for (int nt = 0; nt < 4; nt++)
                    mma_f16(acc[mt][nt], af[mt], bf[nt]);
        }
    }

    #pragma unroll
    for (int mt = 0; mt < 4; mt++) {
        const int m0 = bm + wm + mt * 16 + g;
        #pragma unroll
        for (int nt = 0; nt < 4; nt++) {
            const int n = bn + wn + nt * 8 + 2 * th;
            const float b0 = bias[n], b1 = bias[n + 1];
            float v00 = acc[mt][nt][0] + b0, v01 = acc[mt][nt][1] + b1;
            float v10 = acc[mt][nt][2] + b0, v11 = acc[mt][nt][3] + b1;
            if (EPI == 1) {
                const float2 x0 = *(const float2*)&aux[(size_t)m0 * Ntot + n];
                const float2 x1 = *(const float2*)&aux[(size_t)(m0 + 8) * Ntot + n];
                v00 += x0.x; v01 += x0.y; v10 += x1.x; v11 += x1.y;
            }
            if (OUT16) {
                __half* C = (__half*)Cv;
                *(uint32_t*)&C[(size_t)m0 * Ntot + n]       = pack_h2(v00, v01);
                *(uint32_t*)&C[(size_t)(m0 + 8) * Ntot + n] = pack_h2(v10, v11);
            } else {
                float* C = (float*)Cv;
                *(float2*)&C[(size_t)m0 * Ntot + n]       = make_float2(v00, v01);
                *(float2*)&C[(size_t)(m0 + 8) * Ntot + n] = make_float2(v10, v11);
            }
        }
    }
}

// ---------------- Fused SwiGLU GEMM (fp16) ----------------------------------
// H = silu(A Wg^T + bg) * (A Wu^T + bu). CTA 128x128, 512 threads (16 warps,
// 2x8), warp tile 64x16, dual accumulators, K-chunk 64, 4-stage ring.
#define USTG_BYTES 49152     // A 16KB + Wg 16KB + Wu 16KB
#define USMEM (4 * USTG_BYTES)

__device__ __forceinline__ void u_issue(
    uint32_t sbase, int slot, const __half* A, const __half* Wg,
    const __half* Wu, int bm, int bn, int k0, int tid)
{
    const uint32_t sb = sbase + slot * USTG_BYTES;
    #pragma unroll
    for (int i = 0; i < 6; i++) {
        const int gi = tid + i * 512;
        const int r = (gi & 1023) >> 3, c = gi & 7;
        const uint32_t dst = r * 128 + ((c ^ (r & 7)) * 16);
        if (gi < 1024)
            cp16(sb + dst, A + (size_t)(bm + r) * DMODEL + k0 + c * 8);
        else if (gi < 2048)
            cp16(sb + 16384 + dst, Wg + (size_t)(bn + r) * DMODEL + k0 + c * 8);
        else
            cp16(sb + 32768 + dst, Wu + (size_t)(bn + r) * DMODEL + k0 + c * 8);
    }
}

__global__ __launch_bounds__(512, 1) void gemm_glu(
    const __half* __restrict__ A, const __half* __restrict__ Wg,
    const __half* __restrict__ Wu, const float* __restrict__ bg,
    const float* __restrict__ bu, __half* __restrict__ H)
{
    extern __shared__ float usm[];
    const uint32_t sbase = smem_u32(usm);
    const int tid = threadIdx.x, wid = tid >> 5, lane = tid & 31;
    const int g = lane >> 2, th = lane & 3;
    const int bm = blockIdx.x * 128, bn = blockIdx.y * 128;
    const int wm = (wid & 1) * 64, wn = (wid >> 1) * 16;

    float accG[4][2][4], accU[4][2][4];
    #pragma unroll
    for (int mt = 0; mt < 4; mt++)
        #pragma unroll
        for (int nt = 0; nt < 2; nt++)
            #pragma unroll
            for (int c = 0; c < 4; c++) { accG[mt][nt][c] = 0.f; accU[mt][nt][c] = 0.f; }

    const int NT = DMODEL >> 6;   // 16
    #pragma unroll
    for (int t = 0; t < 3; t++) {
        u_issue(sbase, t, A, Wg, Wu, bm, bn, t * 64, tid);
        cp_commit();
    }

    for (int t = 0; t < NT; t++) {
        cp_wait<2>();
        __syncthreads();
        if (t + 3 < NT) u_issue(sbase, (t + 3) & 3, A, Wg, Wu, bm, bn,
                                (t + 3) * 64, tid);
        cp_commit();

        const uint32_t sa = sbase + (t & 3) * USTG_BYTES;

        #pragma unroll
        for (int ks = 0; ks < 4; ks++) {
            const int gr = 2 * ks + (lane >> 4);
            uint32_t af[4][4], bG[2][2], bU[2][2];
            #pragma unroll
            for (int mt = 0; mt < 4; mt++) {
                const int row = wm + mt * 16 + (lane & 15);
                ldsm_x4(af[mt], sa + row * 128 + ((gr ^ (row & 7)) * 16));
            }
            {
                const int row = wn + (lane & 15);
                const uint32_t off = row * 128 + ((gr ^ (row & 7)) * 16);
                uint32_t q[4];
                ldsm_x4(q, sa + 16384 + off);
                bG[0][0] = q[0]; bG[1][0] = q[1];
                bG[0][1] = q[2]; bG[1][1] = q[3];
                ldsm_x4(q, sa + 32768 + off);
                bU[0][0] = q[0]; bU[1][0] = q[1];
                bU[0][1] = q[2]; bU[1][1] = q[3];
            }
            #pragma unroll
            for (int mt = 0; mt < 4; mt++)
                #pragma unroll
                for (int nt = 0; nt < 2; nt++) {
                    mma_f16(accG[mt][nt], af[mt], bG[nt]);
                    mma_f16(accU[mt][nt], af[mt], bU[nt]);
                }
        }
    }

    #pragma unroll
    for (int mt = 0; mt < 4; mt++) {
        const int m0 = bm + wm + mt * 16 + g;
        #pragma unroll
        for (int nt = 0; nt < 2; nt++) {
            const int n = bn + wn + nt * 8 + 2 * th;
            const float bg0 = bg[n], bg1 = bg[n + 1];
            const float bu0 = bu[n], bu1 = bu[n + 1];
            #pragma unroll
            for (int r = 0; r < 2; r++) {
                const float ga = accG[mt][nt][2 * r]     + bg0;
                const float gb = accG[mt][nt][2 * r + 1] + bg1;
                const float ua = accU[mt][nt][2 * r]     + bu0;
                const float ub = accU[mt][nt][2 * r + 1] + bu1;
                const float ha = ua * ga / (1.f + __expf(-ga));
                const float hb = ub * gb / (1.f + __expf(-gb));
                *(uint32_t*)&H[(size_t)(m0 + 8 * r) * DFFN + n] = pack_h2(ha, hb);
            }
        }
    }
}

// ---------------- Flash attention (fp16 mma, ALiBi) -------------------------
// 256 threads (8 warps), q-tile 128 (16 rows/warp), kv tiles 64, double-buffer.
#define AKV   16384
#define APQ   32768
#define ATT_SMEM (32768 + 16384)

__device__ __forceinline__ void kv_issue(
    uint32_t sb, int slot, const __half* kb, const __half* vb, int tid)
{
    const uint32_t kb0 = sb + slot * AKV;
    const uint32_t vb0 = kb0 + 8192;
    #pragma unroll
    for (int i = 0; i < 4; i++) {
        const int gi = tid + i * 256;
        if (gi < 512) {
            const int r = gi >> 3, c = gi & 7;
            cp16(kb0 + r * 128 + ((c ^ (r & 7)) * 16),
                 kb + (size_t)r * 3072 + c * 8);
        } else {
            const int r2 = (gi - 512) >> 3, c2 = gi & 7;
            cp16(vb0 + r2 * 128 + ((c2 ^ (r2 & 7)) * 16),
                 vb + (size_t)r2 * 3072 + c2 * 8);
        }
    }
}

__global__ __launch_bounds__(256) void attn_mma(
    const __half* __restrict__ qkv, __half* __restrict__ out)
{
    extern __shared__ float smf[];
    const uint32_t sb = smem_u32(smf);
    const int tid = threadIdx.x, wid = tid >> 5, lane = tid & 31;
    const int g = lane >> 2, th = lane & 3;
    const int bq = blockIdx.x, h = blockIdx.y, b = blockIdx.z;
    const float slope = exp2f(-0.5f * (float)(h + 1));

    const __half* base = qkv + (size_t)b * SEQ * 3072;

    {
        const __half* qb = base + (size_t)(bq * 128) * 3072 + h * 64;
        #pragma unroll
        for (int i = 0; i < 4; i++) {
            const int gi = tid + i * 256;
            const int r = gi >> 3, c = gi & 7;
            cp16(sb + APQ + r * 128 + ((c ^ (r & 7)) * 16),
                 qb + (size_t)r * 3072 + c * 8);
        }
        cp_commit();
        cp_wait<0>();
        __syncthreads();
    }

    uint32_t aQ[4][4];
    #pragma unroll
    for (int ks = 0; ks < 4; ks++) {
        const int row = wid * 16 + (lane & 15);
        const int gr = 2 * ks + (lane >> 4);
        ldsm_x4(aQ[ks], sb + APQ + row * 128 + ((gr ^ (row & 7)) * 16));
    }
    __syncthreads();

    const uint32_t wp = sb + APQ + wid * 2048;
    float m0 = -1e30f, m1 = -1e30f, l0 = 0.f, l1 = 0.f;
    float O[8][4];
    #pragma unroll
    for (int nt = 0; nt < 8; nt++)
        #pragma unroll
        for (int c = 0; c < 4; c++) O[nt][c] = 0.f;

    const int q0 = bq * 128 + wid * 16 + g;
    const int q1 = q0 + 8;
    const __half* kb0 = base + DMODEL + h * 64;
    const __half* vb0 = base + 2 * DMODEL + h * 64;

    kv_issue(sb, 0, kb0, vb0, tid);
    cp_commit();

    for (int t = 0; t < 16; t++) {
        if (t + 1 < 16) {
            kv_issue(sb, (t + 1) & 1, kb0 + (size_t)((t + 1) * 64) * 3072,
                     vb0 + (size_t)((t + 1) * 64) * 3072, tid);
        }
        cp_commit();
        cp_wait<1>();
        __syncthreads();

        const uint32_t sk = sb + (t & 1) * AKV;
        const uint32_t sv = sk + 8192;

        float S[8][4];
        #pragma unroll
        for (int nt = 0; nt < 8; nt++)
            #pragma unroll
            for (int c = 0; c < 4; c++) S[nt][c] = 0.f;
        #pragma unroll
        for (int ks = 0; ks < 4; ks++) {
            const int gr = 2 * ks + (lane >> 4);
            uint32_t bf[8][2];
            #pragma unroll
            for (int np = 0; np < 4; np++) {
                const int row = np * 16 + (lane & 15);
                uint32_t q[4];
                ldsm_x4(q, sk + row * 128 + ((gr ^ (row & 7)) * 16));
                bf[2 * np][0] = q[0]; bf[2 * np + 1][0] = q[1];
                bf[2 * np][1] = q[2]; bf[2 * np + 1][1] = q[3];
            }
            #pragma unroll
            for (int nt = 0; nt < 8; nt++)
                mma_f16(S[nt], aQ[ks], bf[nt]);
        }

        float mx0 = -1e30f, mx1 = -1e30f;
        #pragma unroll
        for (int nt = 0; nt < 8; nt++) {
            const int kc = t * 64 + nt * 8 + 2 * th;
            S[nt][0] = S[nt][0] * 0.125f - slope * fabsf((float)(q0 - kc));
            S[nt][1] = S[nt][1] * 0.125f - slope * fabsf((float)(q0 - kc - 1));
            S[nt][2] = S[nt][2] * 0.125f - slope * fabsf((float)(q1 - kc));
            S[nt][3] = S[nt][3] * 0.125f - slope * fabsf((float)(q1 - kc - 1));
            mx0 = fmaxf(mx0, fmaxf(S[nt][0], S[nt][1]));
            mx1 = fmaxf(mx1, fmaxf(S[nt][2], S[nt][3]));
        }
        #pragma unroll
        for (int off = 1; off <= 2; off <<= 1) {
            mx0 = fmaxf(mx0, __shfl_xor_sync(0xffffffffu, mx0, off));
            mx1 = fmaxf(mx1, __shfl_xor_sync(0xffffffffu, mx1, off));
        }
        const float mn0 = fmaxf(m0, mx0), mn1 = fmaxf(m1, mx1);
        const float sc0 = __expf(m0 - mn0), sc1 = __expf(m1 - mn1);
        float s0 = 0.f, s1 = 0.f;
        #pragma unroll
        for (int nt = 0; nt < 8; nt++) {
            const float p00 = __expf(S[nt][0] - mn0);
            const float p01 = __expf(S[nt][1] - mn0);
            const float p10 = __expf(S[nt][2] - mn1);
            const float p11 = __expf(S[nt][3] - mn1);
            s0 += p00 + p01; s1 += p10 + p11;
            sts32(wp + g * 128 + ((nt ^ (g & 7)) * 16) + th * 4,
                  pack_h2(p00, p01));
            sts32(wp + (g + 8) * 128 + ((nt ^ ((g + 8) & 7)) * 16) + th * 4,
                  pack_h2(p10, p11));
        }
        #pragma unroll
        for (int off = 1; off <= 2; off <<= 1) {
            s0 += __shfl_xor_sync(0xffffffffu, s0, off);
            s1 += __shfl_xor_sync(0xffffffffu, s1, off);
        }
        l0 = l0 * sc0 + s0; l1 = l1 * sc1 + s1;
        m0 = mn0; m1 = mn1;
        #pragma unroll
        for (int nt = 0; nt < 8; nt++) {
            O[nt][0] *= sc0; O[nt][1] *= sc0;
            O[nt][2] *= sc1; O[nt][3] *= sc1;
        }
        __syncwarp();

        #pragma unroll
        for (int ks = 0; ks < 4; ks++) {
            uint32_t aP[4];
            {
                const int row = lane & 15;
                const int gr = 2 * ks + (lane >> 4);
                ldsm_x4(aP, wp + row * 128 + ((gr ^ (row & 7)) * 16));
            }
            #pragma unroll
            for (int np = 0; np < 4; np++) {
                const int row = ks * 16 + (lane & 15);
                const int gr = np * 2 + (lane >> 4);
                uint32_t q[4], bf0[2], bf1[2];
                ldsm_x4t(q, sv + row * 128 + ((gr ^ (row & 7)) * 16));
                bf0[0] = q[0]; bf0[1] = q[1];
                bf1[0] = q[2]; bf1[1] = q[3];
                mma_f16(O[2 * np],     aP, bf0);
                mma_f16(O[2 * np + 1], aP, bf1);
            }
        }
        __syncthreads();
    }

    const float i0 = 1.f / l0, i1 = 1.f / l1;
    #pragma unroll
    for (int nt = 0; nt < 8; nt++) {
        const int n = h * 64 + nt * 8 + 2 * th;
        *(uint32_t*)&out[(size_t)(b * SEQ + q0) * DMODEL + n] =
            pack_h2(O[nt][0] * i0, O[nt][1] * i0);
        *(uint32_t*)&out[(size_t)(b * SEQ + q1) * DMODEL + n] =
            pack_h2(O[nt][2] * i1, O[nt][3] * i1);
    }
}

// ---------------- LayerNorm (fp16 output) -----------------------------------
__global__ __launch_bounds__(256) void ln_kernel(
    const float* __restrict__ x, const float* __restrict__ g,
    const float* __restrict__ b, __half* __restrict__ y)
{
    __shared__ float redS[8];
    __shared__ float redQ[8];
    const int row = blockIdx.x;
    const int tid = threadIdx.x;

    const float4 v = ((const float4*)(x + (size_t)row * DMODEL))[tid];
    float s = v.x + v.y + v.z + v.w;
    float q = v.x*v.x + v.y*v.y + v.z*v.z + v.w*v.w;
    #pragma unroll
    for (int off = 16; off >= 1; off >>= 1) {
        s += __shfl_xor_sync(0xffffffffu, s, off);
        q += __shfl_xor_sync(0xffffffffu, q, off);
    }
    if ((tid & 31) == 0) { redS[tid >> 5] = s; redQ[tid >> 5] = q; }
    __syncthreads();
    if (tid < 32) {
        s = (tid < 8) ? redS[tid] : 0.f;
        q = (tid < 8) ? redQ[tid] : 0.f;
        #pragma unroll
        for (int off = 4; off >= 1; off >>= 1) {
            s += __shfl_xor_sync(0xffffffffu, s, off);
            q += __shfl_xor_sync(0xffffffffu, q, off);
        }
        if (tid == 0) { redS[0] = s; redQ[0] = q; }
    }
    __syncthreads();
    const float mu  = redS[0] * (1.f / DMODEL);
    const float var = redQ[0] * (1.f / DMODEL) - mu * mu;
    const float rstd = rsqrtf(var + 1e-5f);

    const float4 gv = ((const float4*)g)[tid];
    const float4 bv = ((const float4*)b)[tid];
    uint32_t o0 = pack_h2((v.x - mu) * rstd * gv.x + bv.x,
                          (v.y - mu) * rstd * gv.y + bv.y);
    uint32_t o1 = pack_h2((v.z - mu) * rstd * gv.z + bv.z,
                          (v.w - mu) * rstd * gv.w + bv.w);
    uint2* yo = (uint2*)(y + (size_t)row * DMODEL);
    yo[tid] = make_uint2(o0, o1);
}

// ---------------- launch -----------------------------------------------------
extern "C" void kernel_launch(void* const* d_in, const int* in_sizes, int n_in,
                              void* d_out, int out_size)
{
    const float* src    = (const float*)d_in[0];
    const float* wqkv   = (const float*)d_in[1];
    const float* bqkv   = (const float*)d_in[2];
    const float* wo     = (const float*)d_in[3];
    const float* bo     = (const float*)d_in[4];
    const float* g1     = (const float*)d_in[5];
    const float* b1     = (const float*)d_in[6];
    const float* g2     = (const float*)d_in[7];
    const float* b2     = (const float*)d_in[8];
    const float* w_gate = (const float*)d_in[9];
    const float* b_gate = (const float*)d_in[10];
    const float* w_up   = (const float*)d_in[11];
    const float* b_up   = (const float*)d_in[12];
    const float* w_down = (const float*)d_in[13];
    const float* b_down = (const float*)d_in[14];
    float* out = (float*)d_out;

    __half *lnh, *qkvh, *atth, *hh, *wh;
    float  *x1;
    cudaGetSymbolAddress((void**)&lnh,  g_lnh);
    cudaGetSymbolAddress((void**)&qkvh, g_qkvh);
    cudaGetSymbolAddress((void**)&atth, g_atth);
    cudaGetSymbolAddress((void**)&hh,   g_hh);
    cudaGetSymbolAddress((void**)&wh,   g_wh);
    cudaGetSymbolAddress((void**)&x1,   g_x1);

    cudaFuncSetAttribute(gemm_h<0, 1>,
        cudaFuncAttributeMaxDynamicSharedMemorySize, GSMEM);
    cudaFuncSetAttribute(gemm_h<1, 0>,
        cudaFuncAttributeMaxDynamicSharedMemorySize, GSMEM);
    cudaFuncSetAttribute(gemm_glu,
        cudaFuncAttributeMaxDynamicSharedMemorySize, USMEM);
    cudaFuncSetAttribute(attn_mma,
        cudaFuncAttributeMaxDynamicSharedMemorySize, ATT_SMEM);

    // weights fp32 -> fp16
    cvt_w<<<3072, 256>>>((const float4*)wqkv,   (__half2*)(wh + W_QKV), 786432);
    cvt_w<<<1024, 256>>>((const float4*)wo,     (__half2*)(wh + W_O),   262144);
    cvt_w<<<4096, 256>>>((const float4*)w_gate, (__half2*)(wh + W_G),  1048576);
    cvt_w<<<4096, 256>>>((const float4*)w_up,   (__half2*)(wh + W_U),  1048576);
    cvt_w<<<4096, 256>>>((const float4*)w_down, (__half2*)(wh + W_D),  1048576);

    // x = src + Attn(LN1(src))
    ln_kernel<<<MTOT, 256>>>(src, g1, b1, lnh);
    gemm_h<0, 1><<<dim3(64, 12), 512, GSMEM>>>(lnh, wh + W_QKV, bqkv, nullptr,
                                               qkvh, 3 * DMODEL, DMODEL);
    attn_mma<<<dim3(8, NHEAD, BATCH), 256, ATT_SMEM>>>(qkvh, atth);
    gemm_h<1, 0><<<dim3(64, 4), 512, GSMEM>>>(atth, wh + W_O, bo, src,
                                              x1, DMODEL, DMODEL);

    // x = x + SwiGLU(LN2(x))
    ln_kernel<<<MTOT, 256>>>(x1, g2, b2, lnh);
    gemm_glu<<<dim3(64, 32), 512, USMEM>>>(lnh, wh + W_G, wh + W_U,
                                           b_gate, b_up, hh);
    gemm_h<1, 0><<<dim3(64, 4), 512, GSMEM>>>(hh, wh + W_D, b_down, x1,
                                              out, DMODEL, DFFN);
}

// round 16
// speedup vs baseline: 6.9529x; 1.0059x over previous
#include <cuda_runtime.h>
#include <cuda_fp16.h>
#include <math.h>
#include <stdint.h>

#define MTOT   8192
#define DMODEL 1024
#define DFFN   4096
#define NHEAD  16
#define HDIM   64
#define SEQ    1024
#define BATCH  8

// ---------------- scratch (device globals; no allocations) ----------------
__device__ __half g_wh[16 * 1024 * 1024];      // fp16 weights (32 MB)
__device__ __half g_lnh[MTOT * DMODEL];        // fp16 LN output
__device__ __half g_qkvh[MTOT * 3 * DMODEL];   // fp16 qkv
__device__ __half g_atth[MTOT * DMODEL];       // fp16 attention output
__device__ __half g_hh[MTOT * DFFN];           // fp16 silu(gate)*up
__device__ float  g_x1[MTOT * DMODEL];         // fp32 residual stream

#define W_QKV  0
#define W_O    (3 * 1024 * 1024)
#define W_G    (4 * 1024 * 1024)
#define W_U    (8 * 1024 * 1024)
#define W_D    (12 * 1024 * 1024)

// ---------------- PTX helpers ---------------------------------------------
__device__ __forceinline__ uint32_t smem_u32(const void* p) {
    uint32_t a;
    asm("{ .reg .u64 t; cvta.to.shared.u64 t, %1; cvt.u32.u64 %0, t; }"
        : "=r"(a) : "l"(p));
    return a;
}
__device__ __forceinline__ void cp16(uint32_t dst, const void* src) {
    asm volatile("cp.async.cg.shared.global [%0], [%1], 16;"
                 :: "r"(dst), "l"(src) : "memory");
}
__device__ __forceinline__ void cp_commit() {
    asm volatile("cp.async.commit_group;" ::: "memory");
}
template <int N>
__device__ __forceinline__ void cp_wait() {
    asm volatile("cp.async.wait_group %0;" :: "n"(N) : "memory");
}
__device__ __forceinline__ void sts32(uint32_t addr, uint32_t val) {
    asm volatile("st.shared.b32 [%0], %1;" :: "r"(addr), "r"(val) : "memory");
}
__device__ __forceinline__ void ldsm_x4(uint32_t r[4], uint32_t addr) {
    asm volatile("ldmatrix.sync.aligned.m8n8.x4.shared.b16 {%0,%1,%2,%3}, [%4];"
        : "=r"(r[0]), "=r"(r[1]), "=r"(r[2]), "=r"(r[3]) : "r"(addr));
}
__device__ __forceinline__ void ldsm_x4t(uint32_t r[4], uint32_t addr) {
    asm volatile("ldmatrix.sync.aligned.m8n8.x4.trans.shared.b16 {%0,%1,%2,%3}, [%4];"
        : "=r"(r[0]), "=r"(r[1]), "=r"(r[2]), "=r"(r[3]) : "r"(addr));
}
__device__ __forceinline__ void mma_f16(float c[4], const uint32_t a[4],
                                        const uint32_t b[2]) {
    asm volatile(
        "mma.sync.aligned.m16n8k16.row.col.f32.f16.f16.f32 "
        "{%0,%1,%2,%3}, {%4,%5,%6,%7}, {%8,%9}, {%0,%1,%2,%3};\n"
        : "+f"(c[0]), "+f"(c[1]), "+f"(c[2]), "+f"(c[3])
        : "r"(a[0]), "r"(a[1]), "r"(a[2]), "r"(a[3]), "r"(b[0]), "r"(b[1]));
}
__device__ __forceinline__ uint32_t pack_h2(float a, float b) {
    __half2 h = __floats2half2_rn(a, b);
    return *reinterpret_cast<uint32_t*>(&h);
}

// ---------------- all-weights fp32 -> fp16 (single kernel) ------------------
// float4 index ranges: qkv [0,786432) | wo [..,1048576) | wg [..,2097152)
// | wu [..,3145728) | wd [..,4194304)
__global__ __launch_bounds__(256) void cvt_all(
    const float4* __restrict__ wqkv, const float4* __restrict__ wo,
    const float4* __restrict__ wg,   const float4* __restrict__ wu,
    const float4* __restrict__ wd,   __half* __restrict__ wh)
{
    const int i = blockIdx.x * 256 + threadIdx.x;
    const float4* src;
    int rel, base;
    if (i < 786432)       { src = wqkv; rel = i;           base = W_QKV; }
    else if (i < 1048576) { src = wo;   rel = i - 786432;  base = W_O;   }
    else if (i < 2097152) { src = wg;   rel = i - 1048576; base = W_G;   }
    else if (i < 3145728) { src = wu;   rel = i - 2097152; base = W_U;   }
    else                  { src = wd;   rel = i - 3145728; base = W_D;   }
    const float4 v = src[rel];
    uint2 o;
    o.x = pack_h2(v.x, v.y);
    o.y = pack_h2(v.z, v.w);
    *(uint2*)(wh + base + (size_t)rel * 4) = o;
}

// ---------------- FP16 mma.sync NT GEMM ------------------------------------
// C[M, Ntot] = A[M, K] * W[Ntot, K]^T + bias. CTA 128x256, 512 threads
// (16 warps, 2x8), warp tile 64x32. K-chunk 64, 4-stage ring, ONE barrier
// per chunk. EPI 0: +bias | 1: +bias+aux(fp32). OUT16: fp16 out else fp32.
#define GSTG_BYTES 49152     // A 16KB + B 32KB
#define GSMEM (4 * GSTG_BYTES)

__device__ __forceinline__ void g_issue(
    uint32_t sbase, int slot, const __half* A, const __half* W,
    int bm, int bn, int K, int k0, int tid)
{
    const uint32_t sb = sbase + slot * GSTG_BYTES;
    #pragma unroll
    for (int i = 0; i < 6; i++) {
        const int gi = tid + i * 512;
        if (gi < 1024) {
            const int r = gi >> 3, c = gi & 7;
            cp16(sb + r * 128 + ((c ^ (r & 7)) * 16),
                 A + (size_t)(bm + r) * K + k0 + c * 8);
        } else {
            const int j = gi - 1024;
            const int r = j >> 3, c = j & 7;
            cp16(sb + 16384 + r * 128 + ((c ^ (r & 7)) * 16),
                 W + (size_t)(bn + r) * K + k0 + c * 8);
        }
    }
}

template <int EPI, int OUT16>
__global__ __launch_bounds__(512, 1) void gemm_h(
    const __half* __restrict__ A, const __half* __restrict__ W,
    const float* __restrict__ bias, const float* __restrict__ aux,
    void* __restrict__ Cv, int Ntot, int K)
{
    extern __shared__ float gsm[];
    const uint32_t sbase = smem_u32(gsm);
    const int tid = threadIdx.x, wid = tid >> 5, lane = tid & 31;
    const int g = lane >> 2, th = lane & 3;
    const int bm = blockIdx.x * 128, bn = blockIdx.y * 256;
    const int wm = (wid & 1) * 64, wn = (wid >> 1) * 32;

    float acc[4][4][4];
    #pragma unroll
    for (int mt = 0; mt < 4; mt++)
        #pragma unroll
        for (int nt = 0; nt < 4; nt++)
            #pragma unroll
            for (int c = 0; c < 4; c++) acc[mt][nt][c] = 0.f;

    const int NT = K >> 6;
    #pragma unroll
    for (int t = 0; t < 3; t++) {
        if (t < NT) g_issue(sbase, t, A, W, bm, bn, K, t * 64, tid);
        cp_commit();
    }

    for (int t = 0; t < NT; t++) {
        cp_wait<2>();
        __syncthreads();
        if (t + 3 < NT) g_issue(sbase, (t + 3) & 3, A, W, bm, bn, K,
                                (t + 3) * 64, tid);
        cp_commit();

        const uint32_t sa = sbase + (t & 3) * GSTG_BYTES;
        const uint32_t sbB = sa + 16384;

        #pragma unroll
        for (int ks = 0; ks < 4; ks++) {
            const int gr = 2 * ks + (lane >> 4);
            uint32_t af[4][4], bf[4][2];
            #pragma unroll
            for (int mt = 0; mt < 4; mt++) {
                const int row = wm + mt * 16 + (lane & 15);
                ldsm_x4(af[mt], sa + row * 128 + ((gr ^ (row & 7)) * 16));
            }
            #pragma unroll
            for (int np = 0; np < 2; np++) {
                const int row = wn + np * 16 + (lane & 15);
                uint32_t q[4];
                ldsm_x4(q, sbB + row * 128 + ((gr ^ (row & 7)) * 16));
                bf[2 * np][0] = q[0]; bf[2 * np + 1][0] = q[1];
                bf[2 * np][1] = q[2]; bf[2 * np + 1][1] = q[3];
            }
            #pragma unroll
            for (int mt = 0; mt < 4; mt++)
                #pragma unroll
                for (int nt = 0; nt < 4; nt++)
                    mma_f16(acc[mt][nt], af[mt], bf[nt]);
        }
    }

    #pragma unroll
    for (int mt = 0; mt < 4; mt++) {
        const int m0 = bm + wm + mt * 16 + g;
        #pragma unroll
        for (int nt = 0; nt < 4; nt++) {
            const int n = bn + wn + nt * 8 + 2 * th;
            const float b0 = bias[n], b1 = bias[n + 1];
            float v00 = acc[mt][nt][0] + b0, v01 = acc[mt][nt][1] + b1;
            float v10 = acc[mt][nt][2] + b0, v11 = acc[mt][nt][3] + b1;
            if (EPI == 1) {
                const float2 x0 = *(const float2*)&aux[(size_t)m0 * Ntot + n];
                const float2 x1 = *(const float2*)&aux[(size_t)(m0 + 8) * Ntot + n];
                v00 += x0.x; v01 += x0.y; v10 += x1.x; v11 += x1.y;
            }
            if (OUT16) {
                __half* C = (__half*)Cv;
                *(uint32_t*)&C[(size_t)m0 * Ntot + n]       = pack_h2(v00, v01);
                *(uint32_t*)&C[(size_t)(m0 + 8) * Ntot + n] = pack_h2(v10, v11);
            } else {
                float* C = (float*)Cv;
                *(float2*)&C[(size_t)m0 * Ntot + n]       = make_float2(v00, v01);
                *(float2*)&C[(size_t)(m0 + 8) * Ntot + n] = make_float2(v10, v11);
            }
        }
    }
}

// ---------------- Fused SwiGLU GEMM (fp16) ----------------------------------
#define USTG_BYTES 49152     // A 16KB + Wg 16KB + Wu 16KB
#define USMEM (4 * USTG_BYTES)

__device__ __forceinline__ void u_issue(
    uint32_t sbase, int slot, const __half* A, const __half* Wg,
    const __half* Wu, int bm, int bn, int k0, int tid)
{
    const uint32_t sb = sbase + slot * USTG_BYTES;
    #pragma unroll
    for (int i = 0; i < 6; i++) {
        const int gi = tid + i * 512;
        const int r = (gi & 1023) >> 3, c = gi & 7;
        const uint32_t dst = r * 128 + ((c ^ (r & 7)) * 16);
        if (gi < 1024)
            cp16(sb + dst, A + (size_t)(bm + r) * DMODEL + k0 + c * 8);
        else if (gi < 2048)
            cp16(sb + 16384 + dst, Wg + (size_t)(bn + r) * DMODEL + k0 + c * 8);
        else
            cp16(sb + 32768 + dst, Wu + (size_t)(bn + r) * DMODEL + k0 + c * 8);
    }
}

__global__ __launch_bounds__(512, 1) void gemm_glu(
    const __half* __restrict__ A, const __half* __restrict__ Wg,
    const __half* __restrict__ Wu, const float* __restrict__ bg,
    const float* __restrict__ bu, __half* __restrict__ H)
{
    extern __shared__ float usm[];
    const uint32_t sbase = smem_u32(usm);
    const int tid = threadIdx.x, wid = tid >> 5, lane = tid & 31;
    const int g = lane >> 2, th = lane & 3;
    const int bm = blockIdx.x * 128, bn = blockIdx.y * 128;
    const int wm = (wid & 1) * 64, wn = (wid >> 1) * 16;

    float accG[4][2][4], accU[4][2][4];
    #pragma unroll
    for (int mt = 0; mt < 4; mt++)
        #pragma unroll
        for (int nt = 0; nt < 2; nt++)
            #pragma unroll
            for (int c = 0; c < 4; c++) { accG[mt][nt][c] = 0.f; accU[mt][nt][c] = 0.f; }

    const int NT = DMODEL >> 6;   // 16
    #pragma unroll
    for (int t = 0; t < 3; t++) {
        u_issue(sbase, t, A, Wg, Wu, bm, bn, t * 64, tid);
        cp_commit();
    }

    for (int t = 0; t < NT; t++) {
        cp_wait<2>();
        __syncthreads();
        if (t + 3 < NT) u_issue(sbase, (t + 3) & 3, A, Wg, Wu, bm, bn,
                                (t + 3) * 64, tid);
        cp_commit();

        const uint32_t sa = sbase + (t & 3) * USTG_BYTES;

        #pragma unroll
        for (int ks = 0; ks < 4; ks++) {
            const int gr = 2 * ks + (lane >> 4);
            uint32_t af[4][4], bG[2][2], bU[2][2];
            #pragma unroll
            for (int mt = 0; mt < 4; mt++) {
                const int row = wm + mt * 16 + (lane & 15);
                ldsm_x4(af[mt], sa + row * 128 + ((gr ^ (row & 7)) * 16));
            }
            {
                const int row = wn + (lane & 15);
                const uint32_t off = row * 128 + ((gr ^ (row & 7)) * 16);
                uint32_t q[4];
                ldsm_x4(q, sa + 16384 + off);
                bG[0][0] = q[0]; bG[1][0] = q[1];
                bG[0][1] = q[2]; bG[1][1] = q[3];
                ldsm_x4(q, sa + 32768 + off);
                bU[0][0] = q[0]; bU[1][0] = q[1];
                bU[0][1] = q[2]; bU[1][1] = q[3];
            }
            #pragma unroll
            for (int mt = 0; mt < 4; mt++)
                #pragma unroll
                for (int nt = 0; nt < 2; nt++) {
                    mma_f16(accG[mt][nt], af[mt], bG[nt]);
                    mma_f16(accU[mt][nt], af[mt], bU[nt]);
                }
        }
    }

    #pragma unroll
    for (int mt = 0; mt < 4; mt++) {
        const int m0 = bm + wm + mt * 16 + g;
        #pragma unroll
        for (int nt = 0; nt < 2; nt++) {
            const int n = bn + wn + nt * 8 + 2 * th;
            const float bg0 = bg[n], bg1 = bg[n + 1];
            const float bu0 = bu[n], bu1 = bu[n + 1];
            #pragma unroll
            for (int r = 0; r < 2; r++) {
                const float ga = accG[mt][nt][2 * r]     + bg0;
                const float gb = accG[mt][nt][2 * r + 1] + bg1;
                const float ua = accU[mt][nt][2 * r]     + bu0;
                const float ub = accU[mt][nt][2 * r + 1] + bu1;
                const float ha = ua * ga / (1.f + __expf(-ga));
                const float hb = ub * gb / (1.f + __expf(-gb));
                *(uint32_t*)&H[(size_t)(m0 + 8 * r) * DFFN + n] = pack_h2(ha, hb);
            }
        }
    }
}

// ---------------- Flash attention (fp16 mma, ALiBi) -------------------------
// 256 threads (8 warps), q-tile 128 (16 rows/warp), kv tiles 64, double-buffer.
#define AKV   16384
#define APQ   32768
#define ATT_SMEM (32768 + 16384)

__device__ __forceinline__ void kv_issue(
    uint32_t sb, int slot, const __half* kb, const __half* vb, int tid)
{
    const uint32_t kb0 = sb + slot * AKV;
    const uint32_t vb0 = kb0 + 8192;
    #pragma unroll
    for (int i = 0; i < 4; i++) {
        const int gi = tid + i * 256;
        if (gi < 512) {
            const int r = gi >> 3, c = gi & 7;
            cp16(kb0 + r * 128 + ((c ^ (r & 7)) * 16),
                 kb + (size_t)r * 3072 + c * 8);
        } else {
            const int r2 = (gi - 512) >> 3, c2 = gi & 7;
            cp16(vb0 + r2 * 128 + ((c2 ^ (r2 & 7)) * 16),
                 vb + (size_t)r2 * 3072 + c2 * 8);
        }
    }
}

__global__ __launch_bounds__(256, 2) void attn_mma(
    const __half* __restrict__ qkv, __half* __restrict__ out)
{
    extern __shared__ float smf[];
    const uint32_t sb = smem_u32(smf);
    const int tid = threadIdx.x, wid = tid >> 5, lane = tid & 31;
    const int g = lane >> 2, th = lane & 3;
    const int bq = blockIdx.x, h = blockIdx.y, b = blockIdx.z;
    const float slope = exp2f(-0.5f * (float)(h + 1));

    const __half* base = qkv + (size_t)b * SEQ * 3072;

    {
        const __half* qb = base + (size_t)(bq * 128) * 3072 + h * 64;
        #pragma unroll
        for (int i = 0; i < 4; i++) {
            const int gi = tid + i * 256;
            const int r = gi >> 3, c = gi & 7;
            cp16(sb + APQ + r * 128 + ((c ^ (r & 7)) * 16),
                 qb + (size_t)r * 3072 + c * 8);
        }
        cp_commit();
        cp_wait<0>();
        __syncthreads();
    }

    uint32_t aQ[4][4];
    #pragma unroll
    for (int ks = 0; ks < 4; ks++) {
        const int row = wid * 16 + (lane & 15);
        const int gr = 2 * ks + (lane >> 4);
        ldsm_x4(aQ[ks], sb + APQ + row * 128 + ((gr ^ (row & 7)) * 16));
    }
    __syncthreads();

    const uint32_t wp = sb + APQ + wid * 2048;
    float m0 = -1e30f, m1 = -1e30f, l0 = 0.f, l1 = 0.f;
    float O[8][4];
    #pragma unroll
    for (int nt = 0; nt < 8; nt++)
        #pragma unroll
        for (int c = 0; c < 4; c++) O[nt][c] = 0.f;

    const int q0 = bq * 128 + wid * 16 + g;
    const int q1 = q0 + 8;
    const __half* kb0 = base + DMODEL + h * 64;
    const __half* vb0 = base + 2 * DMODEL + h * 64;

    kv_issue(sb, 0, kb0, vb0, tid);
    cp_commit();

    for (int t = 0; t < 16; t++) {
        if (t + 1 < 16) {
            kv_issue(sb, (t + 1) & 1, kb0 + (size_t)((t + 1) * 64) * 3072,
                     vb0 + (size_t)((t + 1) * 64) * 3072, tid);
        }
        cp_commit();
        cp_wait<1>();
        __syncthreads();

        const uint32_t sk = sb + (t & 1) * AKV;
        const uint32_t sv = sk + 8192;

        float S[8][4];
        #pragma unroll
        for (int nt = 0; nt < 8; nt++)
            #pragma unroll
            for (int c = 0; c < 4; c++) S[nt][c] = 0.f;
        #pragma unroll
        for (int ks = 0; ks < 4; ks++) {
            const int gr = 2 * ks + (lane >> 4);
            uint32_t bf[8][2];
            #pragma unroll
            for (int np = 0; np < 4; np++) {
                const int row = np * 16 + (lane & 15);
                uint32_t q[4];
                ldsm_x4(q, sk + row * 128 + ((gr ^ (row & 7)) * 16));
                bf[2 * np][0] = q[0]; bf[2 * np + 1][0] = q[1];
                bf[2 * np][1] = q[2]; bf[2 * np + 1][1] = q[3];
            }
            #pragma unroll
            for (int nt = 0; nt < 8; nt++)
                mma_f16(S[nt], aQ[ks], bf[nt]);
        }

        float mx0 = -1e30f, mx1 = -1e30f;
        #pragma unroll
        for (int nt = 0; nt < 8; nt++) {
            const int kc = t * 64 + nt * 8 + 2 * th;
            S[nt][0] = S[nt][0] * 0.125f - slope * fabsf((float)(q0 - kc));
            S[nt][1] = S[nt][1] * 0.125f - slope * fabsf((float)(q0 - kc - 1));
            S[nt][2] = S[nt][2] * 0.125f - slope * fabsf((float)(q1 - kc));
            S[nt][3] = S[nt][3] * 0.125f - slope * fabsf((float)(q1 - kc - 1));
            mx0 = fmaxf(mx0, fmaxf(S[nt][0], S[nt][1]));
            mx1 = fmaxf(mx1, fmaxf(S[nt][2], S[nt][3]));
        }
        #pragma unroll
        for (int off = 1; off <= 2; off <<= 1) {
            mx0 = fmaxf(mx0, __shfl_xor_sync(0xffffffffu, mx0, off));
            mx1 = fmaxf(mx1, __shfl_xor_sync(0xffffffffu, mx1, off));
        }
        const float mn0 = fmaxf(m0, mx0), mn1 = fmaxf(m1, mx1);
        const float sc0 = __expf(m0 - mn0), sc1 = __expf(m1 - mn1);
        float s0 = 0.f, s1 = 0.f;
        #pragma unroll
        for (int nt = 0; nt < 8; nt++) {
            const float p00 = __expf(S[nt][0] - mn0);
            const float p01 = __expf(S[nt][1] - mn0);
            const float p10 = __expf(S[nt][2] - mn1);
            const float p11 = __expf(S[nt][3] - mn1);
            s0 += p00 + p01; s1 += p10 + p11;
            sts32(wp + g * 128 + ((nt ^ (g & 7)) * 16) + th * 4,
                  pack_h2(p00, p01));
            sts32(wp + (g + 8) * 128 + ((nt ^ ((g + 8) & 7)) * 16) + th * 4,
                  pack_h2(p10, p11));
        }
        #pragma unroll
        for (int off = 1; off <= 2; off <<= 1) {
            s0 += __shfl_xor_sync(0xffffffffu, s0, off);
            s1 += __shfl_xor_sync(0xffffffffu, s1, off);
        }
        l0 = l0 * sc0 + s0; l1 = l1 * sc1 + s1;
        m0 = mn0; m1 = mn1;
        #pragma unroll
        for (int nt = 0; nt < 8; nt++) {
            O[nt][0] *= sc0; O[nt][1] *= sc0;
            O[nt][2] *= sc1; O[nt][3] *= sc1;
        }
        __syncwarp();

        #pragma unroll
        for (int ks = 0; ks < 4; ks++) {
            uint32_t aP[4];
            {
                const int row = lane & 15;
                const int gr = 2 * ks + (lane >> 4);
                ldsm_x4(aP, wp + row * 128 + ((gr ^ (row & 7)) * 16));
            }
            #pragma unroll
            for (int np = 0; np < 4; np++) {
                const int row = ks * 16 + (lane & 15);
                const int gr = np * 2 + (lane >> 4);
                uint32_t q[4], bf0[2], bf1[2];
                ldsm_x4t(q, sv + row * 128 + ((gr ^ (row & 7)) * 16));
                bf0[0] = q[0]; bf0[1] = q[1];
                bf1[0] = q[2]; bf1[1] = q[3];
                mma_f16(O[2 * np],     aP, bf0);
                mma_f16(O[2 * np + 1], aP, bf1);
            }
        }
        __syncthreads();
    }

    const float i0 = 1.f / l0, i1 = 1.f / l1;
    #pragma unroll
    for (int nt = 0; nt < 8; nt++) {
        const int n = h * 64 + nt * 8 + 2 * th;
        *(uint32_t*)&out[(size_t)(b * SEQ + q0) * DMODEL + n] =
            pack_h2(O[nt][0] * i0, O[nt][1] * i0);
        *(uint32_t*)&out[(size_t)(b * SEQ + q1) * DMODEL + n] =
            pack_h2(O[nt][2] * i1, O[nt][3] * i1);
    }
}

// ---------------- LayerNorm (fp16 output) -----------------------------------
__global__ __launch_bounds__(256) void ln_kernel(
    const float* __restrict__ x, const float* __restrict__ g,
    const float* __restrict__ b, __half* __restrict__ y)
{
    __shared__ float redS[8];
    __shared__ float redQ[8];
    const int row = blockIdx.x;
    const int tid = threadIdx.x;

    const float4 v = ((const float4*)(x + (size_t)row * DMODEL))[tid];
    float s = v.x + v.y + v.z + v.w;
    float q = v.x*v.x + v.y*v.y + v.z*v.z + v.w*v.w;
    #pragma unroll
    for (int off = 16; off >= 1; off >>= 1) {
        s += __shfl_xor_sync(0xffffffffu, s, off);
        q += __shfl_xor_sync(0xffffffffu, q, off);
    }
    if ((tid & 31) == 0) { redS[tid >> 5] = s; redQ[tid >> 5] = q; }
    __syncthreads();
    if (tid < 32) {
        s = (tid < 8) ? redS[tid] : 0.f;
        q = (tid < 8) ? redQ[tid] : 0.f;
        #pragma unroll
        for (int off = 4; off >= 1; off >>= 1) {
            s += __shfl_xor_sync(0xffffffffu, s, off);
            q += __shfl_xor_sync(0xffffffffu, q, off);
        }
        if (tid == 0) { redS[0] = s; redQ[0] = q; }
    }
    __syncthreads();
    const float mu  = redS[0] * (1.f / DMODEL);
    const float var = redQ[0] * (1.f / DMODEL) - mu * mu;
    const float rstd = rsqrtf(var + 1e-5f);

    const float4 gv = ((const float4*)g)[tid];
    const float4 bv = ((const float4*)b)[tid];
    uint32_t o0 = pack_h2((v.x - mu) * rstd * gv.x + bv.x,
                          (v.y - mu) * rstd * gv.y + bv.y);
    uint32_t o1 = pack_h2((v.z - mu) * rstd * gv.z + bv.z,
                          (v.w - mu) * rstd * gv.w + bv.w);
    uint2* yo = (uint2*)(y + (size_t)row * DMODEL);
    yo[tid] = make_uint2(o0, o1);
}

// ---------------- launch -----------------------------------------------------
extern "C" void kernel_launch(void* const* d_in, const int* in_sizes, int n_in,
                              void* d_out, int out_size)
{
    const float* src    = (const float*)d_in[0];
    const float* wqkv   = (const float*)d_in[1];
    const float* bqkv   = (const float*)d_in[2];
    const float* wo     = (const float*)d_in[3];
    const float* bo     = (const float*)d_in[4];
    const float* g1     = (const float*)d_in[5];
    const float* b1     = (const float*)d_in[6];
    const float* g2     = (const float*)d_in[7];
    const float* b2     = (const float*)d_in[8];
    const float* w_gate = (const float*)d_in[9];
    const float* b_gate = (const float*)d_in[10];
    const float* w_up   = (const float*)d_in[11];
    const float* b_up   = (const float*)d_in[12];
    const float* w_down = (const float*)d_in[13];
    const float* b_down = (const float*)d_in[14];
    float* out = (float*)d_out;

    __half *lnh, *qkvh, *atth, *hh, *wh;
    float  *x1;
    cudaGetSymbolAddress((void**)&lnh,  g_lnh);
    cudaGetSymbolAddress((void**)&qkvh, g_qkvh);
    cudaGetSymbolAddress((void**)&atth, g_atth);
    cudaGetSymbolAddress((void**)&hh,   g_hh);
    cudaGetSymbolAddress((void**)&wh,   g_wh);
    cudaGetSymbolAddress((void**)&x1,   g_x1);

    cudaFuncSetAttribute(gemm_h<0, 1>,
        cudaFuncAttributeMaxDynamicSharedMemorySize, GSMEM);
    cudaFuncSetAttribute(gemm_h<1, 0>,
        cudaFuncAttributeMaxDynamicSharedMemorySize, GSMEM);
    cudaFuncSetAttribute(gemm_glu,
        cudaFuncAttributeMaxDynamicSharedMemorySize, USMEM);
    cudaFuncSetAttribute(attn_mma,
        cudaFuncAttributeMaxDynamicSharedMemorySize, ATT_SMEM);

    // all weights fp32 -> fp16 in one kernel
    cvt_all<<<16384, 256>>>((const float4*)wqkv, (const float4*)wo,
                            (const float4*)w_gate, (const float4*)w_up,
                            (const float4*)w_down, wh);

    // x = src + Attn(LN1(src))
    ln_kernel<<<MTOT, 256>>>(src, g1, b1, lnh);
    gemm_h<0, 1><<<dim3(64, 12), 512, GSMEM>>>(lnh, wh + W_QKV, bqkv, nullptr,
                                               qkvh, 3 * DMODEL, DMODEL);
    attn_mma<<<dim3(8, NHEAD, BATCH), 256, ATT_SMEM>>>(qkvh, atth);
    gemm_h<1, 0><<<dim3(64, 4), 512, GSMEM>>>(atth, wh + W_O, bo, src,
                                              x1, DMODEL, DMODEL);

    // x = x + SwiGLU(LN2(x))
    ln_kernel<<<MTOT, 256>>>(x1, g2, b2, lnh);
    gemm_glu<<<dim3(64, 32), 512, USMEM>>>(lnh, wh + W_G, wh + W_U,
                                           b_gate, b_up, hh);
    gemm_h<1, 0><<<dim3(64, 4), 512, GSMEM>>>(hh, wh + W_D, b_down, x1,
                                              out, DMODEL, DFFN);
}

// round 17
// speedup vs baseline: 7.1334x; 1.0260x over previous
#include <cuda_runtime.h>
#include <cuda_fp16.h>
#include <math.h>
#include <stdint.h>

#define MTOT   8192
#define DMODEL 1024
#define DFFN   4096
#define NHEAD  16
#define HDIM   64
#define SEQ    1024
#define BATCH  8

// ---------------- scratch (device globals; no allocations) ----------------
__device__ __half g_wh[16 * 1024 * 1024];      // fp16 weights (32 MB)
__device__ __half g_lnh[MTOT * DMODEL];        // fp16 LN output
__device__ __half g_qkvh[MTOT * 3 * DMODEL];   // fp16 qkv
__device__ __half g_atth[MTOT * DMODEL];       // fp16 attention output
__device__ __half g_hh[MTOT * DFFN];           // fp16 silu(gate)*up
__device__ float  g_x1[MTOT * DMODEL];         // fp32 residual stream

#define W_QKV  0
#define W_O    (3 * 1024 * 1024)
#define W_G    (4 * 1024 * 1024)
#define W_U    (8 * 1024 * 1024)
#define W_D    (12 * 1024 * 1024)

// ---------------- PTX helpers ---------------------------------------------
__device__ __forceinline__ uint32_t smem_u32(const void* p) {
    uint32_t a;
    asm("{ .reg .u64 t; cvta.to.shared.u64 t, %1; cvt.u32.u64 %0, t; }"
        : "=r"(a) : "l"(p));
    return a;
}
__device__ __forceinline__ void cp16(uint32_t dst, const void* src) {
    asm volatile("cp.async.cg.shared.global [%0], [%1], 16;"
                 :: "r"(dst), "l"(src) : "memory");
}
__device__ __forceinline__ void cp_commit() {
    asm volatile("cp.async.commit_group;" ::: "memory");
}
template <int N>
__device__ __forceinline__ void cp_wait() {
    asm volatile("cp.async.wait_group %0;" :: "n"(N) : "memory");
}
__device__ __forceinline__ void ldsm_x4(uint32_t r[4], uint32_t addr) {
    asm volatile("ldmatrix.sync.aligned.m8n8.x4.shared.b16 {%0,%1,%2,%3}, [%4];"
        : "=r"(r[0]), "=r"(r[1]), "=r"(r[2]), "=r"(r[3]) : "r"(addr));
}
__device__ __forceinline__ void ldsm_x4t(uint32_t r[4], uint32_t addr) {
    asm volatile("ldmatrix.sync.aligned.m8n8.x4.trans.shared.b16 {%0,%1,%2,%3}, [%4];"
        : "=r"(r[0]), "=r"(r[1]), "=r"(r[2]), "=r"(r[3]) : "r"(addr));
}
__device__ __forceinline__ void mma_f16(float c[4], const uint32_t a[4],
                                        const uint32_t b[2]) {
    asm volatile(
        "mma.sync.aligned.m16n8k16.row.col.f32.f16.f16.f32 "
        "{%0,%1,%2,%3}, {%4,%5,%6,%7}, {%8,%9}, {%0,%1,%2,%3};\n"
        : "+f"(c[0]), "+f"(c[1]), "+f"(c[2]), "+f"(c[3])
        : "r"(a[0]), "r"(a[1]), "r"(a[2]), "r"(a[3]), "r"(b[0]), "r"(b[1]));
}
__device__ __forceinline__ uint32_t pack_h2(float a, float b) {
    __half2 h = __floats2half2_rn(a, b);
    return *reinterpret_cast<uint32_t*>(&h);
}

// ---------------- all-weights fp32 -> fp16 (single kernel) ------------------
__global__ __launch_bounds__(256) void cvt_all(
    const float4* __restrict__ wqkv, const float4* __restrict__ wo,
    const float4* __restrict__ wg,   const float4* __restrict__ wu,
    const float4* __restrict__ wd,   __half* __restrict__ wh)
{
    const int i = blockIdx.x * 256 + threadIdx.x;
    const float4* src;
    int rel, base;
    if (i < 786432)       { src = wqkv; rel = i;           base = W_QKV; }
    else if (i < 1048576) { src = wo;   rel = i - 786432;  base = W_O;   }
    else if (i < 2097152) { src = wg;   rel = i - 1048576; base = W_G;   }
    else if (i < 3145728) { src = wu;   rel = i - 2097152; base = W_U;   }
    else                  { src = wd;   rel = i - 3145728; base = W_D;   }
    const float4 v = src[rel];
    uint2 o;
    o.x = pack_h2(v.x, v.y);
    o.y = pack_h2(v.z, v.w);
    *(uint2*)(wh + base + (size_t)rel * 4) = o;
}

// ---------------- FP16 mma.sync NT GEMM ------------------------------------
// CTA 128x256, 512 threads (16 warps, 2x8), warp tile 64x32. K-chunk 64,
// 4-stage ring, one barrier per chunk.
#define GSTG_BYTES 49152     // A 16KB + B 32KB
#define GSMEM (4 * GSTG_BYTES)

__device__ __forceinline__ void g_issue(
    uint32_t sbase, int slot, const __half* A, const __half* W,
    int bm, int bn, int K, int k0, int tid)
{
    const uint32_t sb = sbase + slot * GSTG_BYTES;
    #pragma unroll
    for (int i = 0; i < 6; i++) {
        const int gi = tid + i * 512;
        if (gi < 1024) {
            const int r = gi >> 3, c = gi & 7;
            cp16(sb + r * 128 + ((c ^ (r & 7)) * 16),
                 A + (size_t)(bm + r) * K + k0 + c * 8);
        } else {
            const int j = gi - 1024;
            const int r = j >> 3, c = j & 7;
            cp16(sb + 16384 + r * 128 + ((c ^ (r & 7)) * 16),
                 W + (size_t)(bn + r) * K + k0 + c * 8);
        }
    }
}

template <int EPI, int OUT16>
__global__ __launch_bounds__(512, 1) void gemm_h(
    const __half* __restrict__ A, const __half* __restrict__ W,
    const float* __restrict__ bias, const float* __restrict__ aux,
    void* __restrict__ Cv, int Ntot, int K)
{
    extern __shared__ float gsm[];
    const uint32_t sbase = smem_u32(gsm);
    const int tid = threadIdx.x, wid = tid >> 5, lane = tid & 31;
    const int g = lane >> 2, th = lane & 3;
    const int bm = blockIdx.x * 128, bn = blockIdx.y * 256;
    const int wm = (wid & 1) * 64, wn = (wid >> 1) * 32;

    float acc[4][4][4];
    #pragma unroll
    for (int mt = 0; mt < 4; mt++)
        #pragma unroll
        for (int nt = 0; nt < 4; nt++)
            #pragma unroll
            for (int c = 0; c < 4; c++) acc[mt][nt][c] = 0.f;

    const int NT = K >> 6;
    #pragma unroll
    for (int t = 0; t < 3; t++) {
        if (t < NT) g_issue(sbase, t, A, W, bm, bn, K, t * 64, tid);
        cp_commit();
    }

    for (int t = 0; t < NT; t++) {
        cp_wait<2>();
        __syncthreads();
        if (t + 3 < NT) g_issue(sbase, (t + 3) & 3, A, W, bm, bn, K,
                                (t + 3) * 64, tid);
        cp_commit();

        const uint32_t sa = sbase + (t & 3) * GSTG_BYTES;
        const uint32_t sbB = sa + 16384;

        #pragma unroll
        for (int ks = 0; ks < 4; ks++) {
            const int gr = 2 * ks + (lane >> 4);
            uint32_t af[4][4], bf[4][2];
            #pragma unroll
            for (int mt = 0; mt < 4; mt++) {
                const int row = wm + mt * 16 + (lane & 15);
                ldsm_x4(af[mt], sa + row * 128 + ((gr ^ (row & 7)) * 16));
            }
            #pragma unroll
            for (int np = 0; np < 2; np++) {
                const int row = wn + np * 16 + (lane & 15);
                uint32_t q[4];
                ldsm_x4(q, sbB + row * 128 + ((gr ^ (row & 7)) * 16));
                bf[2 * np][0] = q[0]; bf[2 * np + 1][0] = q[1];
                bf[2 * np][1] = q[2]; bf[2 * np + 1][1] = q[3];
            }
            #pragma unroll
            for (int mt = 0; mt < 4; mt++)
                #pragma unroll
                for (int nt = 0; nt < 4; nt++)
                    mma_f16(acc[mt][nt], af[mt], bf[nt]);
        }
    }

    #pragma unroll
    for (int mt = 0; mt < 4; mt++) {
        const int m0 = bm + wm + mt * 16 + g;
        #pragma unroll
        for (int nt = 0; nt < 4; nt++) {
            const int n = bn + wn + nt * 8 + 2 * th;
            const float b0 = bias[n], b1 = bias[n + 1];
            float v00 = acc[mt][nt][0] + b0, v01 = acc[mt][nt][1] + b1;
            float v10 = acc[mt][nt][2] + b0, v11 = acc[mt][nt][3] + b1;
            if (EPI == 1) {
                const float2 x0 = *(const float2*)&aux[(size_t)m0 * Ntot + n];
                const float2 x1 = *(const float2*)&aux[(size_t)(m0 + 8) * Ntot + n];
                v00 += x0.x; v01 += x0.y; v10 += x1.x; v11 += x1.y;
            }
            if (OUT16) {
                __half* C = (__half*)Cv;
                *(uint32_t*)&C[(size_t)m0 * Ntot + n]       = pack_h2(v00, v01);
                *(uint32_t*)&C[(size_t)(m0 + 8) * Ntot + n] = pack_h2(v10, v11);
            } else {
                float* C = (float*)Cv;
                *(float2*)&C[(size_t)m0 * Ntot + n]       = make_float2(v00, v01);
                *(float2*)&C[(size_t)(m0 + 8) * Ntot + n] = make_float2(v10, v11);
            }
        }
    }
}

// ---------------- Fused SwiGLU GEMM (fp16) ----------------------------------
#define USTG_BYTES 49152     // A 16KB + Wg 16KB + Wu 16KB
#define USMEM (4 * USTG_BYTES)

__device__ __forceinline__ void u_issue(
    uint32_t sbase, int slot, const __half* A, const __half* Wg,
    const __half* Wu, int bm, int bn, int k0, int tid)
{
    const uint32_t sb = sbase + slot * USTG_BYTES;
    #pragma unroll
    for (int i = 0; i < 6; i++) {
        const int gi = tid + i * 512;
        const int r = (gi & 1023) >> 3, c = gi & 7;
        const uint32_t dst = r * 128 + ((c ^ (r & 7)) * 16);
        if (gi < 1024)
            cp16(sb + dst, A + (size_t)(bm + r) * DMODEL + k0 + c * 8);
        else if (gi < 2048)
            cp16(sb + 16384 + dst, Wg + (size_t)(bn + r) * DMODEL + k0 + c * 8);
        else
            cp16(sb + 32768 + dst, Wu + (size_t)(bn + r) * DMODEL + k0 + c * 8);
    }
}

__global__ __launch_bounds__(512, 1) void gemm_glu(
    const __half* __restrict__ A, const __half* __restrict__ Wg,
    const __half* __restrict__ Wu, const float* __restrict__ bg,
    const float* __restrict__ bu, __half* __restrict__ H)
{
    extern __shared__ float usm[];
    const uint32_t sbase = smem_u32(usm);
    const int tid = threadIdx.x, wid = tid >> 5, lane = tid & 31;
    const int g = lane >> 2, th = lane & 3;
    const int bm = blockIdx.x * 128, bn = blockIdx.y * 128;
    const int wm = (wid & 1) * 64, wn = (wid >> 1) * 16;

    float accG[4][2][4], accU[4][2][4];
    #pragma unroll
    for (int mt = 0; mt < 4; mt++)
        #pragma unroll
        for (int nt = 0; nt < 2; nt++)
            #pragma unroll
            for (int c = 0; c < 4; c++) { accG[mt][nt][c] = 0.f; accU[mt][nt][c] = 0.f; }

    const int NT = DMODEL >> 6;   // 16
    #pragma unroll
    for (int t = 0; t < 3; t++) {
        u_issue(sbase, t, A, Wg, Wu, bm, bn, t * 64, tid);
        cp_commit();
    }

    for (int t = 0; t < NT; t++) {
        cp_wait<2>();
        __syncthreads();
        if (t + 3 < NT) u_issue(sbase, (t + 3) & 3, A, Wg, Wu, bm, bn,
                                (t + 3) * 64, tid);
        cp_commit();

        const uint32_t sa = sbase + (t & 3) * USTG_BYTES;

        #pragma unroll
        for (int ks = 0; ks < 4; ks++) {
            const int gr = 2 * ks + (lane >> 4);
            uint32_t af[4][4], bG[2][2], bU[2][2];
            #pragma unroll
            for (int mt = 0; mt < 4; mt++) {
                const int row = wm + mt * 16 + (lane & 15);
                ldsm_x4(af[mt], sa + row * 128 + ((gr ^ (row & 7)) * 16));
            }
            {
                const int row = wn + (lane & 15);
                const uint32_t off = row * 128 + ((gr ^ (row & 7)) * 16);
                uint32_t q[4];
                ldsm_x4(q, sa + 16384 + off);
                bG[0][0] = q[0]; bG[1][0] = q[1];
                bG[0][1] = q[2]; bG[1][1] = q[3];
                ldsm_x4(q, sa + 32768 + off);
                bU[0][0] = q[0]; bU[1][0] = q[1];
                bU[0][1] = q[2]; bU[1][1] = q[3];
            }
            #pragma unroll
            for (int mt = 0; mt < 4; mt++)
                #pragma unroll
                for (int nt = 0; nt < 2; nt++) {
                    mma_f16(accG[mt][nt], af[mt], bG[nt]);
                    mma_f16(accU[mt][nt], af[mt], bU[nt]);
                }
        }
    }

    #pragma unroll
    for (int mt = 0; mt < 4; mt++) {
        const int m0 = bm + wm + mt * 16 + g;
        #pragma unroll
        for (int nt = 0; nt < 2; nt++) {
            const int n = bn + wn + nt * 8 + 2 * th;
            const float bg0 = bg[n], bg1 = bg[n + 1];
            const float bu0 = bu[n], bu1 = bu[n + 1];
            #pragma unroll
            for (int r = 0; r < 2; r++) {
                const float ga = accG[mt][nt][2 * r]     + bg0;
                const float gb = accG[mt][nt][2 * r + 1] + bg1;
                const float ua = accU[mt][nt][2 * r]     + bu0;
                const float ub = accU[mt][nt][2 * r + 1] + bu1;
                const float ha = ua * ga / (1.f + __expf(-ga));
                const float hb = ub * gb / (1.f + __expf(-gb));
                *(uint32_t*)&H[(size_t)(m0 + 8 * r) * DFFN + n] = pack_h2(ha, hb);
            }
        }
    }
}

// ---------------- Flash attention (fp16 mma, ALiBi, P in registers) ---------
// 256 threads (8 warps), q-tile 128 (16 rows/warp), kv tiles 64, double-buffer.
// P stays in registers: S c-frags pack directly into PV a-frags (FA2 layout).
#define AKV   16384
#define APQ   32768
#define ATT_SMEM (32768 + 16384)

__device__ __forceinline__ void kv_issue(
    uint32_t sb, int slot, const __half* kb, const __half* vb, int tid)
{
    const uint32_t kb0 = sb + slot * AKV;
    const uint32_t vb0 = kb0 + 8192;
    #pragma unroll
    for (int i = 0; i < 4; i++) {
        const int gi = tid + i * 256;
        if (gi < 512) {
            const int r = gi >> 3, c = gi & 7;
            cp16(kb0 + r * 128 + ((c ^ (r & 7)) * 16),
                 kb + (size_t)r * 3072 + c * 8);
        } else {
            const int r2 = (gi - 512) >> 3, c2 = gi & 7;
            cp16(vb0 + r2 * 128 + ((c2 ^ (r2 & 7)) * 16),
                 vb + (size_t)r2 * 3072 + c2 * 8);
        }
    }
}

__global__ __launch_bounds__(256, 2) void attn_mma(
    const __half* __restrict__ qkv, __half* __restrict__ out)
{
    extern __shared__ float smf[];
    const uint32_t sb = smem_u32(smf);
    const int tid = threadIdx.x, wid = tid >> 5, lane = tid & 31;
    const int g = lane >> 2, th = lane & 3;
    const int bq = blockIdx.x, h = blockIdx.y, b = blockIdx.z;
    const float LOG2E = 1.44269504f;
    const float scale2 = 0.125f * LOG2E;
    const float slope2 = exp2f(-0.5f * (float)(h + 1)) * LOG2E;

    const __half* base = qkv + (size_t)b * SEQ * 3072;

    // stage Q tile (128 x 64 fp16)
    {
        const __half* qb = base + (size_t)(bq * 128) * 3072 + h * 64;
        #pragma unroll
        for (int i = 0; i < 4; i++) {
            const int gi = tid + i * 256;
            const int r = gi >> 3, c = gi & 7;
            cp16(sb + APQ + r * 128 + ((c ^ (r & 7)) * 16),
                 qb + (size_t)r * 3072 + c * 8);
        }
        cp_commit();
        cp_wait<0>();
        __syncthreads();
    }

    uint32_t aQ[4][4];
    #pragma unroll
    for (int ks = 0; ks < 4; ks++) {
        const int row = wid * 16 + (lane & 15);
        const int gr = 2 * ks + (lane >> 4);
        ldsm_x4(aQ[ks], sb + APQ + row * 128 + ((gr ^ (row & 7)) * 16));
    }
    __syncthreads();

    float m0 = -1e30f, m1 = -1e30f, l0 = 0.f, l1 = 0.f;
    float O[8][4];
    #pragma unroll
    for (int nt = 0; nt < 8; nt++)
        #pragma unroll
        for (int c = 0; c < 4; c++) O[nt][c] = 0.f;

    const int q0 = bq * 128 + wid * 16 + g;
    const int q1 = q0 + 8;
    const float q0f = (float)q0, q1f = (float)q1;
    const __half* kb0 = base + DMODEL + h * 64;
    const __half* vb0 = base + 2 * DMODEL + h * 64;

    kv_issue(sb, 0, kb0, vb0, tid);
    cp_commit();

    for (int t = 0; t < 16; t++) {
        if (t + 1 < 16) {
            kv_issue(sb, (t + 1) & 1, kb0 + (size_t)((t + 1) * 64) * 3072,
                     vb0 + (size_t)((t + 1) * 64) * 3072, tid);
        }
        cp_commit();
        cp_wait<1>();
        __syncthreads();

        const uint32_t sk = sb + (t & 1) * AKV;
        const uint32_t sv = sk + 8192;

        // S = Q K^T (16 x 64 per warp)
        float S[8][4];
        #pragma unroll
        for (int nt = 0; nt < 8; nt++)
            #pragma unroll
            for (int c = 0; c < 4; c++) S[nt][c] = 0.f;
        #pragma unroll
        for (int ks = 0; ks < 4; ks++) {
            const int gr = 2 * ks + (lane >> 4);
            uint32_t bf[8][2];
            #pragma unroll
            for (int np = 0; np < 4; np++) {
                const int row = np * 16 + (lane & 15);
                uint32_t q[4];
                ldsm_x4(q, sk + row * 128 + ((gr ^ (row & 7)) * 16));
                bf[2 * np][0] = q[0]; bf[2 * np + 1][0] = q[1];
                bf[2 * np][1] = q[2]; bf[2 * np + 1][1] = q[3];
            }
            #pragma unroll
            for (int nt = 0; nt < 8; nt++)
                mma_f16(S[nt], aQ[ks], bf[nt]);
        }

        // base-2 softmax with folded ALiBi; float distances
        const float kbf = (float)(t * 64 + 2 * th);
        float mx0 = -1e30f, mx1 = -1e30f;
        #pragma unroll
        for (int nt = 0; nt < 8; nt++) {
            const float kc = kbf + (float)(nt * 8);
            S[nt][0] = S[nt][0] * scale2 - slope2 * fabsf(q0f - kc);
            S[nt][1] = S[nt][1] * scale2 - slope2 * fabsf(q0f - kc - 1.f);
            S[nt][2] = S[nt][2] * scale2 - slope2 * fabsf(q1f - kc);
            S[nt][3] = S[nt][3] * scale2 - slope2 * fabsf(q1f - kc - 1.f);
            mx0 = fmaxf(mx0, fmaxf(S[nt][0], S[nt][1]));
            mx1 = fmaxf(mx1, fmaxf(S[nt][2], S[nt][3]));
        }
        #pragma unroll
        for (int off = 1; off <= 2; off <<= 1) {
            mx0 = fmaxf(mx0, __shfl_xor_sync(0xffffffffu, mx0, off));
            mx1 = fmaxf(mx1, __shfl_xor_sync(0xffffffffu, mx1, off));
        }
        const float mn0 = fmaxf(m0, mx0), mn1 = fmaxf(m1, mx1);
        const float sc0 = exp2f(m0 - mn0), sc1 = exp2f(m1 - mn1);
        float s0 = 0.f, s1 = 0.f;
        uint32_t aP[4][4];
        #pragma unroll
        for (int nt = 0; nt < 8; nt++) {
            const float p00 = exp2f(S[nt][0] - mn0);
            const float p01 = exp2f(S[nt][1] - mn0);
            const float p10 = exp2f(S[nt][2] - mn1);
            const float p11 = exp2f(S[nt][3] - mn1);
            s0 += p00 + p01; s1 += p10 + p11;
            // c-frag -> PV a-frag: nt even -> a0/a1, nt odd -> a2/a3 of ks=nt/2
            aP[nt >> 1][(nt & 1) * 2]     = pack_h2(p00, p01);
            aP[nt >> 1][(nt & 1) * 2 + 1] = pack_h2(p10, p11);
        }
        #pragma unroll
        for (int off = 1; off <= 2; off <<= 1) {
            s0 += __shfl_xor_sync(0xffffffffu, s0, off);
            s1 += __shfl_xor_sync(0xffffffffu, s1, off);
        }
        l0 = l0 * sc0 + s0; l1 = l1 * sc1 + s1;
        m0 = mn0; m1 = mn1;
        #pragma unroll
        for (int nt = 0; nt < 8; nt++) {
            O[nt][0] *= sc0; O[nt][1] *= sc0;
            O[nt][2] *= sc1; O[nt][3] *= sc1;
        }

        // O += P V  (A = aP registers; B = V via ldmatrix.trans)
        #pragma unroll
        for (int ks = 0; ks < 4; ks++) {
            #pragma unroll
            for (int np = 0; np < 4; np++) {
                const int row = ks * 16 + (lane & 15);       // kv row
                const int gr = np * 2 + (lane >> 4);         // hd chunk
                uint32_t q[4], bf0[2], bf1[2];
                ldsm_x4t(q, sv + row * 128 + ((gr ^ (row & 7)) * 16));
                bf0[0] = q[0]; bf0[1] = q[1];                // hd np*16+0..7
                bf1[0] = q[2]; bf1[1] = q[3];                // hd np*16+8..15
                mma_f16(O[2 * np],     aP[ks], bf0);
                mma_f16(O[2 * np + 1], aP[ks], bf1);
            }
        }
        __syncthreads();
    }

    const float i0 = 1.f / l0, i1 = 1.f / l1;
    #pragma unroll
    for (int nt = 0; nt < 8; nt++) {
        const int n = h * 64 + nt * 8 + 2 * th;
        *(uint32_t*)&out[(size_t)(b * SEQ + q0) * DMODEL + n] =
            pack_h2(O[nt][0] * i0, O[nt][1] * i0);
        *(uint32_t*)&out[(size_t)(b * SEQ + q1) * DMODEL + n] =
            pack_h2(O[nt][2] * i1, O[nt][3] * i1);
    }
}

// ---------------- LayerNorm (fp16 output) -----------------------------------
__global__ __launch_bounds__(256) void ln_kernel(
    const float* __restrict__ x, const float* __restrict__ g,
    const float* __restrict__ b, __half* __restrict__ y)
{
    __shared__ float redS[8];
    __shared__ float redQ[8];
    const int row = blockIdx.x;
    const int tid = threadIdx.x;

    const float4 v = ((const float4*)(x + (size_t)row * DMODEL))[tid];
    float s = v.x + v.y + v.z + v.w;
    float q = v.x*v.x + v.y*v.y + v.z*v.z + v.w*v.w;
    #pragma unroll
    for (int off = 16; off >= 1; off >>= 1) {
        s += __shfl_xor_sync(0xffffffffu, s, off);
        q += __shfl_xor_sync(0xffffffffu, q, off);
    }
    if ((tid & 31) == 0) { redS[tid >> 5] = s; redQ[tid >> 5] = q; }
    __syncthreads();
    if (tid < 32) {
        s = (tid < 8) ? redS[tid] : 0.f;
        q = (tid < 8) ? redQ[tid] : 0.f;
        #pragma unroll
        for (int off = 4; off >= 1; off >>= 1) {
            s += __shfl_xor_sync(0xffffffffu, s, off);
            q += __shfl_xor_sync(0xffffffffu, q, off);
        }
        if (tid == 0) { redS[0] = s; redQ[0] = q; }
    }
    __syncthreads();
    const float mu  = redS[0] * (1.f / DMODEL);
    const float var = redQ[0] * (1.f / DMODEL) - mu * mu;
    const float rstd = rsqrtf(var + 1e-5f);

    const float4 gv = ((const float4*)g)[tid];
    const float4 bv = ((const float4*)b)[tid];
    uint32_t o0 = pack_h2((v.x - mu) * rstd * gv.x + bv.x,
                          (v.y - mu) * rstd * gv.y + bv.y);
    uint32_t o1 = pack_h2((v.z - mu) * rstd * gv.z + bv.z,
                          (v.w - mu) * rstd * gv.w + bv.w);
    uint2* yo = (uint2*)(y + (size_t)row * DMODEL);
    yo[tid] = make_uint2(o0, o1);
}

// ---------------- launch -----------------------------------------------------
extern "C" void kernel_launch(void* const* d_in, const int* in_sizes, int n_in,
                              void* d_out, int out_size)
{
    const float* src    = (const float*)d_in[0];
    const float* wqkv   = (const float*)d_in[1];
    const float* bqkv   = (const float*)d_in[2];
    const float* wo     = (const float*)d_in[3];
    const float* bo     = (const float*)d_in[4];
    const float* g1     = (const float*)d_in[5];
    const float* b1     = (const float*)d_in[6];
    const float* g2     = (const float*)d_in[7];
    const float* b2     = (const float*)d_in[8];
    const float* w_gate = (const float*)d_in[9];
    const float* b_gate = (const float*)d_in[10];
    const float* w_up   = (const float*)d_in[11];
    const float* b_up   = (const float*)d_in[12];
    const float* w_down = (const float*)d_in[13];
    const float* b_down = (const float*)d_in[14];
    float* out = (float*)d_out;

    __half *lnh, *qkvh, *atth, *hh, *wh;
    float  *x1;
    cudaGetSymbolAddress((void**)&lnh,  g_lnh);
    cudaGetSymbolAddress((void**)&qkvh, g_qkvh);
    cudaGetSymbolAddress((void**)&atth, g_atth);
    cudaGetSymbolAddress((void**)&hh,   g_hh);
    cudaGetSymbolAddress((void**)&wh,   g_wh);
    cudaGetSymbolAddress((void**)&x1,   g_x1);

    cudaFuncSetAttribute(gemm_h<0, 1>,
        cudaFuncAttributeMaxDynamicSharedMemorySize, GSMEM);
    cudaFuncSetAttribute(gemm_h<1, 0>,
        cudaFuncAttributeMaxDynamicSharedMemorySize, GSMEM);
    cudaFuncSetAttribute(gemm_glu,
        cudaFuncAttributeMaxDynamicSharedMemorySize, USMEM);
    cudaFuncSetAttribute(attn_mma,
        cudaFuncAttributeMaxDynamicSharedMemorySize, ATT_SMEM);

    // all weights fp32 -> fp16 in one kernel
    cvt_all<<<16384, 256>>>((const float4*)wqkv, (const float4*)wo,
                            (const float4*)w_gate, (const float4*)w_up,
                            (const float4*)w_down, wh);

    // x = src + Attn(LN1(src))
    ln_kernel<<<MTOT, 256>>>(src, g1, b1, lnh);
    gemm_h<0, 1><<<dim3(64, 12), 512, GSMEM>>>(lnh, wh + W_QKV, bqkv, nullptr,
                                               qkvh, 3 * DMODEL, DMODEL);
    attn_mma<<<dim3(8, NHEAD, BATCH), 256, ATT_SMEM>>>(qkvh, atth);
    gemm_h<1, 0><<<dim3(64, 4), 512, GSMEM>>>(atth, wh + W_O, bo, src,
                                              x1, DMODEL, DMODEL);

    // x = x + SwiGLU(LN2(x))
    ln_kernel<<<MTOT, 256>>>(x1, g2, b2, lnh);
    gemm_glu<<<dim3(64, 32), 512, USMEM>>>(lnh, wh + W_G, wh + W_U,
                                           b_gate, b_up, hh);
    gemm_h<1, 0><<<dim3(64, 4), 512, GSMEM>>>(hh, wh + W_D, b_down, x1,
                                              out, DMODEL, DFFN);
}